// round 2
// baseline (speedup 1.0000x reference)
#include <cuda_runtime.h>
#include <math.h>

namespace cfg {
constexpr int N    = 2048;
constexpr int D    = 128;
constexpr int H    = 8;
constexpr int FFD  = 512;
constexpr int NL   = 3;
constexpr int E    = 65536;
constexpr int HS   = 8;
constexpr int OUTD = 64;
}
using namespace cfg;

// ---------------- scratch (static device arrays; no allocation) ------------
__device__ float g_h[N * D];
__device__ float g_xn[N * D];
__device__ float g_spbias[(size_t)N * N];
__device__ float g_q[H * N * D];
__device__ float g_k[H * N * D];
__device__ float g_v[H * N * D];
__device__ float g_ao[N * H * D];   // [n][h*D + e]
__device__ float g_ff[N * FFD];
__device__ int   g_indeg[N];
__device__ int   g_outdeg[N];

// ---------------- degrees --------------------------------------------------
__global__ void k_zero_deg() {
    int i = blockIdx.x * blockDim.x + threadIdx.x;
    if (i < N) { g_indeg[i] = 0; g_outdeg[i] = 0; }
}

__global__ void k_deg(const int* __restrict__ ei) {
    int e = blockIdx.x * blockDim.x + threadIdx.x;
    if (e < E) {
        atomicAdd(&g_outdeg[ei[e]], 1);       // row 0: source
        atomicAdd(&g_indeg[ei[E + e]], 1);    // row 1: destination
    }
}

// ---------------- node embedding -------------------------------------------
__global__ void k_embed(const float* __restrict__ x,
                        const float* __restrict__ W,
                        const float* __restrict__ b,
                        const float* __restrict__ z_in,
                        const float* __restrict__ z_out) {
    int n = blockIdx.x;
    int d = threadIdx.x;                 // 0..127
    __shared__ float xs[16];
    if (d < 16) xs[d] = x[n * 16 + d];
    __syncthreads();
    float acc = b[d];
#pragma unroll
    for (int k = 0; k < 16; k++) acc = fmaf(xs[k], W[k * D + d], acc);
    int id = min(g_indeg[n], 63);
    int od = min(g_outdeg[n], 63);
    acc += z_in[id * D + d] + z_out[od * D + d];
    g_h[n * D + d] = acc;
}

// ---------------- spatial bias table ---------------------------------------
__global__ void k_spbias(const float* __restrict__ pos,
                         const float* __restrict__ mu,
                         const float* __restrict__ sig,
                         const float* __restrict__ w,
                         const float* __restrict__ b0) {
    int j = blockIdx.x * blockDim.x + threadIdx.x;
    int i = blockIdx.y;
    float px = pos[i * 3], py = pos[i * 3 + 1], pz = pos[i * 3 + 2];
    float dx = px - pos[j * 3];
    float dy = py - pos[j * 3 + 1];
    float dz = pz - pos[j * 3 + 2];
    float dist = sqrtf(dx * dx + dy * dy + dz * dz + 1e-12f);
    float acc = b0[0];
#pragma unroll
    for (int k = 0; k < HS; k++) {
        float t = (dist - mu[k]) / sig[k];
        acc = fmaf(w[k], __expf(-0.5f * t * t), acc);
    }
    g_spbias[(size_t)i * N + j] = acc;
}

// ---------------- layernorm ------------------------------------------------
__global__ void k_ln(const float* __restrict__ in,
                     const float* __restrict__ g,
                     const float* __restrict__ b,
                     float* __restrict__ out) {
    int n = blockIdx.x, d = threadIdx.x;
    float v = in[n * D + d];
    float s = v;
#pragma unroll
    for (int o = 16; o; o >>= 1) s += __shfl_xor_sync(0xffffffffu, s, o);
    __shared__ float r1[4], r2[4];
    int w = d >> 5;
    if ((d & 31) == 0) r1[w] = s;
    __syncthreads();
    float mean = (r1[0] + r1[1] + r1[2] + r1[3]) * (1.0f / D);
    float t = v - mean;
    float s2 = t * t;
#pragma unroll
    for (int o = 16; o; o >>= 1) s2 += __shfl_xor_sync(0xffffffffu, s2, o);
    if ((d & 31) == 0) r2[w] = s2;
    __syncthreads();
    float var = (r2[0] + r2[1] + r2[2] + r2[3]) * (1.0f / D);
    out[n * D + d] = t * rsqrtf(var + 1e-5f) * g[d] + b[d];
}

// ---------------- tiled GEMM with fused epilogue ---------------------------
// C = act(A[M,K] @ B[K,Nc] + bias) (+ res). BM=BN=64, BK=16, 256 thr, 4x4.
__global__ __launch_bounds__(256) void k_gemm(
    const float* __restrict__ A, const float* __restrict__ Bm,
    const float* __restrict__ bias, const float* __restrict__ res,
    float* __restrict__ C, int M, int Kd, int Nc,
    long sB, long sBias, long sC, int gelu) {
    int zb = blockIdx.z;
    Bm += (size_t)zb * sB;
    bias += (size_t)zb * sBias;
    C += (size_t)zb * sC;

    __shared__ float As[16][68];   // A tile, transposed
    __shared__ float Bs[16][64];
    int tid = threadIdx.x;
    int tx = tid & 15, ty = tid >> 4;
    int row0 = blockIdx.y * 64, col0 = blockIdx.x * 64;
    float acc[4][4] = {};

    for (int k0 = 0; k0 < Kd; k0 += 16) {
        int ar = tid >> 2, ak = (tid & 3) * 4;
        float4 a4 = *(const float4*)&A[(size_t)(row0 + ar) * Kd + k0 + ak];
        As[ak + 0][ar] = a4.x; As[ak + 1][ar] = a4.y;
        As[ak + 2][ar] = a4.z; As[ak + 3][ar] = a4.w;
        int bk = tid >> 4, bc = (tid & 15) * 4;
        *(float4*)&Bs[bk][bc] =
            *(const float4*)&Bm[(size_t)(k0 + bk) * Nc + col0 + bc];
        __syncthreads();
#pragma unroll
        for (int kk = 0; kk < 16; kk++) {
            float4 a = *(const float4*)&As[kk][ty * 4];
            float4 b = *(const float4*)&Bs[kk][tx * 4];
            float av[4] = {a.x, a.y, a.z, a.w};
            float bv[4] = {b.x, b.y, b.z, b.w};
#pragma unroll
            for (int i = 0; i < 4; i++)
#pragma unroll
                for (int j = 0; j < 4; j++)
                    acc[i][j] = fmaf(av[i], bv[j], acc[i][j]);
        }
        __syncthreads();
    }

#pragma unroll
    for (int i = 0; i < 4; i++) {
        int r = row0 + ty * 4 + i;
#pragma unroll
        for (int j = 0; j < 4; j++) {
            int c = col0 + tx * 4 + j;
            float v = acc[i][j] + bias[c];
            if (gelu) v = 0.5f * v * (1.0f + erff(v * 0.70710678118654752f));
            if (res)  v += res[(size_t)r * Nc + c];
            C[(size_t)r * Nc + c] = v;
        }
    }
}

// ---------------- fused flash attention with spatial bias ------------------
constexpr int QP = 129;   // row pad (odd) -> bank-clean
constexpr int PP = 68;
constexpr int ATTN_SMEM = (3 * 64 * QP + 64 * PP) * 4;

__global__ __launch_bounds__(256, 1) void k_attn(
    const float* __restrict__ Qg, const float* __restrict__ Kg,
    const float* __restrict__ Vg, const float* __restrict__ Bg,
    float* __restrict__ Og) {
    extern __shared__ float sm[];
    float* sQ = sm;
    float* sK = sm + 64 * QP;
    float* sV = sm + 2 * 64 * QP;
    float* sP = sm + 3 * 64 * QP;

    const int hh = blockIdx.y;
    const int q0 = blockIdx.x * 64;
    const float* q  = Qg + (size_t)hh * N * D;
    const float* kp = Kg + (size_t)hh * N * D;
    const float* vp = Vg + (size_t)hh * N * D;

    const int tid = threadIdx.x;
    const int tx = tid & 15, ty = tid >> 4;
    const int wr = tid >> 5;        // 0..7
    const int lane = tid & 31;

#pragma unroll
    for (int rr = 0; rr < 8; rr++) {
        int row = rr * 8 + wr;
        float4 t = *(const float4*)&q[(size_t)(q0 + row) * D + lane * 4];
        float* dst = &sQ[row * QP + lane * 4];
        dst[0] = t.x; dst[1] = t.y; dst[2] = t.z; dst[3] = t.w;
    }

    float m_i[4], l_i[4], o[4][8];
#pragma unroll
    for (int i = 0; i < 4; i++) {
        m_i[i] = -1e30f; l_i[i] = 0.0f;
#pragma unroll
        for (int m = 0; m < 8; m++) o[i][m] = 0.0f;
    }
    const float scale = 0.08838834764831845f;   // 1/sqrt(128)

    for (int t0 = 0; t0 < N; t0 += 64) {
#pragma unroll
        for (int rr = 0; rr < 8; rr++) {
            int row = rr * 8 + wr;
            float4 a = *(const float4*)&kp[(size_t)(t0 + row) * D + lane * 4];
            float* dk = &sK[row * QP + lane * 4];
            dk[0] = a.x; dk[1] = a.y; dk[2] = a.z; dk[3] = a.w;
            float4 b = *(const float4*)&vp[(size_t)(t0 + row) * D + lane * 4];
            float* dv = &sV[row * QP + lane * 4];
            dv[0] = b.x; dv[1] = b.y; dv[2] = b.z; dv[3] = b.w;
        }
        __syncthreads();

        // S = Q @ K^T  (cols tx+16*j : 16 distinct banks)
        float s[4][4];
#pragma unroll
        for (int i = 0; i < 4; i++)
#pragma unroll
            for (int j = 0; j < 4; j++) s[i][j] = 0.0f;

#pragma unroll 4
        for (int d = 0; d < D; d++) {
            float qv[4], kv[4];
#pragma unroll
            for (int i = 0; i < 4; i++) qv[i] = sQ[(ty * 4 + i) * QP + d];
#pragma unroll
            for (int j = 0; j < 4; j++) kv[j] = sK[(tx + 16 * j) * QP + d];
#pragma unroll
            for (int i = 0; i < 4; i++)
#pragma unroll
                for (int j = 0; j < 4; j++)
                    s[i][j] = fmaf(qv[i], kv[j], s[i][j]);
        }

        float mt[4];
#pragma unroll
        for (int i = 0; i < 4; i++) {
            const float* br = &Bg[(size_t)(q0 + ty * 4 + i) * N + t0];
            float mx = -1e30f;
#pragma unroll
            for (int j = 0; j < 4; j++) {
                s[i][j] = fmaf(s[i][j], scale, br[tx + 16 * j]);
                mx = fmaxf(mx, s[i][j]);
            }
            mt[i] = mx;
        }
#pragma unroll
        for (int i = 0; i < 4; i++) {
            float mm = mt[i];
            mm = fmaxf(mm, __shfl_xor_sync(0xffffffffu, mm, 1));
            mm = fmaxf(mm, __shfl_xor_sync(0xffffffffu, mm, 2));
            mm = fmaxf(mm, __shfl_xor_sync(0xffffffffu, mm, 4));
            mm = fmaxf(mm, __shfl_xor_sync(0xffffffffu, mm, 8));
            mt[i] = mm;
        }
#pragma unroll
        for (int i = 0; i < 4; i++) {
            float mnew = fmaxf(m_i[i], mt[i]);
            float corr = __expf(m_i[i] - mnew);
            m_i[i] = mnew;
            float rs = 0.0f;
#pragma unroll
            for (int j = 0; j < 4; j++) {
                float p = __expf(s[i][j] - mnew);
                sP[(ty * 4 + i) * PP + tx + 16 * j] = p;
                rs += p;
            }
            rs += __shfl_xor_sync(0xffffffffu, rs, 1);
            rs += __shfl_xor_sync(0xffffffffu, rs, 2);
            rs += __shfl_xor_sync(0xffffffffu, rs, 4);
            rs += __shfl_xor_sync(0xffffffffu, rs, 8);
            l_i[i] = l_i[i] * corr + rs;
#pragma unroll
            for (int m = 0; m < 8; m++) o[i][m] *= corr;
        }
        __syncthreads();

        // O += P @ V  (cols tx+16*m : conflict-free)
#pragma unroll 8
        for (int jj = 0; jj < 64; jj++) {
            float p0 = sP[(ty * 4 + 0) * PP + jj];
            float p1 = sP[(ty * 4 + 1) * PP + jj];
            float p2 = sP[(ty * 4 + 2) * PP + jj];
            float p3 = sP[(ty * 4 + 3) * PP + jj];
#pragma unroll
            for (int m = 0; m < 8; m++) {
                float vv = sV[jj * QP + tx + 16 * m];
                o[0][m] = fmaf(p0, vv, o[0][m]);
                o[1][m] = fmaf(p1, vv, o[1][m]);
                o[2][m] = fmaf(p2, vv, o[2][m]);
                o[3][m] = fmaf(p3, vv, o[3][m]);
            }
        }
        __syncthreads();
    }

#pragma unroll
    for (int i = 0; i < 4; i++) {
        float inv = 1.0f / l_i[i];
        int row = q0 + ty * 4 + i;
#pragma unroll
        for (int m = 0; m < 8; m++)
            Og[(size_t)row * (H * D) + hh * D + tx + 16 * m] = o[i][m] * inv;
    }
}

// ---------------- launch ---------------------------------------------------
extern "C" void kernel_launch(void* const* d_in, const int* in_sizes, int n_in,
                              void* d_out, int out_size) {
    const float* x         = (const float*)d_in[0];
    const int*   ei        = (const int*)d_in[1];
    const float* pos       = (const float*)d_in[3];
    const float* node_in_w = (const float*)d_in[4];
    const float* node_in_b = (const float*)d_in[5];
    const float* z_in      = (const float*)d_in[8];
    const float* z_out     = (const float*)d_in[9];
    const float* sp_mu     = (const float*)d_in[10];
    const float* sp_sigma  = (const float*)d_in[11];
    const float* sp_w      = (const float*)d_in[12];
    const float* sp_b      = (const float*)d_in[13];
    const float* Wq        = (const float*)d_in[14];
    const float* bq        = (const float*)d_in[15];
    const float* Wk        = (const float*)d_in[16];
    const float* bk        = (const float*)d_in[17];
    const float* Wv        = (const float*)d_in[18];
    const float* bv        = (const float*)d_in[19];
    const float* Wo        = (const float*)d_in[20];
    const float* bo        = (const float*)d_in[21];
    const float* ln1_g     = (const float*)d_in[22];
    const float* ln1_b     = (const float*)d_in[23];
    const float* ln2_g     = (const float*)d_in[24];
    const float* ln2_b     = (const float*)d_in[25];
    const float* ff1_w     = (const float*)d_in[26];
    const float* ff1_b     = (const float*)d_in[27];
    const float* ff2_w     = (const float*)d_in[28];
    const float* ff2_b     = (const float*)d_in[29];
    const float* out_w     = (const float*)d_in[30];
    const float* out_b     = (const float*)d_in[31];
    float* out = (float*)d_out;

    float *p_h, *p_xn, *p_bias, *p_q, *p_k, *p_v, *p_ao, *p_ff;
    cudaGetSymbolAddress((void**)&p_h, g_h);
    cudaGetSymbolAddress((void**)&p_xn, g_xn);
    cudaGetSymbolAddress((void**)&p_bias, g_spbias);
    cudaGetSymbolAddress((void**)&p_q, g_q);
    cudaGetSymbolAddress((void**)&p_k, g_k);
    cudaGetSymbolAddress((void**)&p_v, g_v);
    cudaGetSymbolAddress((void**)&p_ao, g_ao);
    cudaGetSymbolAddress((void**)&p_ff, g_ff);

    static int smem_set = 0;
    if (!smem_set) {
        cudaFuncSetAttribute(k_attn,
                             cudaFuncAttributeMaxDynamicSharedMemorySize,
                             ATTN_SMEM);
        smem_set = 1;
    }

    k_zero_deg<<<(N + 255) / 256, 256>>>();
    k_deg<<<(E + 255) / 256, 256>>>(ei);
    k_spbias<<<dim3(N / 256, N), 256>>>(pos, sp_mu, sp_sigma, sp_w, sp_b);
    k_embed<<<N, D>>>(x, node_in_w, node_in_b, z_in, z_out);

    for (int l = 0; l < NL; l++) {
        k_ln<<<N, 128>>>(p_h, ln1_g + l * D, ln1_b + l * D, p_xn);
        k_gemm<<<dim3(D / 64, N / 64, H), 256>>>(
            p_xn, Wq + (size_t)l * H * D * D, bq + (size_t)l * H * D, nullptr,
            p_q, N, D, D, (long)D * D, (long)D, (long)N * D, 0);
        k_gemm<<<dim3(D / 64, N / 64, H), 256>>>(
            p_xn, Wk + (size_t)l * H * D * D, bk + (size_t)l * H * D, nullptr,
            p_k, N, D, D, (long)D * D, (long)D, (long)N * D, 0);
        k_gemm<<<dim3(D / 64, N / 64, H), 256>>>(
            p_xn, Wv + (size_t)l * H * D * D, bv + (size_t)l * H * D, nullptr,
            p_v, N, D, D, (long)D * D, (long)D, (long)N * D, 0);

        k_attn<<<dim3(N / 64, H), 256, ATTN_SMEM>>>(p_q, p_k, p_v, p_bias,
                                                    p_ao);

        k_gemm<<<dim3(D / 64, N / 64, 1), 256>>>(
            p_ao, Wo + (size_t)l * H * D * D, bo + (size_t)l * D, p_h,
            p_h, N, H * D, D, 0, 0, 0, 0);

        k_ln<<<N, 128>>>(p_h, ln2_g + l * D, ln2_b + l * D, p_xn);
        k_gemm<<<dim3(FFD / 64, N / 64, 1), 256>>>(
            p_xn, ff1_w + (size_t)l * D * FFD, ff1_b + (size_t)l * FFD,
            nullptr, p_ff, N, D, FFD, 0, 0, 0, 1);
        k_gemm<<<dim3(D / 64, N / 64, 1), 256>>>(
            p_ff, ff2_w + (size_t)l * FFD * D, ff2_b + (size_t)l * D, p_h,
            p_h, N, FFD, D, 0, 0, 0, 0);
    }

    k_gemm<<<dim3(OUTD / 64, N / 64, 1), 256>>>(
        p_h, out_w, out_b, nullptr, out, N, D, OUTD, 0, 0, 0, 0);
}

// round 3
// speedup vs baseline: 1.6616x; 1.6616x over previous
#include <cuda_runtime.h>
#include <math.h>
#include <stdint.h>

namespace cfg {
constexpr int N    = 2048;
constexpr int D    = 128;
constexpr int H    = 8;
constexpr int FFD  = 512;
constexpr int NL   = 3;
constexpr int E    = 65536;
constexpr int HS   = 8;
constexpr int OUTD = 64;
}
using namespace cfg;

// ---------------- scratch ---------------------------------------------------
__device__ float g_h[N * D];
__device__ float g_xn[N * D];
__device__ float g_spbias[(size_t)N * N];
__device__ float g_q[H * N * D];
__device__ float g_k[H * N * D];
__device__ float g_v[H * N * D];
__device__ float g_ao[N * H * D];   // [n][h*D + e]
__device__ float g_ff[N * FFD];
__device__ int   g_indeg[N];
__device__ int   g_outdeg[N];

constexpr int TABN = 16384;
constexpr float DMAX = 16.0f;
__device__ float g_tab[TABN];

// ---------------- degrees ---------------------------------------------------
__global__ void k_zero_deg() {
    int i = blockIdx.x * blockDim.x + threadIdx.x;
    if (i < N) { g_indeg[i] = 0; g_outdeg[i] = 0; }
}

__global__ void k_deg(const int* __restrict__ ei) {
    int e = blockIdx.x * blockDim.x + threadIdx.x;
    if (e < E) {
        atomicAdd(&g_outdeg[ei[e]], 1);
        atomicAdd(&g_indeg[ei[E + e]], 1);
    }
}

// ---------------- node embedding --------------------------------------------
__global__ void k_embed(const float* __restrict__ x,
                        const float* __restrict__ W,
                        const float* __restrict__ b,
                        const float* __restrict__ z_in,
                        const float* __restrict__ z_out) {
    int n = blockIdx.x;
    int d = threadIdx.x;
    __shared__ float xs[16];
    if (d < 16) xs[d] = x[n * 16 + d];
    __syncthreads();
    float acc = b[d];
#pragma unroll
    for (int k = 0; k < 16; k++) acc = fmaf(xs[k], W[k * D + d], acc);
    int id = min(g_indeg[n], 63);
    int od = min(g_outdeg[n], 63);
    acc += z_in[id * D + d] + z_out[od * D + d];
    g_h[n * D + d] = acc;
}

// ---------------- spatial bias: table build + interp ------------------------
__global__ void k_tab(const float* __restrict__ mu,
                      const float* __restrict__ sig,
                      const float* __restrict__ w,
                      const float* __restrict__ b0) {
    int i = blockIdx.x * blockDim.x + threadIdx.x;
    float d = (float)i * (DMAX / (float)(TABN - 1));
    float acc = b0[0];
#pragma unroll
    for (int k = 0; k < HS; k++) {
        float t = (d - mu[k]) / sig[k];
        acc = fmaf(w[k], expf(-0.5f * t * t), acc);
    }
    g_tab[i] = acc;
}

__global__ void k_spbias(const float* __restrict__ pos) {
    int j = blockIdx.x * blockDim.x + threadIdx.x;
    int i = blockIdx.y;
    float dx = pos[i * 3]     - pos[j * 3];
    float dy = pos[i * 3 + 1] - pos[j * 3 + 1];
    float dz = pos[i * 3 + 2] - pos[j * 3 + 2];
    float dist = sqrtf(dx * dx + dy * dy + dz * dz + 1e-12f);
    float xx = fminf(dist, DMAX) * ((float)(TABN - 1) / DMAX);
    int i0 = min((int)xx, TABN - 2);
    float fr = xx - (float)i0;
    float t0 = g_tab[i0], t1 = g_tab[i0 + 1];
    g_spbias[(size_t)i * N + j] = t0 + fr * (t1 - t0);
}

// ---------------- layernorm -------------------------------------------------
__global__ void k_ln(const float* __restrict__ in,
                     const float* __restrict__ g,
                     const float* __restrict__ b,
                     float* __restrict__ out) {
    int n = blockIdx.x, d = threadIdx.x;
    float v = in[n * D + d];
    float s = v;
#pragma unroll
    for (int o = 16; o; o >>= 1) s += __shfl_xor_sync(0xffffffffu, s, o);
    __shared__ float r1[4], r2[4];
    int w = d >> 5;
    if ((d & 31) == 0) r1[w] = s;
    __syncthreads();
    float mean = (r1[0] + r1[1] + r1[2] + r1[3]) * (1.0f / D);
    float t = v - mean;
    float s2 = t * t;
#pragma unroll
    for (int o = 16; o; o >>= 1) s2 += __shfl_xor_sync(0xffffffffu, s2, o);
    if ((d & 31) == 0) r2[w] = s2;
    __syncthreads();
    float var = (r2[0] + r2[1] + r2[2] + r2[3]) * (1.0f / D);
    out[n * D + d] = t * rsqrtf(var + 1e-5f) * g[d] + b[d];
}

// ---------------- tiled GEMM with fused epilogue (scalar fp32) --------------
__global__ __launch_bounds__(256) void k_gemm(
    const float* __restrict__ A, const float* __restrict__ Bm,
    const float* __restrict__ bias, const float* __restrict__ res,
    float* __restrict__ C, int M, int Kd, int Nc,
    long sB, long sBias, long sC, int gelu) {
    int zb = blockIdx.z;
    Bm += (size_t)zb * sB;
    bias += (size_t)zb * sBias;
    C += (size_t)zb * sC;

    __shared__ float As[16][68];
    __shared__ float Bs[16][64];
    int tid = threadIdx.x;
    int tx = tid & 15, ty = tid >> 4;
    int row0 = blockIdx.y * 64, col0 = blockIdx.x * 64;
    float acc[4][4] = {};

    for (int k0 = 0; k0 < Kd; k0 += 16) {
        int ar = tid >> 2, ak = (tid & 3) * 4;
        float4 a4 = *(const float4*)&A[(size_t)(row0 + ar) * Kd + k0 + ak];
        As[ak + 0][ar] = a4.x; As[ak + 1][ar] = a4.y;
        As[ak + 2][ar] = a4.z; As[ak + 3][ar] = a4.w;
        int bk = tid >> 4, bc = (tid & 15) * 4;
        *(float4*)&Bs[bk][bc] =
            *(const float4*)&Bm[(size_t)(k0 + bk) * Nc + col0 + bc];
        __syncthreads();
#pragma unroll
        for (int kk = 0; kk < 16; kk++) {
            float4 a = *(const float4*)&As[kk][ty * 4];
            float4 b = *(const float4*)&Bs[kk][tx * 4];
            float av[4] = {a.x, a.y, a.z, a.w};
            float bv[4] = {b.x, b.y, b.z, b.w};
#pragma unroll
            for (int i = 0; i < 4; i++)
#pragma unroll
                for (int j = 0; j < 4; j++)
                    acc[i][j] = fmaf(av[i], bv[j], acc[i][j]);
        }
        __syncthreads();
    }

#pragma unroll
    for (int i = 0; i < 4; i++) {
        int r = row0 + ty * 4 + i;
#pragma unroll
        for (int j = 0; j < 4; j++) {
            int c = col0 + tx * 4 + j;
            float v = acc[i][j] + bias[c];
            if (gelu) v = 0.5f * v * (1.0f + erff(v * 0.70710678118654752f));
            if (res)  v += res[(size_t)r * Nc + c];
            C[(size_t)r * Nc + c] = v;
        }
    }
}

// ---------------- tf32 tensor-core flash attention --------------------------
// BM=128 (8 warps x m16), BN=64, D=128. mma.m16n8k8 tf32, fp32 accumulate.
// smem strides: sQ/sP stride % 32 == 4 (a-frag pattern g*s+t conflict-free),
//               sKt/sV stride % 32 == 8 (b-frag pattern t*s+g conflict-free).
constexpr int QS  = 132;
constexpr int KTS = 72;
constexpr int VS  = 136;
constexpr int PS  = 68;
constexpr int SM_Q  = 0;
constexpr int SM_KT = SM_Q  + 128 * QS;     // 16896
constexpr int SM_V  = SM_KT + 128 * KTS;    // +9216
constexpr int SM_P  = SM_V  + 64 * VS;      // +8704
constexpr int ATTN_FLOATS = SM_P + 128 * PS;
constexpr int ATTN_SMEM = ATTN_FLOATS * 4;  // 174080 bytes

__device__ __forceinline__ unsigned f2tf(float v) {
    unsigned r;
    asm("cvt.rna.tf32.f32 %0, %1;" : "=r"(r) : "f"(v));
    return r;
}

__device__ __forceinline__ void mma8(float* d, unsigned a0, unsigned a1,
                                     unsigned a2, unsigned a3,
                                     unsigned b0, unsigned b1) {
    asm volatile(
        "mma.sync.aligned.m16n8k8.row.col.f32.tf32.tf32.f32 "
        "{%0,%1,%2,%3}, {%4,%5,%6,%7}, {%8,%9}, {%0,%1,%2,%3};"
        : "+f"(d[0]), "+f"(d[1]), "+f"(d[2]), "+f"(d[3])
        : "r"(a0), "r"(a1), "r"(a2), "r"(a3), "r"(b0), "r"(b1));
}

__global__ __launch_bounds__(256, 1) void k_attn(
    const float* __restrict__ Qg, const float* __restrict__ Kg,
    const float* __restrict__ Vg, const float* __restrict__ Bg,
    float* __restrict__ Og) {
    extern __shared__ float sm[];
    float* sQ  = sm + SM_Q;
    float* sKt = sm + SM_KT;
    float* sV  = sm + SM_V;
    float* sP  = sm + SM_P;

    const int hh = blockIdx.y;
    const int q0 = blockIdx.x * 128;
    const float* q  = Qg + (size_t)hh * N * D;
    const float* kp = Kg + (size_t)hh * N * D;
    const float* vp = Vg + (size_t)hh * N * D;

    const int tid  = threadIdx.x;
    const int wid  = tid >> 5;
    const int lane = tid & 31;
    const int g    = lane >> 2;       // group id 0..7
    const int t    = lane & 3;        // thread-in-group
    const int wm   = wid * 16;        // warp's row base

    // ---- load Q tile (tf32-converted) ----
#pragma unroll
    for (int i = 0; i < 16; i++) {
        int idx = tid + 256 * i;
        int r = idx >> 5, c = (idx & 31) * 4;
        float4 v4 = *(const float4*)&q[(size_t)(q0 + r) * D + c];
        float* dst = &sQ[r * QS + c];
        dst[0] = __uint_as_float(f2tf(v4.x));
        dst[1] = __uint_as_float(f2tf(v4.y));
        dst[2] = __uint_as_float(f2tf(v4.z));
        dst[3] = __uint_as_float(f2tf(v4.w));
    }

    float of[16][4];
#pragma unroll
    for (int dt = 0; dt < 16; dt++)
#pragma unroll
        for (int j = 0; j < 4; j++) of[dt][j] = 0.0f;
    float m0 = -1e30f, m1 = -1e30f, l0 = 0.0f, l1 = 0.0f;
    const float scale = 0.08838834764831845f;   // 1/sqrt(128)

    for (int t0 = 0; t0 < N; t0 += 64) {
        // ---- load K^T and V tiles ----
#pragma unroll
        for (int i = 0; i < 8; i++) {
            int idx = tid + 256 * i;
            int n = idx >> 5, c = (idx & 31) * 4;
            float4 kv = *(const float4*)&kp[(size_t)(t0 + n) * D + c];
            sKt[(c + 0) * KTS + n] = __uint_as_float(f2tf(kv.x));
            sKt[(c + 1) * KTS + n] = __uint_as_float(f2tf(kv.y));
            sKt[(c + 2) * KTS + n] = __uint_as_float(f2tf(kv.z));
            sKt[(c + 3) * KTS + n] = __uint_as_float(f2tf(kv.w));
            float4 vv = *(const float4*)&vp[(size_t)(t0 + n) * D + c];
            float* dv = &sV[n * VS + c];
            dv[0] = __uint_as_float(f2tf(vv.x));
            dv[1] = __uint_as_float(f2tf(vv.y));
            dv[2] = __uint_as_float(f2tf(vv.z));
            dv[3] = __uint_as_float(f2tf(vv.w));
        }
        __syncthreads();

        // ---- S = Q @ K^T ----
        float sf[8][4];
#pragma unroll
        for (int nt = 0; nt < 8; nt++)
#pragma unroll
            for (int j = 0; j < 4; j++) sf[nt][j] = 0.0f;

        const float* qb = &sQ[(wm + g) * QS];
#pragma unroll
        for (int k0 = 0; k0 < 128; k0 += 8) {
            unsigned a0 = __float_as_uint(qb[k0 + t]);
            unsigned a1 = __float_as_uint(qb[8 * QS + k0 + t]);
            unsigned a2 = __float_as_uint(qb[k0 + t + 4]);
            unsigned a3 = __float_as_uint(qb[8 * QS + k0 + t + 4]);
            const float* kb  = &sKt[(k0 + t) * KTS];
            const float* kb4 = &sKt[(k0 + t + 4) * KTS];
#pragma unroll
            for (int nt = 0; nt < 8; nt++) {
                unsigned b0 = __float_as_uint(kb[nt * 8 + g]);
                unsigned b1 = __float_as_uint(kb4[nt * 8 + g]);
                mma8(sf[nt], a0, a1, a2, a3, b0, b1);
            }
        }

        // ---- scale + bias + online softmax ----
        const float* br0 = &Bg[(size_t)(q0 + wm + g) * N + t0];
        const float* br1 = br0 + 8 * N;
        float mx0 = -1e30f, mx1 = -1e30f;
#pragma unroll
        for (int nt = 0; nt < 8; nt++) {
            float2 b01 = *(const float2*)&br0[nt * 8 + 2 * t];
            float2 b23 = *(const float2*)&br1[nt * 8 + 2 * t];
            sf[nt][0] = fmaf(sf[nt][0], scale, b01.x);
            sf[nt][1] = fmaf(sf[nt][1], scale, b01.y);
            sf[nt][2] = fmaf(sf[nt][2], scale, b23.x);
            sf[nt][3] = fmaf(sf[nt][3], scale, b23.y);
            mx0 = fmaxf(mx0, fmaxf(sf[nt][0], sf[nt][1]));
            mx1 = fmaxf(mx1, fmaxf(sf[nt][2], sf[nt][3]));
        }
        mx0 = fmaxf(mx0, __shfl_xor_sync(0xffffffffu, mx0, 1));
        mx0 = fmaxf(mx0, __shfl_xor_sync(0xffffffffu, mx0, 2));
        mx1 = fmaxf(mx1, __shfl_xor_sync(0xffffffffu, mx1, 1));
        mx1 = fmaxf(mx1, __shfl_xor_sync(0xffffffffu, mx1, 2));

        float mn0 = fmaxf(m0, mx0), mn1 = fmaxf(m1, mx1);
        float c0 = __expf(m0 - mn0), c1 = __expf(m1 - mn1);
        m0 = mn0; m1 = mn1;

        float rs0 = 0.0f, rs1 = 0.0f;
        float* pr0 = &sP[(wm + g) * PS];
        float* pr1 = pr0 + 8 * PS;
#pragma unroll
        for (int nt = 0; nt < 8; nt++) {
            float p0 = __uint_as_float(f2tf(__expf(sf[nt][0] - mn0)));
            float p1 = __uint_as_float(f2tf(__expf(sf[nt][1] - mn0)));
            float p2 = __uint_as_float(f2tf(__expf(sf[nt][2] - mn1)));
            float p3 = __uint_as_float(f2tf(__expf(sf[nt][3] - mn1)));
            rs0 += p0 + p1; rs1 += p2 + p3;
            *(float2*)&pr0[nt * 8 + 2 * t] = make_float2(p0, p1);
            *(float2*)&pr1[nt * 8 + 2 * t] = make_float2(p2, p3);
        }
        rs0 += __shfl_xor_sync(0xffffffffu, rs0, 1);
        rs0 += __shfl_xor_sync(0xffffffffu, rs0, 2);
        rs1 += __shfl_xor_sync(0xffffffffu, rs1, 1);
        rs1 += __shfl_xor_sync(0xffffffffu, rs1, 2);
        l0 = l0 * c0 + rs0;
        l1 = l1 * c1 + rs1;
#pragma unroll
        for (int dt = 0; dt < 16; dt++) {
            of[dt][0] *= c0; of[dt][1] *= c0;
            of[dt][2] *= c1; of[dt][3] *= c1;
        }
        __syncwarp();

        // ---- O += P @ V ----
        const float* pb = &sP[(wm + g) * PS];
#pragma unroll
        for (int j0 = 0; j0 < 64; j0 += 8) {
            unsigned a0 = __float_as_uint(pb[j0 + t]);
            unsigned a1 = __float_as_uint(pb[8 * PS + j0 + t]);
            unsigned a2 = __float_as_uint(pb[j0 + t + 4]);
            unsigned a3 = __float_as_uint(pb[8 * PS + j0 + t + 4]);
            const float* vb  = &sV[(j0 + t) * VS];
            const float* vb4 = &sV[(j0 + t + 4) * VS];
#pragma unroll
            for (int dt = 0; dt < 16; dt++) {
                unsigned b0 = __float_as_uint(vb[dt * 8 + g]);
                unsigned b1 = __float_as_uint(vb4[dt * 8 + g]);
                mma8(of[dt], a0, a1, a2, a3, b0, b1);
            }
        }
        __syncthreads();
    }

    // ---- epilogue ----
    float inv0 = 1.0f / l0, inv1 = 1.0f / l1;
    int row0 = q0 + wm + g, row1 = row0 + 8;
#pragma unroll
    for (int dt = 0; dt < 16; dt++) {
        int col = hh * D + dt * 8 + 2 * t;
        *(float2*)&Og[(size_t)row0 * (H * D) + col] =
            make_float2(of[dt][0] * inv0, of[dt][1] * inv0);
        *(float2*)&Og[(size_t)row1 * (H * D) + col] =
            make_float2(of[dt][2] * inv1, of[dt][3] * inv1);
    }
}

// ---------------- launch ----------------------------------------------------
extern "C" void kernel_launch(void* const* d_in, const int* in_sizes, int n_in,
                              void* d_out, int out_size) {
    const float* x         = (const float*)d_in[0];
    const int*   ei        = (const int*)d_in[1];
    const float* pos       = (const float*)d_in[3];
    const float* node_in_w = (const float*)d_in[4];
    const float* node_in_b = (const float*)d_in[5];
    const float* z_in      = (const float*)d_in[8];
    const float* z_out     = (const float*)d_in[9];
    const float* sp_mu     = (const float*)d_in[10];
    const float* sp_sigma  = (const float*)d_in[11];
    const float* sp_w      = (const float*)d_in[12];
    const float* sp_b      = (const float*)d_in[13];
    const float* Wq        = (const float*)d_in[14];
    const float* bq        = (const float*)d_in[15];
    const float* Wk        = (const float*)d_in[16];
    const float* bk        = (const float*)d_in[17];
    const float* Wv        = (const float*)d_in[18];
    const float* bv        = (const float*)d_in[19];
    const float* Wo        = (const float*)d_in[20];
    const float* bo        = (const float*)d_in[21];
    const float* ln1_g     = (const float*)d_in[22];
    const float* ln1_b     = (const float*)d_in[23];
    const float* ln2_g     = (const float*)d_in[24];
    const float* ln2_b     = (const float*)d_in[25];
    const float* ff1_w     = (const float*)d_in[26];
    const float* ff1_b     = (const float*)d_in[27];
    const float* ff2_w     = (const float*)d_in[28];
    const float* ff2_b     = (const float*)d_in[29];
    const float* out_w     = (const float*)d_in[30];
    const float* out_b     = (const float*)d_in[31];
    float* out = (float*)d_out;

    float *p_h, *p_xn, *p_bias, *p_q, *p_k, *p_v, *p_ao, *p_ff;
    cudaGetSymbolAddress((void**)&p_h, g_h);
    cudaGetSymbolAddress((void**)&p_xn, g_xn);
    cudaGetSymbolAddress((void**)&p_bias, g_spbias);
    cudaGetSymbolAddress((void**)&p_q, g_q);
    cudaGetSymbolAddress((void**)&p_k, g_k);
    cudaGetSymbolAddress((void**)&p_v, g_v);
    cudaGetSymbolAddress((void**)&p_ao, g_ao);
    cudaGetSymbolAddress((void**)&p_ff, g_ff);

    cudaFuncSetAttribute(k_attn, cudaFuncAttributeMaxDynamicSharedMemorySize,
                         ATTN_SMEM);

    k_zero_deg<<<(N + 255) / 256, 256>>>();
    k_deg<<<(E + 255) / 256, 256>>>(ei);
    k_tab<<<TABN / 256, 256>>>(sp_mu, sp_sigma, sp_w, sp_b);
    k_spbias<<<dim3(N / 256, N), 256>>>(pos);
    k_embed<<<N, D>>>(x, node_in_w, node_in_b, z_in, z_out);

    for (int l = 0; l < NL; l++) {
        k_ln<<<N, 128>>>(p_h, ln1_g + l * D, ln1_b + l * D, p_xn);
        k_gemm<<<dim3(D / 64, N / 64, H), 256>>>(
            p_xn, Wq + (size_t)l * H * D * D, bq + (size_t)l * H * D, nullptr,
            p_q, N, D, D, (long)D * D, (long)D, (long)N * D, 0);
        k_gemm<<<dim3(D / 64, N / 64, H), 256>>>(
            p_xn, Wk + (size_t)l * H * D * D, bk + (size_t)l * H * D, nullptr,
            p_k, N, D, D, (long)D * D, (long)D, (long)N * D, 0);
        k_gemm<<<dim3(D / 64, N / 64, H), 256>>>(
            p_xn, Wv + (size_t)l * H * D * D, bv + (size_t)l * H * D, nullptr,
            p_v, N, D, D, (long)D * D, (long)D, (long)N * D, 0);

        k_attn<<<dim3(N / 128, H), 256, ATTN_SMEM>>>(p_q, p_k, p_v, p_bias,
                                                     p_ao);

        k_gemm<<<dim3(D / 64, N / 64, 1), 256>>>(
            p_ao, Wo + (size_t)l * H * D * D, bo + (size_t)l * D, p_h,
            p_h, N, H * D, D, 0, 0, 0, 0);

        k_ln<<<N, 128>>>(p_h, ln2_g + l * D, ln2_b + l * D, p_xn);
        k_gemm<<<dim3(FFD / 64, N / 64, 1), 256>>>(
            p_xn, ff1_w + (size_t)l * D * FFD, ff1_b + (size_t)l * FFD,
            nullptr, p_ff, N, D, FFD, 0, 0, 0, 1);
        k_gemm<<<dim3(D / 64, N / 64, 1), 256>>>(
            p_ff, ff2_w + (size_t)l * FFD * D, ff2_b + (size_t)l * D, p_h,
            p_h, N, FFD, D, 0, 0, 0, 0);
    }

    k_gemm<<<dim3(OUTD / 64, N / 64, 1), 256>>>(
        p_h, out_w, out_b, nullptr, out, N, D, OUTD, 0, 0, 0, 0);
}

// round 4
// speedup vs baseline: 1.9272x; 1.1598x over previous
#include <cuda_runtime.h>
#include <math.h>
#include <stdint.h>

namespace cfg {
constexpr int N    = 2048;
constexpr int D    = 128;
constexpr int H    = 8;
constexpr int FFD  = 512;
constexpr int NL   = 3;
constexpr int E    = 65536;
constexpr int HS   = 8;
constexpr int OUTD = 64;
}
using namespace cfg;

// ---------------- scratch ---------------------------------------------------
__device__ float g_h[N * D];
__device__ float g_xn[N * D];
__device__ float g_spbias[(size_t)N * N];
__device__ float g_q[H * N * D];
__device__ float g_k[H * N * D];
__device__ float g_v[H * N * D];
__device__ float g_ao[N * H * D];   // [n][h*D + e]
__device__ float g_ff[N * FFD];
__device__ int   g_indeg[N];
__device__ int   g_outdeg[N];

constexpr int TABN = 16384;
constexpr float DMAX = 16.0f;
__device__ float g_tab[TABN];

// ---------------- helpers ----------------------------------------------------
__device__ __forceinline__ unsigned f2tf(float v) {
    unsigned r;
    asm("cvt.rna.tf32.f32 %0, %1;" : "=r"(r) : "f"(v));
    return r;
}

__device__ __forceinline__ void mma8(float* d, unsigned a0, unsigned a1,
                                     unsigned a2, unsigned a3,
                                     unsigned b0, unsigned b1) {
    asm volatile(
        "mma.sync.aligned.m16n8k8.row.col.f32.tf32.tf32.f32 "
        "{%0,%1,%2,%3}, {%4,%5,%6,%7}, {%8,%9}, {%0,%1,%2,%3};"
        : "+f"(d[0]), "+f"(d[1]), "+f"(d[2]), "+f"(d[3])
        : "r"(a0), "r"(a1), "r"(a2), "r"(a3), "r"(b0), "r"(b1));
}

// ---------------- degrees ----------------------------------------------------
__global__ void k_zero_deg() {
    int i = blockIdx.x * blockDim.x + threadIdx.x;
    if (i < N) { g_indeg[i] = 0; g_outdeg[i] = 0; }
}

__global__ void k_deg(const int* __restrict__ ei) {
    int e = blockIdx.x * blockDim.x + threadIdx.x;
    if (e < E) {
        atomicAdd(&g_outdeg[ei[e]], 1);
        atomicAdd(&g_indeg[ei[E + e]], 1);
    }
}

// ---------------- node embedding ---------------------------------------------
__global__ void k_embed(const float* __restrict__ x,
                        const float* __restrict__ W,
                        const float* __restrict__ b,
                        const float* __restrict__ z_in,
                        const float* __restrict__ z_out) {
    int n = blockIdx.x;
    int d = threadIdx.x;
    __shared__ float xs[16];
    if (d < 16) xs[d] = x[n * 16 + d];
    __syncthreads();
    float acc = b[d];
#pragma unroll
    for (int k = 0; k < 16; k++) acc = fmaf(xs[k], W[k * D + d], acc);
    int id = min(g_indeg[n], 63);
    int od = min(g_outdeg[n], 63);
    acc += z_in[id * D + d] + z_out[od * D + d];
    g_h[n * D + d] = acc;
}

// ---------------- spatial bias: table build + interp -------------------------
__global__ void k_tab(const float* __restrict__ mu,
                      const float* __restrict__ sig,
                      const float* __restrict__ w,
                      const float* __restrict__ b0) {
    int i = blockIdx.x * blockDim.x + threadIdx.x;
    float d = (float)i * (DMAX / (float)(TABN - 1));
    float acc = b0[0];
#pragma unroll
    for (int k = 0; k < HS; k++) {
        float t = (d - mu[k]) / sig[k];
        acc = fmaf(w[k], expf(-0.5f * t * t), acc);
    }
    g_tab[i] = acc;
}

__global__ void k_spbias(const float* __restrict__ pos) {
    int j = blockIdx.x * blockDim.x + threadIdx.x;
    int i = blockIdx.y;
    float dx = pos[i * 3]     - pos[j * 3];
    float dy = pos[i * 3 + 1] - pos[j * 3 + 1];
    float dz = pos[i * 3 + 2] - pos[j * 3 + 2];
    float dist = sqrtf(dx * dx + dy * dy + dz * dz + 1e-12f);
    float xx = fminf(dist, DMAX) * ((float)(TABN - 1) / DMAX);
    int i0 = min((int)xx, TABN - 2);
    float fr = xx - (float)i0;
    float t0 = g_tab[i0], t1 = g_tab[i0 + 1];
    g_spbias[(size_t)i * N + j] = t0 + fr * (t1 - t0);
}

// ---------------- layernorm --------------------------------------------------
__global__ void k_ln(const float* __restrict__ in,
                     const float* __restrict__ g,
                     const float* __restrict__ b,
                     float* __restrict__ out) {
    int n = blockIdx.x, d = threadIdx.x;
    float v = in[n * D + d];
    float s = v;
#pragma unroll
    for (int o = 16; o; o >>= 1) s += __shfl_xor_sync(0xffffffffu, s, o);
    __shared__ float r1[4], r2[4];
    int w = d >> 5;
    if ((d & 31) == 0) r1[w] = s;
    __syncthreads();
    float mean = (r1[0] + r1[1] + r1[2] + r1[3]) * (1.0f / D);
    float t = v - mean;
    float s2 = t * t;
#pragma unroll
    for (int o = 16; o; o >>= 1) s2 += __shfl_xor_sync(0xffffffffu, s2, o);
    if ((d & 31) == 0) r2[w] = s2;
    __syncthreads();
    float var = (r2[0] + r2[1] + r2[2] + r2[3]) * (1.0f / D);
    out[n * D + d] = t * rsqrtf(var + 1e-5f) * g[d] + b[d];
}

// ---------------- tf32 tensor-core GEMM with fused epilogue ------------------
// C = act(A[M,Kd] @ B[Kd,Nc] + bias) (+ res). BM=BN=64, BK=16.
// 256 thr = 8 warps in 4x2 grid; warp tile 16x32 = 4 n-tiles of m16n8k8.
// sA stride 20 (a-frag g*20+t bank-clean), sB stride 72 (t*72+g covers 32).
constexpr int AS_G = 20;
constexpr int BS_G = 72;

__global__ __launch_bounds__(256) void k_gemm_t(
    const float* __restrict__ A, const float* __restrict__ Bm,
    const float* __restrict__ bias, const float* __restrict__ res,
    float* __restrict__ C, int Kd, int Nc,
    long sB, long sBias, long sC, int gelu) {
    int zb = blockIdx.z;
    Bm += (size_t)zb * sB;
    bias += (size_t)zb * sBias;
    C += (size_t)zb * sC;

    __shared__ float sA[64 * AS_G];
    __shared__ float sBt[16 * BS_G];

    const int tid = threadIdx.x;
    const int wid = tid >> 5;
    const int lane = tid & 31;
    const int g = lane >> 2, t = lane & 3;
    const int wr = wid & 3, wc = wid >> 2;
    const int m0 = wr * 16, n0 = wc * 32;
    const int row0 = blockIdx.y * 64, col0 = blockIdx.x * 64;

    float acc[4][4] = {};

    const int ar = tid >> 2, ak = (tid & 3) * 4;      // A: 64 rows x 16 k
    const int bk = tid >> 4, bc = (tid & 15) * 4;     // B: 16 k x 64 cols

    for (int k0 = 0; k0 < Kd; k0 += 16) {
        float4 a4 = *(const float4*)&A[(size_t)(row0 + ar) * Kd + k0 + ak];
        float* da = &sA[ar * AS_G + ak];
        da[0] = __uint_as_float(f2tf(a4.x));
        da[1] = __uint_as_float(f2tf(a4.y));
        da[2] = __uint_as_float(f2tf(a4.z));
        da[3] = __uint_as_float(f2tf(a4.w));
        float4 b4 = *(const float4*)&Bm[(size_t)(k0 + bk) * Nc + col0 + bc];
        float* db = &sBt[bk * BS_G + bc];
        db[0] = __uint_as_float(f2tf(b4.x));
        db[1] = __uint_as_float(f2tf(b4.y));
        db[2] = __uint_as_float(f2tf(b4.z));
        db[3] = __uint_as_float(f2tf(b4.w));
        __syncthreads();

#pragma unroll
        for (int kc = 0; kc < 16; kc += 8) {
            unsigned a0 = __float_as_uint(sA[(m0 + g) * AS_G + kc + t]);
            unsigned a1 = __float_as_uint(sA[(m0 + g + 8) * AS_G + kc + t]);
            unsigned a2 = __float_as_uint(sA[(m0 + g) * AS_G + kc + t + 4]);
            unsigned a3 = __float_as_uint(sA[(m0 + g + 8) * AS_G + kc + t + 4]);
            const float* b0p = &sBt[(kc + t) * BS_G + n0];
            const float* b1p = &sBt[(kc + t + 4) * BS_G + n0];
#pragma unroll
            for (int nt = 0; nt < 4; nt++) {
                unsigned b0 = __float_as_uint(b0p[nt * 8 + g]);
                unsigned b1 = __float_as_uint(b1p[nt * 8 + g]);
                mma8(acc[nt], a0, a1, a2, a3, b0, b1);
            }
        }
        __syncthreads();
    }

#pragma unroll
    for (int nt = 0; nt < 4; nt++) {
#pragma unroll
        for (int half = 0; half < 2; half++) {
            int r = row0 + m0 + g + half * 8;
            int c = col0 + n0 + nt * 8 + 2 * t;
            float v0 = acc[nt][half * 2 + 0] + bias[c];
            float v1 = acc[nt][half * 2 + 1] + bias[c + 1];
            if (gelu) {
                v0 = 0.5f * v0 * (1.0f + erff(v0 * 0.70710678118654752f));
                v1 = 0.5f * v1 * (1.0f + erff(v1 * 0.70710678118654752f));
            }
            if (res) {
                v0 += res[(size_t)r * Nc + c];
                v1 += res[(size_t)r * Nc + c + 1];
            }
            *(float2*)&C[(size_t)r * Nc + c] = make_float2(v0, v1);
        }
    }
}

// ---------------- tf32 tensor-core flash attention ---------------------------
constexpr int QS  = 132;
constexpr int KTS = 72;
constexpr int VS  = 136;
constexpr int PS  = 68;
constexpr int SM_Q  = 0;
constexpr int SM_KT = SM_Q  + 128 * QS;
constexpr int SM_V  = SM_KT + 128 * KTS;
constexpr int SM_P  = SM_V  + 64 * VS;
constexpr int ATTN_FLOATS = SM_P + 128 * PS;
constexpr int ATTN_SMEM = ATTN_FLOATS * 4;

__global__ __launch_bounds__(256, 1) void k_attn(
    const float* __restrict__ Qg, const float* __restrict__ Kg,
    const float* __restrict__ Vg, const float* __restrict__ Bg,
    float* __restrict__ Og) {
    extern __shared__ float sm[];
    float* sQ  = sm + SM_Q;
    float* sKt = sm + SM_KT;
    float* sV  = sm + SM_V;
    float* sP  = sm + SM_P;

    const int hh = blockIdx.y;
    const int q0 = blockIdx.x * 128;
    const float* q  = Qg + (size_t)hh * N * D;
    const float* kp = Kg + (size_t)hh * N * D;
    const float* vp = Vg + (size_t)hh * N * D;

    const int tid  = threadIdx.x;
    const int wid  = tid >> 5;
    const int lane = tid & 31;
    const int g    = lane >> 2;
    const int t    = lane & 3;
    const int wm   = wid * 16;

#pragma unroll
    for (int i = 0; i < 16; i++) {
        int idx = tid + 256 * i;
        int r = idx >> 5, c = (idx & 31) * 4;
        float4 v4 = *(const float4*)&q[(size_t)(q0 + r) * D + c];
        float* dst = &sQ[r * QS + c];
        dst[0] = __uint_as_float(f2tf(v4.x));
        dst[1] = __uint_as_float(f2tf(v4.y));
        dst[2] = __uint_as_float(f2tf(v4.z));
        dst[3] = __uint_as_float(f2tf(v4.w));
    }

    float of[16][4];
#pragma unroll
    for (int dt = 0; dt < 16; dt++)
#pragma unroll
        for (int j = 0; j < 4; j++) of[dt][j] = 0.0f;
    float m0 = -1e30f, m1 = -1e30f, l0 = 0.0f, l1 = 0.0f;
    const float scale = 0.08838834764831845f;

    for (int t0 = 0; t0 < N; t0 += 64) {
#pragma unroll
        for (int i = 0; i < 8; i++) {
            int idx = tid + 256 * i;
            int n = idx >> 5, c = (idx & 31) * 4;
            float4 kv = *(const float4*)&kp[(size_t)(t0 + n) * D + c];
            sKt[(c + 0) * KTS + n] = __uint_as_float(f2tf(kv.x));
            sKt[(c + 1) * KTS + n] = __uint_as_float(f2tf(kv.y));
            sKt[(c + 2) * KTS + n] = __uint_as_float(f2tf(kv.z));
            sKt[(c + 3) * KTS + n] = __uint_as_float(f2tf(kv.w));
            float4 vv = *(const float4*)&vp[(size_t)(t0 + n) * D + c];
            float* dv = &sV[n * VS + c];
            dv[0] = __uint_as_float(f2tf(vv.x));
            dv[1] = __uint_as_float(f2tf(vv.y));
            dv[2] = __uint_as_float(f2tf(vv.z));
            dv[3] = __uint_as_float(f2tf(vv.w));
        }
        __syncthreads();

        float sf[8][4];
#pragma unroll
        for (int nt = 0; nt < 8; nt++)
#pragma unroll
            for (int j = 0; j < 4; j++) sf[nt][j] = 0.0f;

        const float* qb = &sQ[(wm + g) * QS];
#pragma unroll
        for (int k0 = 0; k0 < 128; k0 += 8) {
            unsigned a0 = __float_as_uint(qb[k0 + t]);
            unsigned a1 = __float_as_uint(qb[8 * QS + k0 + t]);
            unsigned a2 = __float_as_uint(qb[k0 + t + 4]);
            unsigned a3 = __float_as_uint(qb[8 * QS + k0 + t + 4]);
            const float* kb  = &sKt[(k0 + t) * KTS];
            const float* kb4 = &sKt[(k0 + t + 4) * KTS];
#pragma unroll
            for (int nt = 0; nt < 8; nt++) {
                unsigned b0 = __float_as_uint(kb[nt * 8 + g]);
                unsigned b1 = __float_as_uint(kb4[nt * 8 + g]);
                mma8(sf[nt], a0, a1, a2, a3, b0, b1);
            }
        }

        const float* br0 = &Bg[(size_t)(q0 + wm + g) * N + t0];
        const float* br1 = br0 + 8 * N;
        float mx0 = -1e30f, mx1 = -1e30f;
#pragma unroll
        for (int nt = 0; nt < 8; nt++) {
            float2 b01 = *(const float2*)&br0[nt * 8 + 2 * t];
            float2 b23 = *(const float2*)&br1[nt * 8 + 2 * t];
            sf[nt][0] = fmaf(sf[nt][0], scale, b01.x);
            sf[nt][1] = fmaf(sf[nt][1], scale, b01.y);
            sf[nt][2] = fmaf(sf[nt][2], scale, b23.x);
            sf[nt][3] = fmaf(sf[nt][3], scale, b23.y);
            mx0 = fmaxf(mx0, fmaxf(sf[nt][0], sf[nt][1]));
            mx1 = fmaxf(mx1, fmaxf(sf[nt][2], sf[nt][3]));
        }
        mx0 = fmaxf(mx0, __shfl_xor_sync(0xffffffffu, mx0, 1));
        mx0 = fmaxf(mx0, __shfl_xor_sync(0xffffffffu, mx0, 2));
        mx1 = fmaxf(mx1, __shfl_xor_sync(0xffffffffu, mx1, 1));
        mx1 = fmaxf(mx1, __shfl_xor_sync(0xffffffffu, mx1, 2));

        float mn0 = fmaxf(m0, mx0), mn1 = fmaxf(m1, mx1);
        float c0 = __expf(m0 - mn0), c1 = __expf(m1 - mn1);
        m0 = mn0; m1 = mn1;

        float rs0 = 0.0f, rs1 = 0.0f;
        float* pr0 = &sP[(wm + g) * PS];
        float* pr1 = pr0 + 8 * PS;
#pragma unroll
        for (int nt = 0; nt < 8; nt++) {
            float p0 = __uint_as_float(f2tf(__expf(sf[nt][0] - mn0)));
            float p1 = __uint_as_float(f2tf(__expf(sf[nt][1] - mn0)));
            float p2 = __uint_as_float(f2tf(__expf(sf[nt][2] - mn1)));
            float p3 = __uint_as_float(f2tf(__expf(sf[nt][3] - mn1)));
            rs0 += p0 + p1; rs1 += p2 + p3;
            *(float2*)&pr0[nt * 8 + 2 * t] = make_float2(p0, p1);
            *(float2*)&pr1[nt * 8 + 2 * t] = make_float2(p2, p3);
        }
        rs0 += __shfl_xor_sync(0xffffffffu, rs0, 1);
        rs0 += __shfl_xor_sync(0xffffffffu, rs0, 2);
        rs1 += __shfl_xor_sync(0xffffffffu, rs1, 1);
        rs1 += __shfl_xor_sync(0xffffffffu, rs1, 2);
        l0 = l0 * c0 + rs0;
        l1 = l1 * c1 + rs1;
#pragma unroll
        for (int dt = 0; dt < 16; dt++) {
            of[dt][0] *= c0; of[dt][1] *= c0;
            of[dt][2] *= c1; of[dt][3] *= c1;
        }
        __syncwarp();

        const float* pb = &sP[(wm + g) * PS];
#pragma unroll
        for (int j0 = 0; j0 < 64; j0 += 8) {
            unsigned a0 = __float_as_uint(pb[j0 + t]);
            unsigned a1 = __float_as_uint(pb[8 * PS + j0 + t]);
            unsigned a2 = __float_as_uint(pb[j0 + t + 4]);
            unsigned a3 = __float_as_uint(pb[8 * PS + j0 + t + 4]);
            const float* vb  = &sV[(j0 + t) * VS];
            const float* vb4 = &sV[(j0 + t + 4) * VS];
#pragma unroll
            for (int dt = 0; dt < 16; dt++) {
                unsigned b0 = __float_as_uint(vb[dt * 8 + g]);
                unsigned b1 = __float_as_uint(vb4[dt * 8 + g]);
                mma8(of[dt], a0, a1, a2, a3, b0, b1);
            }
        }
        __syncthreads();
    }

    float inv0 = 1.0f / l0, inv1 = 1.0f / l1;
    int row0 = q0 + wm + g, row1 = row0 + 8;
#pragma unroll
    for (int dt = 0; dt < 16; dt++) {
        int col = hh * D + dt * 8 + 2 * t;
        *(float2*)&Og[(size_t)row0 * (H * D) + col] =
            make_float2(of[dt][0] * inv0, of[dt][1] * inv0);
        *(float2*)&Og[(size_t)row1 * (H * D) + col] =
            make_float2(of[dt][2] * inv1, of[dt][3] * inv1);
    }
}

// ---------------- launch -----------------------------------------------------
extern "C" void kernel_launch(void* const* d_in, const int* in_sizes, int n_in,
                              void* d_out, int out_size) {
    const float* x         = (const float*)d_in[0];
    const int*   ei        = (const int*)d_in[1];
    const float* pos       = (const float*)d_in[3];
    const float* node_in_w = (const float*)d_in[4];
    const float* node_in_b = (const float*)d_in[5];
    const float* z_in      = (const float*)d_in[8];
    const float* z_out     = (const float*)d_in[9];
    const float* sp_mu     = (const float*)d_in[10];
    const float* sp_sigma  = (const float*)d_in[11];
    const float* sp_w      = (const float*)d_in[12];
    const float* sp_b      = (const float*)d_in[13];
    const float* Wq        = (const float*)d_in[14];
    const float* bq        = (const float*)d_in[15];
    const float* Wk        = (const float*)d_in[16];
    const float* bk        = (const float*)d_in[17];
    const float* Wv        = (const float*)d_in[18];
    const float* bv        = (const float*)d_in[19];
    const float* Wo        = (const float*)d_in[20];
    const float* bo        = (const float*)d_in[21];
    const float* ln1_g     = (const float*)d_in[22];
    const float* ln1_b     = (const float*)d_in[23];
    const float* ln2_g     = (const float*)d_in[24];
    const float* ln2_b     = (const float*)d_in[25];
    const float* ff1_w     = (const float*)d_in[26];
    const float* ff1_b     = (const float*)d_in[27];
    const float* ff2_w     = (const float*)d_in[28];
    const float* ff2_b     = (const float*)d_in[29];
    const float* out_w     = (const float*)d_in[30];
    const float* out_b     = (const float*)d_in[31];
    float* out = (float*)d_out;

    float *p_h, *p_xn, *p_bias, *p_q, *p_k, *p_v, *p_ao, *p_ff;
    cudaGetSymbolAddress((void**)&p_h, g_h);
    cudaGetSymbolAddress((void**)&p_xn, g_xn);
    cudaGetSymbolAddress((void**)&p_bias, g_spbias);
    cudaGetSymbolAddress((void**)&p_q, g_q);
    cudaGetSymbolAddress((void**)&p_k, g_k);
    cudaGetSymbolAddress((void**)&p_v, g_v);
    cudaGetSymbolAddress((void**)&p_ao, g_ao);
    cudaGetSymbolAddress((void**)&p_ff, g_ff);

    cudaFuncSetAttribute(k_attn, cudaFuncAttributeMaxDynamicSharedMemorySize,
                         ATTN_SMEM);

    k_zero_deg<<<(N + 255) / 256, 256>>>();
    k_deg<<<(E + 255) / 256, 256>>>(ei);
    k_tab<<<TABN / 256, 256>>>(sp_mu, sp_sigma, sp_w, sp_b);
    k_spbias<<<dim3(N / 256, N), 256>>>(pos);
    k_embed<<<N, D>>>(x, node_in_w, node_in_b, z_in, z_out);

    for (int l = 0; l < NL; l++) {
        k_ln<<<N, 128>>>(p_h, ln1_g + l * D, ln1_b + l * D, p_xn);
        k_gemm_t<<<dim3(D / 64, N / 64, H), 256>>>(
            p_xn, Wq + (size_t)l * H * D * D, bq + (size_t)l * H * D, nullptr,
            p_q, D, D, (long)D * D, (long)D, (long)N * D, 0);
        k_gemm_t<<<dim3(D / 64, N / 64, H), 256>>>(
            p_xn, Wk + (size_t)l * H * D * D, bk + (size_t)l * H * D, nullptr,
            p_k, D, D, (long)D * D, (long)D, (long)N * D, 0);
        k_gemm_t<<<dim3(D / 64, N / 64, H), 256>>>(
            p_xn, Wv + (size_t)l * H * D * D, bv + (size_t)l * H * D, nullptr,
            p_v, D, D, (long)D * D, (long)D, (long)N * D, 0);

        k_attn<<<dim3(N / 128, H), 256, ATTN_SMEM>>>(p_q, p_k, p_v, p_bias,
                                                     p_ao);

        k_gemm_t<<<dim3(D / 64, N / 64, 1), 256>>>(
            p_ao, Wo + (size_t)l * H * D * D, bo + (size_t)l * D, p_h,
            p_h, H * D, D, 0, 0, 0, 0);

        k_ln<<<N, 128>>>(p_h, ln2_g + l * D, ln2_b + l * D, p_xn);
        k_gemm_t<<<dim3(FFD / 64, N / 64, 1), 256>>>(
            p_xn, ff1_w + (size_t)l * D * FFD, ff1_b + (size_t)l * FFD,
            nullptr, p_ff, D, FFD, 0, 0, 0, 1);
        k_gemm_t<<<dim3(D / 64, N / 64, 1), 256>>>(
            p_ff, ff2_w + (size_t)l * FFD * D, ff2_b + (size_t)l * D, p_h,
            p_h, FFD, D, 0, 0, 0, 0);
    }

    k_gemm_t<<<dim3(OUTD / 64, N / 64, 1), 256>>>(
        p_h, out_w, out_b, nullptr, out, D, OUTD, 0, 0, 0, 0);
}

// round 5
// speedup vs baseline: 2.7739x; 1.4393x over previous
#include <cuda_runtime.h>
#include <math.h>
#include <stdint.h>

namespace cfg {
constexpr int N    = 2048;
constexpr int D    = 128;
constexpr int H    = 8;
constexpr int FFD  = 512;
constexpr int NL   = 3;
constexpr int E    = 65536;
constexpr int HS   = 8;
constexpr int OUTD = 64;
}
using namespace cfg;

// ---------------- scratch ---------------------------------------------------
__device__ float g_h[N * D];
__device__ float g_xn[N * D];
__device__ float g_spbias[(size_t)N * N];
__device__ float g_q[H * N * D];
__device__ float g_k[H * N * D];
__device__ float g_v[H * N * D];
__device__ float g_ao[N * H * D];
__device__ float g_ff[N * FFD];
__device__ int   g_indeg[N];
__device__ int   g_outdeg[N];

constexpr int TABN = 16384;
constexpr float DMAX = 16.0f;
__device__ float g_tab[TABN];

// ---------------- helpers ----------------------------------------------------
__device__ __forceinline__ unsigned f2tf(float v) {
    unsigned r;
    asm("cvt.rna.tf32.f32 %0, %1;" : "=r"(r) : "f"(v));
    return r;
}

__device__ __forceinline__ void mma8(float* d, unsigned a0, unsigned a1,
                                     unsigned a2, unsigned a3,
                                     unsigned b0, unsigned b1) {
    asm volatile(
        "mma.sync.aligned.m16n8k8.row.col.f32.tf32.tf32.f32 "
        "{%0,%1,%2,%3}, {%4,%5,%6,%7}, {%8,%9}, {%0,%1,%2,%3};"
        : "+f"(d[0]), "+f"(d[1]), "+f"(d[2]), "+f"(d[3])
        : "r"(a0), "r"(a1), "r"(a2), "r"(a3), "r"(b0), "r"(b1));
}

// ---------------- degrees ----------------------------------------------------
__global__ void k_zero_deg() {
    int i = blockIdx.x * blockDim.x + threadIdx.x;
    if (i < N) { g_indeg[i] = 0; g_outdeg[i] = 0; }
}

__global__ void k_deg(const int* __restrict__ ei) {
    int e = blockIdx.x * blockDim.x + threadIdx.x;
    if (e < E) {
        atomicAdd(&g_outdeg[ei[e]], 1);
        atomicAdd(&g_indeg[ei[E + e]], 1);
    }
}

// ---------------- node embedding ---------------------------------------------
__global__ void k_embed(const float* __restrict__ x,
                        const float* __restrict__ W,
                        const float* __restrict__ b,
                        const float* __restrict__ z_in,
                        const float* __restrict__ z_out) {
    int n = blockIdx.x;
    int d = threadIdx.x;
    __shared__ float xs[16];
    if (d < 16) xs[d] = x[n * 16 + d];
    __syncthreads();
    float acc = b[d];
#pragma unroll
    for (int k = 0; k < 16; k++) acc = fmaf(xs[k], W[k * D + d], acc);
    int id = min(g_indeg[n], 63);
    int od = min(g_outdeg[n], 63);
    acc += z_in[id * D + d] + z_out[od * D + d];
    g_h[n * D + d] = acc;
}

// ---------------- spatial bias: table build + interp -------------------------
__global__ void k_tab(const float* __restrict__ mu,
                      const float* __restrict__ sig,
                      const float* __restrict__ w,
                      const float* __restrict__ b0) {
    int i = blockIdx.x * blockDim.x + threadIdx.x;
    float d = (float)i * (DMAX / (float)(TABN - 1));
    float acc = b0[0];
#pragma unroll
    for (int k = 0; k < HS; k++) {
        float t = (d - mu[k]) / sig[k];
        acc = fmaf(w[k], expf(-0.5f * t * t), acc);
    }
    g_tab[i] = acc;
}

__global__ void k_spbias(const float* __restrict__ pos) {
    int j = blockIdx.x * blockDim.x + threadIdx.x;
    int i = blockIdx.y;
    float dx = pos[i * 3]     - pos[j * 3];
    float dy = pos[i * 3 + 1] - pos[j * 3 + 1];
    float dz = pos[i * 3 + 2] - pos[j * 3 + 2];
    float dist = sqrtf(dx * dx + dy * dy + dz * dz + 1e-12f);
    float xx = fminf(dist, DMAX) * ((float)(TABN - 1) / DMAX);
    int i0 = min((int)xx, TABN - 2);
    float fr = xx - (float)i0;
    float t0 = g_tab[i0], t1 = g_tab[i0 + 1];
    g_spbias[(size_t)i * N + j] = t0 + fr * (t1 - t0);
}

// ---------------- layernorm --------------------------------------------------
__global__ void k_ln(const float* __restrict__ in,
                     const float* __restrict__ g,
                     const float* __restrict__ b,
                     float* __restrict__ out) {
    int n = blockIdx.x, d = threadIdx.x;
    float v = in[n * D + d];
    float s = v;
#pragma unroll
    for (int o = 16; o; o >>= 1) s += __shfl_xor_sync(0xffffffffu, s, o);
    __shared__ float r1[4], r2[4];
    int w = d >> 5;
    if ((d & 31) == 0) r1[w] = s;
    __syncthreads();
    float mean = (r1[0] + r1[1] + r1[2] + r1[3]) * (1.0f / D);
    float t = v - mean;
    float s2 = t * t;
#pragma unroll
    for (int o = 16; o; o >>= 1) s2 += __shfl_xor_sync(0xffffffffu, s2, o);
    if ((d & 31) == 0) r2[w] = s2;
    __syncthreads();
    float var = (r2[0] + r2[1] + r2[2] + r2[3]) * (1.0f / D);
    out[n * D + d] = t * rsqrtf(var + 1e-5f) * g[d] + b[d];
}

// ---------------- tf32 tensor-core GEMM with fused epilogue ------------------
constexpr int AS_G = 20;
constexpr int BS_G = 72;

__global__ __launch_bounds__(256) void k_gemm_t(
    const float* __restrict__ A, const float* __restrict__ Bm,
    const float* __restrict__ bias, const float* __restrict__ res,
    float* __restrict__ C, int Kd, int Nc,
    long sB, long sBias, long sC, int gelu) {
    int zb = blockIdx.z;
    Bm += (size_t)zb * sB;
    bias += (size_t)zb * sBias;
    C += (size_t)zb * sC;

    __shared__ float sA[64 * AS_G];
    __shared__ float sBt[16 * BS_G];

    const int tid = threadIdx.x;
    const int wid = tid >> 5;
    const int lane = tid & 31;
    const int g = lane >> 2, t = lane & 3;
    const int wr = wid & 3, wc = wid >> 2;
    const int m0 = wr * 16, n0 = wc * 32;
    const int row0 = blockIdx.y * 64, col0 = blockIdx.x * 64;

    float acc[4][4] = {};

    const int ar = tid >> 2, ak = (tid & 3) * 4;
    const int bk = tid >> 4, bc = (tid & 15) * 4;

    for (int k0 = 0; k0 < Kd; k0 += 16) {
        float4 a4 = *(const float4*)&A[(size_t)(row0 + ar) * Kd + k0 + ak];
        float* da = &sA[ar * AS_G + ak];
        da[0] = __uint_as_float(f2tf(a4.x));
        da[1] = __uint_as_float(f2tf(a4.y));
        da[2] = __uint_as_float(f2tf(a4.z));
        da[3] = __uint_as_float(f2tf(a4.w));
        float4 b4 = *(const float4*)&Bm[(size_t)(k0 + bk) * Nc + col0 + bc];
        float* db = &sBt[bk * BS_G + bc];
        db[0] = __uint_as_float(f2tf(b4.x));
        db[1] = __uint_as_float(f2tf(b4.y));
        db[2] = __uint_as_float(f2tf(b4.z));
        db[3] = __uint_as_float(f2tf(b4.w));
        __syncthreads();

#pragma unroll
        for (int kc = 0; kc < 16; kc += 8) {
            unsigned a0 = __float_as_uint(sA[(m0 + g) * AS_G + kc + t]);
            unsigned a1 = __float_as_uint(sA[(m0 + g + 8) * AS_G + kc + t]);
            unsigned a2 = __float_as_uint(sA[(m0 + g) * AS_G + kc + t + 4]);
            unsigned a3 = __float_as_uint(sA[(m0 + g + 8) * AS_G + kc + t + 4]);
            const float* b0p = &sBt[(kc + t) * BS_G + n0];
            const float* b1p = &sBt[(kc + t + 4) * BS_G + n0];
#pragma unroll
            for (int nt = 0; nt < 4; nt++) {
                unsigned b0 = __float_as_uint(b0p[nt * 8 + g]);
                unsigned b1 = __float_as_uint(b1p[nt * 8 + g]);
                mma8(acc[nt], a0, a1, a2, a3, b0, b1);
            }
        }
        __syncthreads();
    }

#pragma unroll
    for (int nt = 0; nt < 4; nt++) {
#pragma unroll
        for (int half = 0; half < 2; half++) {
            int r = row0 + m0 + g + half * 8;
            int c = col0 + n0 + nt * 8 + 2 * t;
            float v0 = acc[nt][half * 2 + 0] + bias[c];
            float v1 = acc[nt][half * 2 + 1] + bias[c + 1];
            if (gelu) {
                v0 = 0.5f * v0 * (1.0f + erff(v0 * 0.70710678118654752f));
                v1 = 0.5f * v1 * (1.0f + erff(v1 * 0.70710678118654752f));
            }
            if (res) {
                v0 += res[(size_t)r * Nc + c];
                v1 += res[(size_t)r * Nc + c + 1];
            }
            *(float2*)&C[(size_t)r * Nc + c] = make_float2(v0, v1);
        }
    }
}

// ---------------- tf32 tensor-core flash attention ---------------------------
// K stored ROW-MAJOR stride 132 (132 % 32 == 4): b-frag read
// sK[(n)*132 + k] has bank = g*4 + t -> 32 distinct banks; store is one
// STS.128 (was 4x scalar STS at 32-way conflict).
constexpr int QS  = 132;
constexpr int KS  = 132;
constexpr int VS  = 136;
constexpr int PS  = 68;
constexpr int SM_Q  = 0;
constexpr int SM_K  = SM_Q + 128 * QS;      // 16896
constexpr int SM_V  = SM_K + 64 * KS;       // +8448
constexpr int SM_P  = SM_V + 64 * VS;       // +8704
constexpr int ATTN_FLOATS = SM_P + 128 * PS;
constexpr int ATTN_SMEM = ATTN_FLOATS * 4;  // 171,008 bytes

__global__ __launch_bounds__(256, 1) void k_attn(
    const float* __restrict__ Qg, const float* __restrict__ Kg,
    const float* __restrict__ Vg, const float* __restrict__ Bg,
    float* __restrict__ Og) {
    extern __shared__ float sm[];
    float* sQ = sm + SM_Q;
    float* sK = sm + SM_K;
    float* sV = sm + SM_V;
    float* sP = sm + SM_P;

    const int hh = blockIdx.y;
    const int q0 = blockIdx.x * 128;
    const float* q  = Qg + (size_t)hh * N * D;
    const float* kp = Kg + (size_t)hh * N * D;
    const float* vp = Vg + (size_t)hh * N * D;

    const int tid  = threadIdx.x;
    const int wid  = tid >> 5;
    const int lane = tid & 31;
    const int g    = lane >> 2;
    const int t    = lane & 3;
    const int wm   = wid * 16;

#pragma unroll
    for (int i = 0; i < 16; i++) {
        int idx = tid + 256 * i;
        int r = idx >> 5, c = (idx & 31) * 4;
        float4 v4 = *(const float4*)&q[(size_t)(q0 + r) * D + c];
        float* dst = &sQ[r * QS + c];
        dst[0] = __uint_as_float(f2tf(v4.x));
        dst[1] = __uint_as_float(f2tf(v4.y));
        dst[2] = __uint_as_float(f2tf(v4.z));
        dst[3] = __uint_as_float(f2tf(v4.w));
    }

    float of[16][4];
#pragma unroll
    for (int dt = 0; dt < 16; dt++)
#pragma unroll
        for (int j = 0; j < 4; j++) of[dt][j] = 0.0f;
    float m0 = -1e30f, m1 = -1e30f, l0 = 0.0f, l1 = 0.0f;
    const float scale = 0.08838834764831845f;

    for (int t0 = 0; t0 < N; t0 += 64) {
        // ---- load K (row-major) and V tiles ----
#pragma unroll
        for (int i = 0; i < 8; i++) {
            int idx = tid + 256 * i;
            int n = idx >> 5, c = (idx & 31) * 4;
            float4 kv = *(const float4*)&kp[(size_t)(t0 + n) * D + c];
            float* dk = &sK[n * KS + c];
            dk[0] = __uint_as_float(f2tf(kv.x));
            dk[1] = __uint_as_float(f2tf(kv.y));
            dk[2] = __uint_as_float(f2tf(kv.z));
            dk[3] = __uint_as_float(f2tf(kv.w));
            float4 vv = *(const float4*)&vp[(size_t)(t0 + n) * D + c];
            float* dv = &sV[n * VS + c];
            dv[0] = __uint_as_float(f2tf(vv.x));
            dv[1] = __uint_as_float(f2tf(vv.y));
            dv[2] = __uint_as_float(f2tf(vv.z));
            dv[3] = __uint_as_float(f2tf(vv.w));
        }
        __syncthreads();

        // ---- prefetch bias tile into registers (overlaps QK MMAs) ----
        const float* br0 = &Bg[(size_t)(q0 + wm + g) * N + t0];
        const float* br1 = br0 + 8 * N;
        float2 pb0[8], pb1[8];
#pragma unroll
        for (int nt = 0; nt < 8; nt++) {
            pb0[nt] = *(const float2*)&br0[nt * 8 + 2 * t];
            pb1[nt] = *(const float2*)&br1[nt * 8 + 2 * t];
        }

        // ---- S = Q @ K^T ----
        float sf[8][4];
#pragma unroll
        for (int nt = 0; nt < 8; nt++)
#pragma unroll
            for (int j = 0; j < 4; j++) sf[nt][j] = 0.0f;

        const float* qb = &sQ[(wm + g) * QS];
#pragma unroll
        for (int k0 = 0; k0 < 128; k0 += 8) {
            unsigned a0 = __float_as_uint(qb[k0 + t]);
            unsigned a1 = __float_as_uint(qb[8 * QS + k0 + t]);
            unsigned a2 = __float_as_uint(qb[k0 + t + 4]);
            unsigned a3 = __float_as_uint(qb[8 * QS + k0 + t + 4]);
#pragma unroll
            for (int nt = 0; nt < 8; nt++) {
                const float* kb = &sK[(nt * 8 + g) * KS + k0];
                unsigned b0 = __float_as_uint(kb[t]);
                unsigned b1 = __float_as_uint(kb[t + 4]);
                mma8(sf[nt], a0, a1, a2, a3, b0, b1);
            }
        }

        // ---- scale + bias + online softmax ----
        float mx0 = -1e30f, mx1 = -1e30f;
#pragma unroll
        for (int nt = 0; nt < 8; nt++) {
            sf[nt][0] = fmaf(sf[nt][0], scale, pb0[nt].x);
            sf[nt][1] = fmaf(sf[nt][1], scale, pb0[nt].y);
            sf[nt][2] = fmaf(sf[nt][2], scale, pb1[nt].x);
            sf[nt][3] = fmaf(sf[nt][3], scale, pb1[nt].y);
            mx0 = fmaxf(mx0, fmaxf(sf[nt][0], sf[nt][1]));
            mx1 = fmaxf(mx1, fmaxf(sf[nt][2], sf[nt][3]));
        }
        mx0 = fmaxf(mx0, __shfl_xor_sync(0xffffffffu, mx0, 1));
        mx0 = fmaxf(mx0, __shfl_xor_sync(0xffffffffu, mx0, 2));
        mx1 = fmaxf(mx1, __shfl_xor_sync(0xffffffffu, mx1, 1));
        mx1 = fmaxf(mx1, __shfl_xor_sync(0xffffffffu, mx1, 2));

        float mn0 = fmaxf(m0, mx0), mn1 = fmaxf(m1, mx1);
        float c0 = __expf(m0 - mn0), c1 = __expf(m1 - mn1);
        m0 = mn0; m1 = mn1;

        float rs0 = 0.0f, rs1 = 0.0f;
        float* pr0 = &sP[(wm + g) * PS];
        float* pr1 = pr0 + 8 * PS;
#pragma unroll
        for (int nt = 0; nt < 8; nt++) {
            float p0 = __uint_as_float(f2tf(__expf(sf[nt][0] - mn0)));
            float p1 = __uint_as_float(f2tf(__expf(sf[nt][1] - mn0)));
            float p2 = __uint_as_float(f2tf(__expf(sf[nt][2] - mn1)));
            float p3 = __uint_as_float(f2tf(__expf(sf[nt][3] - mn1)));
            rs0 += p0 + p1; rs1 += p2 + p3;
            *(float2*)&pr0[nt * 8 + 2 * t] = make_float2(p0, p1);
            *(float2*)&pr1[nt * 8 + 2 * t] = make_float2(p2, p3);
        }
        rs0 += __shfl_xor_sync(0xffffffffu, rs0, 1);
        rs0 += __shfl_xor_sync(0xffffffffu, rs0, 2);
        rs1 += __shfl_xor_sync(0xffffffffu, rs1, 1);
        rs1 += __shfl_xor_sync(0xffffffffu, rs1, 2);
        l0 = l0 * c0 + rs0;
        l1 = l1 * c1 + rs1;
#pragma unroll
        for (int dt = 0; dt < 16; dt++) {
            of[dt][0] *= c0; of[dt][1] *= c0;
            of[dt][2] *= c1; of[dt][3] *= c1;
        }
        __syncwarp();

        // ---- O += P @ V ----
        const float* pb = &sP[(wm + g) * PS];
#pragma unroll
        for (int j0 = 0; j0 < 64; j0 += 8) {
            unsigned a0 = __float_as_uint(pb[j0 + t]);
            unsigned a1 = __float_as_uint(pb[8 * PS + j0 + t]);
            unsigned a2 = __float_as_uint(pb[j0 + t + 4]);
            unsigned a3 = __float_as_uint(pb[8 * PS + j0 + t + 4]);
            const float* vb  = &sV[(j0 + t) * VS];
            const float* vb4 = &sV[(j0 + t + 4) * VS];
#pragma unroll
            for (int dt = 0; dt < 16; dt++) {
                unsigned b0 = __float_as_uint(vb[dt * 8 + g]);
                unsigned b1 = __float_as_uint(vb4[dt * 8 + g]);
                mma8(of[dt], a0, a1, a2, a3, b0, b1);
            }
        }
        __syncthreads();
    }

    float inv0 = 1.0f / l0, inv1 = 1.0f / l1;
    int row0 = q0 + wm + g, row1 = row0 + 8;
#pragma unroll
    for (int dt = 0; dt < 16; dt++) {
        int col = hh * D + dt * 8 + 2 * t;
        *(float2*)&Og[(size_t)row0 * (H * D) + col] =
            make_float2(of[dt][0] * inv0, of[dt][1] * inv0);
        *(float2*)&Og[(size_t)row1 * (H * D) + col] =
            make_float2(of[dt][2] * inv1, of[dt][3] * inv1);
    }
}

// ---------------- launch -----------------------------------------------------
extern "C" void kernel_launch(void* const* d_in, const int* in_sizes, int n_in,
                              void* d_out, int out_size) {
    const float* x         = (const float*)d_in[0];
    const int*   ei        = (const int*)d_in[1];
    const float* pos       = (const float*)d_in[3];
    const float* node_in_w = (const float*)d_in[4];
    const float* node_in_b = (const float*)d_in[5];
    const float* z_in      = (const float*)d_in[8];
    const float* z_out     = (const float*)d_in[9];
    const float* sp_mu     = (const float*)d_in[10];
    const float* sp_sigma  = (const float*)d_in[11];
    const float* sp_w      = (const float*)d_in[12];
    const float* sp_b      = (const float*)d_in[13];
    const float* Wq        = (const float*)d_in[14];
    const float* bq        = (const float*)d_in[15];
    const float* Wk        = (const float*)d_in[16];
    const float* bk        = (const float*)d_in[17];
    const float* Wv        = (const float*)d_in[18];
    const float* bv        = (const float*)d_in[19];
    const float* Wo        = (const float*)d_in[20];
    const float* bo        = (const float*)d_in[21];
    const float* ln1_g     = (const float*)d_in[22];
    const float* ln1_b     = (const float*)d_in[23];
    const float* ln2_g     = (const float*)d_in[24];
    const float* ln2_b     = (const float*)d_in[25];
    const float* ff1_w     = (const float*)d_in[26];
    const float* ff1_b     = (const float*)d_in[27];
    const float* ff2_w     = (const float*)d_in[28];
    const float* ff2_b     = (const float*)d_in[29];
    const float* out_w     = (const float*)d_in[30];
    const float* out_b     = (const float*)d_in[31];
    float* out = (float*)d_out;

    float *p_h, *p_xn, *p_bias, *p_q, *p_k, *p_v, *p_ao, *p_ff;
    cudaGetSymbolAddress((void**)&p_h, g_h);
    cudaGetSymbolAddress((void**)&p_xn, g_xn);
    cudaGetSymbolAddress((void**)&p_bias, g_spbias);
    cudaGetSymbolAddress((void**)&p_q, g_q);
    cudaGetSymbolAddress((void**)&p_k, g_k);
    cudaGetSymbolAddress((void**)&p_v, g_v);
    cudaGetSymbolAddress((void**)&p_ao, g_ao);
    cudaGetSymbolAddress((void**)&p_ff, g_ff);

    cudaFuncSetAttribute(k_attn, cudaFuncAttributeMaxDynamicSharedMemorySize,
                         ATTN_SMEM);

    k_zero_deg<<<(N + 255) / 256, 256>>>();
    k_deg<<<(E + 255) / 256, 256>>>(ei);
    k_tab<<<TABN / 256, 256>>>(sp_mu, sp_sigma, sp_w, sp_b);
    k_spbias<<<dim3(N / 256, N), 256>>>(pos);
    k_embed<<<N, D>>>(x, node_in_w, node_in_b, z_in, z_out);

    for (int l = 0; l < NL; l++) {
        k_ln<<<N, 128>>>(p_h, ln1_g + l * D, ln1_b + l * D, p_xn);
        k_gemm_t<<<dim3(D / 64, N / 64, H), 256>>>(
            p_xn, Wq + (size_t)l * H * D * D, bq + (size_t)l * H * D, nullptr,
            p_q, D, D, (long)D * D, (long)D, (long)N * D, 0);
        k_gemm_t<<<dim3(D / 64, N / 64, H), 256>>>(
            p_xn, Wk + (size_t)l * H * D * D, bk + (size_t)l * H * D, nullptr,
            p_k, D, D, (long)D * D, (long)D, (long)N * D, 0);
        k_gemm_t<<<dim3(D / 64, N / 64, H), 256>>>(
            p_xn, Wv + (size_t)l * H * D * D, bv + (size_t)l * H * D, nullptr,
            p_v, D, D, (long)D * D, (long)D, (long)N * D, 0);

        k_attn<<<dim3(N / 128, H), 256, ATTN_SMEM>>>(p_q, p_k, p_v, p_bias,
                                                     p_ao);

        k_gemm_t<<<dim3(D / 64, N / 64, 1), 256>>>(
            p_ao, Wo + (size_t)l * H * D * D, bo + (size_t)l * D, p_h,
            p_h, H * D, D, 0, 0, 0, 0);

        k_ln<<<N, 128>>>(p_h, ln2_g + l * D, ln2_b + l * D, p_xn);
        k_gemm_t<<<dim3(FFD / 64, N / 64, 1), 256>>>(
            p_xn, ff1_w + (size_t)l * D * FFD, ff1_b + (size_t)l * FFD,
            nullptr, p_ff, D, FFD, 0, 0, 0, 1);
        k_gemm_t<<<dim3(D / 64, N / 64, 1), 256>>>(
            p_ff, ff2_w + (size_t)l * FFD * D, ff2_b + (size_t)l * D, p_h,
            p_h, FFD, D, 0, 0, 0, 0);
    }

    k_gemm_t<<<dim3(OUTD / 64, N / 64, 1), 256>>>(
        p_h, out_w, out_b, nullptr, out, D, OUTD, 0, 0, 0, 0);
}

// round 8
// speedup vs baseline: 2.8815x; 1.0388x over previous
#include <cuda_runtime.h>
#include <math.h>
#include <stdint.h>

namespace cfg {
constexpr int N    = 2048;
constexpr int D    = 128;
constexpr int H    = 8;
constexpr int FFD  = 512;
constexpr int NL   = 3;
constexpr int E    = 65536;
constexpr int HS   = 8;
constexpr int OUTD = 64;
}
using namespace cfg;

// ---------------- scratch ---------------------------------------------------
__device__ float g_h[N * D];
__device__ float g_xn[N * D];
__device__ float g_spbias[(size_t)N * N];
__device__ float g_q[H * N * D];
__device__ float g_k[H * N * D];
__device__ float g_v[H * N * D];
__device__ float g_ao[N * H * D];
__device__ float g_ff[N * FFD];
__device__ int   g_indeg[N];
__device__ int   g_outdeg[N];

constexpr int TABN = 16384;
constexpr float DMAX = 16.0f;
__device__ float g_tab[TABN];

// ---------------- helpers ----------------------------------------------------
__device__ __forceinline__ unsigned f2tf(float v) {
    unsigned r;
    asm("cvt.rna.tf32.f32 %0, %1;" : "=r"(r) : "f"(v));
    return r;
}

__device__ __forceinline__ void mma8(float* d, unsigned a0, unsigned a1,
                                     unsigned a2, unsigned a3,
                                     unsigned b0, unsigned b1) {
    asm volatile(
        "mma.sync.aligned.m16n8k8.row.col.f32.tf32.tf32.f32 "
        "{%0,%1,%2,%3}, {%4,%5,%6,%7}, {%8,%9}, {%0,%1,%2,%3};"
        : "+f"(d[0]), "+f"(d[1]), "+f"(d[2]), "+f"(d[3])
        : "r"(a0), "r"(a1), "r"(a2), "r"(a3), "r"(b0), "r"(b1));
}

// ---------------- degrees ----------------------------------------------------
__global__ void k_zero_deg() {
    int i = blockIdx.x * blockDim.x + threadIdx.x;
    if (i < N) { g_indeg[i] = 0; g_outdeg[i] = 0; }
}

__global__ void k_deg(const int* __restrict__ ei) {
    int e = blockIdx.x * blockDim.x + threadIdx.x;
    if (e < E) {
        atomicAdd(&g_outdeg[ei[e]], 1);
        atomicAdd(&g_indeg[ei[E + e]], 1);
    }
}

// ---------------- node embedding ---------------------------------------------
__global__ void k_embed(const float* __restrict__ x,
                        const float* __restrict__ W,
                        const float* __restrict__ b,
                        const float* __restrict__ z_in,
                        const float* __restrict__ z_out) {
    int n = blockIdx.x;
    int d = threadIdx.x;
    __shared__ float xs[16];
    if (d < 16) xs[d] = x[n * 16 + d];
    __syncthreads();
    float acc = b[d];
#pragma unroll
    for (int k = 0; k < 16; k++) acc = fmaf(xs[k], W[k * D + d], acc);
    int id = min(g_indeg[n], 63);
    int od = min(g_outdeg[n], 63);
    acc += z_in[id * D + d] + z_out[od * D + d];
    g_h[n * D + d] = acc;
}

// ---------------- spatial bias -----------------------------------------------
__global__ void k_tab(const float* __restrict__ mu,
                      const float* __restrict__ sig,
                      const float* __restrict__ w,
                      const float* __restrict__ b0) {
    int i = blockIdx.x * blockDim.x + threadIdx.x;
    float d = (float)i * (DMAX / (float)(TABN - 1));
    float acc = b0[0];
#pragma unroll
    for (int k = 0; k < HS; k++) {
        float t = (d - mu[k]) / sig[k];
        acc = fmaf(w[k], expf(-0.5f * t * t), acc);
    }
    g_tab[i] = acc;
}

__global__ void k_spbias(const float* __restrict__ pos) {
    int j = blockIdx.x * blockDim.x + threadIdx.x;
    int i = blockIdx.y;
    float dx = pos[i * 3]     - pos[j * 3];
    float dy = pos[i * 3 + 1] - pos[j * 3 + 1];
    float dz = pos[i * 3 + 2] - pos[j * 3 + 2];
    float dist = sqrtf(dx * dx + dy * dy + dz * dz + 1e-12f);
    float xx = fminf(dist, DMAX) * ((float)(TABN - 1) / DMAX);
    int i0 = min((int)xx, TABN - 2);
    float fr = xx - (float)i0;
    float t0 = g_tab[i0], t1 = g_tab[i0 + 1];
    g_spbias[(size_t)i * N + j] = t0 + fr * (t1 - t0);
}

// ---------------- layernorm --------------------------------------------------
__global__ void k_ln(const float* __restrict__ in,
                     const float* __restrict__ g,
                     const float* __restrict__ b,
                     float* __restrict__ out) {
    int n = blockIdx.x, d = threadIdx.x;
    float v = in[n * D + d];
    float s = v;
#pragma unroll
    for (int o = 16; o; o >>= 1) s += __shfl_xor_sync(0xffffffffu, s, o);
    __shared__ float r1[4], r2[4];
    int w = d >> 5;
    if ((d & 31) == 0) r1[w] = s;
    __syncthreads();
    float mean = (r1[0] + r1[1] + r1[2] + r1[3]) * (1.0f / D);
    float t = v - mean;
    float s2 = t * t;
#pragma unroll
    for (int o = 16; o; o >>= 1) s2 += __shfl_xor_sync(0xffffffffu, s2, o);
    if ((d & 31) == 0) r2[w] = s2;
    __syncthreads();
    float var = (r2[0] + r2[1] + r2[2] + r2[3]) * (1.0f / D);
    out[n * D + d] = t * rsqrtf(var + 1e-5f) * g[d] + b[d];
}

// ---------------- tf32 tensor-core GEMM with fused epilogue ------------------
constexpr int AS_G = 20;
constexpr int BS_G = 72;

__global__ __launch_bounds__(256) void k_gemm_t(
    const float* __restrict__ A, const float* __restrict__ Bm,
    const float* __restrict__ bias, const float* __restrict__ res,
    float* __restrict__ C, int Kd, int Nc,
    long sB, long sBias, long sC, int gelu, int cvt) {
    int zb = blockIdx.z;
    Bm += (size_t)zb * sB;
    bias += (size_t)zb * sBias;
    C += (size_t)zb * sC;

    __shared__ float sA[64 * AS_G];
    __shared__ float sBt[16 * BS_G];

    const int tid = threadIdx.x;
    const int wid = tid >> 5;
    const int lane = tid & 31;
    const int g = lane >> 2, t = lane & 3;
    const int wr = wid & 3, wc = wid >> 2;
    const int m0 = wr * 16, n0 = wc * 32;
    const int row0 = blockIdx.y * 64, col0 = blockIdx.x * 64;

    float acc[4][4] = {};

    const int ar = tid >> 2, ak = (tid & 3) * 4;
    const int bk = tid >> 4, bc = (tid & 15) * 4;

    for (int k0 = 0; k0 < Kd; k0 += 16) {
        float4 a4 = *(const float4*)&A[(size_t)(row0 + ar) * Kd + k0 + ak];
        float* da = &sA[ar * AS_G + ak];
        da[0] = __uint_as_float(f2tf(a4.x));
        da[1] = __uint_as_float(f2tf(a4.y));
        da[2] = __uint_as_float(f2tf(a4.z));
        da[3] = __uint_as_float(f2tf(a4.w));
        float4 b4 = *(const float4*)&Bm[(size_t)(k0 + bk) * Nc + col0 + bc];
        float* db = &sBt[bk * BS_G + bc];
        db[0] = __uint_as_float(f2tf(b4.x));
        db[1] = __uint_as_float(f2tf(b4.y));
        db[2] = __uint_as_float(f2tf(b4.z));
        db[3] = __uint_as_float(f2tf(b4.w));
        __syncthreads();

#pragma unroll
        for (int kc = 0; kc < 16; kc += 8) {
            unsigned a0 = __float_as_uint(sA[(m0 + g) * AS_G + kc + t]);
            unsigned a1 = __float_as_uint(sA[(m0 + g + 8) * AS_G + kc + t]);
            unsigned a2 = __float_as_uint(sA[(m0 + g) * AS_G + kc + t + 4]);
            unsigned a3 = __float_as_uint(sA[(m0 + g + 8) * AS_G + kc + t + 4]);
            const float* b0p = &sBt[(kc + t) * BS_G + n0];
            const float* b1p = &sBt[(kc + t + 4) * BS_G + n0];
#pragma unroll
            for (int nt = 0; nt < 4; nt++) {
                unsigned b0 = __float_as_uint(b0p[nt * 8 + g]);
                unsigned b1 = __float_as_uint(b1p[nt * 8 + g]);
                mma8(acc[nt], a0, a1, a2, a3, b0, b1);
            }
        }
        __syncthreads();
    }

#pragma unroll
    for (int nt = 0; nt < 4; nt++) {
#pragma unroll
        for (int half = 0; half < 2; half++) {
            int r = row0 + m0 + g + half * 8;
            int c = col0 + n0 + nt * 8 + 2 * t;
            float v0 = acc[nt][half * 2 + 0] + bias[c];
            float v1 = acc[nt][half * 2 + 1] + bias[c + 1];
            if (gelu) {
                v0 = 0.5f * v0 * (1.0f + erff(v0 * 0.70710678118654752f));
                v1 = 0.5f * v1 * (1.0f + erff(v1 * 0.70710678118654752f));
            }
            if (res) {
                v0 += res[(size_t)r * Nc + c];
                v1 += res[(size_t)r * Nc + c + 1];
            }
            if (cvt) {
                v0 = __uint_as_float(f2tf(v0));
                v1 = __uint_as_float(f2tf(v1));
            }
            *(float2*)&C[(size_t)r * Nc + c] = make_float2(v0, v1);
        }
    }
}

// ---------------- tf32 flash attention, register-prefetched K/V --------------
// Same proven layout as the 919us kernel. Q/K/V are pre-rounded to tf32 by
// the producer GEMM (cvt=1) -> loads are raw copies. Next K/V tile is
// prefetched into registers with plain LDG while MMAs run (no cp.async).
constexpr int QS  = 132;
constexpr int KS  = 132;
constexpr int VS  = 136;
constexpr int PS  = 68;
constexpr int SM_Q  = 0;
constexpr int SM_K  = SM_Q + 128 * QS;      // 16896
constexpr int SM_V  = SM_K + 64 * KS;       // 25344
constexpr int SM_P  = SM_V + 64 * VS;       // 34048
constexpr int ATTN_FLOATS = SM_P + 128 * PS;
constexpr int ATTN_SMEM = ATTN_FLOATS * 4;  // 171008 bytes
constexpr int NT = N / 64;

__global__ __launch_bounds__(256, 1) void k_attn(
    const float* __restrict__ Qg, const float* __restrict__ Kg,
    const float* __restrict__ Vg, const float* __restrict__ Bg,
    float* __restrict__ Og) {
    extern __shared__ float sm[];
    float* sQ = sm + SM_Q;
    float* sK = sm + SM_K;
    float* sV = sm + SM_V;
    float* sP = sm + SM_P;

    const int hh = blockIdx.y;
    const int q0 = blockIdx.x * 128;
    const float* q  = Qg + (size_t)hh * N * D;
    const float* kp = Kg + (size_t)hh * N * D;
    const float* vp = Vg + (size_t)hh * N * D;

    const int tid  = threadIdx.x;
    const int wid  = tid >> 5;
    const int lane = tid & 31;
    const int g    = lane >> 2;
    const int t    = lane & 3;
    const int wm   = wid * 16;

    // ---- Q tile (already tf32): raw vector copy into smem ----
#pragma unroll
    for (int i = 0; i < 16; i++) {
        int idx = tid + 256 * i;
        int r = idx >> 5, c = (idx & 31) * 4;
        *(float4*)&sQ[r * QS + c] = *(const float4*)&q[(size_t)(q0 + r) * D + c];
    }

    // ---- prefetch kv tile 0 into registers ----
    const int pr = tid >> 5;          // 0..7  (row base, 8 rows per chunk)
    const int pc = (tid & 31) * 4;    // 0..124
    float4 kr[8], vr[8];
#pragma unroll
    for (int i = 0; i < 8; i++) {
        int r = pr + 8 * i;
        kr[i] = *(const float4*)&kp[(size_t)r * D + pc];
        vr[i] = *(const float4*)&vp[(size_t)r * D + pc];
    }

    float of[16][4];
#pragma unroll
    for (int dt = 0; dt < 16; dt++)
#pragma unroll
        for (int j = 0; j < 4; j++) of[dt][j] = 0.0f;
    float m0 = -1e30f, m1 = -1e30f, l0 = 0.0f, l1 = 0.0f;
    const float scale = 0.08838834764831845f;

    for (int iter = 0; iter < NT; iter++) {
        const int t0 = iter * 64;

        // ---- store prefetched tile to smem ----
#pragma unroll
        for (int i = 0; i < 8; i++) {
            int r = pr + 8 * i;
            *(float4*)&sK[r * KS + pc] = kr[i];
            *(float4*)&sV[r * VS + pc] = vr[i];
        }
        __syncthreads();

        // ---- issue next tile's loads (in flight during compute) ----
        if (iter + 1 < NT) {
            const float* kn = &kp[(size_t)(t0 + 64) * D];
            const float* vn = &vp[(size_t)(t0 + 64) * D];
#pragma unroll
            for (int i = 0; i < 8; i++) {
                int r = pr + 8 * i;
                kr[i] = *(const float4*)&kn[(size_t)r * D + pc];
                vr[i] = *(const float4*)&vn[(size_t)r * D + pc];
            }
        }

        // ---- bias tile prefetch ----
        const float* br0 = &Bg[(size_t)(q0 + wm + g) * N + t0];
        const float* br1 = br0 + 8 * N;
        float2 pb0[8], pb1[8];
#pragma unroll
        for (int nt = 0; nt < 8; nt++) {
            pb0[nt] = *(const float2*)&br0[nt * 8 + 2 * t];
            pb1[nt] = *(const float2*)&br1[nt * 8 + 2 * t];
        }

        // ---- S = Q @ K^T ----
        float sf[8][4];
#pragma unroll
        for (int nt = 0; nt < 8; nt++)
#pragma unroll
            for (int j = 0; j < 4; j++) sf[nt][j] = 0.0f;

        const float* qb = &sQ[(wm + g) * QS];
#pragma unroll
        for (int k0 = 0; k0 < 128; k0 += 8) {
            unsigned a0 = __float_as_uint(qb[k0 + t]);
            unsigned a1 = __float_as_uint(qb[8 * QS + k0 + t]);
            unsigned a2 = __float_as_uint(qb[k0 + t + 4]);
            unsigned a3 = __float_as_uint(qb[8 * QS + k0 + t + 4]);
#pragma unroll
            for (int nt = 0; nt < 8; nt++) {
                const float* kb = &sK[(nt * 8 + g) * KS + k0];
                unsigned b0 = __float_as_uint(kb[t]);
                unsigned b1 = __float_as_uint(kb[t + 4]);
                mma8(sf[nt], a0, a1, a2, a3, b0, b1);
            }
        }

        // ---- scale + bias + online softmax ----
        float mx0 = -1e30f, mx1 = -1e30f;
#pragma unroll
        for (int nt = 0; nt < 8; nt++) {
            sf[nt][0] = fmaf(sf[nt][0], scale, pb0[nt].x);
            sf[nt][1] = fmaf(sf[nt][1], scale, pb0[nt].y);
            sf[nt][2] = fmaf(sf[nt][2], scale, pb1[nt].x);
            sf[nt][3] = fmaf(sf[nt][3], scale, pb1[nt].y);
            mx0 = fmaxf(mx0, fmaxf(sf[nt][0], sf[nt][1]));
            mx1 = fmaxf(mx1, fmaxf(sf[nt][2], sf[nt][3]));
        }
        mx0 = fmaxf(mx0, __shfl_xor_sync(0xffffffffu, mx0, 1));
        mx0 = fmaxf(mx0, __shfl_xor_sync(0xffffffffu, mx0, 2));
        mx1 = fmaxf(mx1, __shfl_xor_sync(0xffffffffu, mx1, 1));
        mx1 = fmaxf(mx1, __shfl_xor_sync(0xffffffffu, mx1, 2));

        float mn0 = fmaxf(m0, mx0), mn1 = fmaxf(m1, mx1);
        float c0 = __expf(m0 - mn0), c1 = __expf(m1 - mn1);
        m0 = mn0; m1 = mn1;

        float rs0 = 0.0f, rs1 = 0.0f;
        float* pr0 = &sP[(wm + g) * PS];
        float* pr1 = pr0 + 8 * PS;
#pragma unroll
        for (int nt = 0; nt < 8; nt++) {
            float p0 = __uint_as_float(f2tf(__expf(sf[nt][0] - mn0)));
            float p1 = __uint_as_float(f2tf(__expf(sf[nt][1] - mn0)));
            float p2 = __uint_as_float(f2tf(__expf(sf[nt][2] - mn1)));
            float p3 = __uint_as_float(f2tf(__expf(sf[nt][3] - mn1)));
            rs0 += p0 + p1; rs1 += p2 + p3;
            *(float2*)&pr0[nt * 8 + 2 * t] = make_float2(p0, p1);
            *(float2*)&pr1[nt * 8 + 2 * t] = make_float2(p2, p3);
        }
        rs0 += __shfl_xor_sync(0xffffffffu, rs0, 1);
        rs0 += __shfl_xor_sync(0xffffffffu, rs0, 2);
        rs1 += __shfl_xor_sync(0xffffffffu, rs1, 1);
        rs1 += __shfl_xor_sync(0xffffffffu, rs1, 2);
        l0 = l0 * c0 + rs0;
        l1 = l1 * c1 + rs1;
#pragma unroll
        for (int dt = 0; dt < 16; dt++) {
            of[dt][0] *= c0; of[dt][1] *= c0;
            of[dt][2] *= c1; of[dt][3] *= c1;
        }
        __syncwarp();

        // ---- O += P @ V ----
        const float* pb = &sP[(wm + g) * PS];
#pragma unroll
        for (int j0 = 0; j0 < 64; j0 += 8) {
            unsigned a0 = __float_as_uint(pb[j0 + t]);
            unsigned a1 = __float_as_uint(pb[8 * PS + j0 + t]);
            unsigned a2 = __float_as_uint(pb[j0 + t + 4]);
            unsigned a3 = __float_as_uint(pb[8 * PS + j0 + t + 4]);
            const float* vb  = &sV[(j0 + t) * VS];
            const float* vb4 = &sV[(j0 + t + 4) * VS];
#pragma unroll
            for (int dt = 0; dt < 16; dt++) {
                unsigned b0 = __float_as_uint(vb[dt * 8 + g]);
                unsigned b1 = __float_as_uint(vb4[dt * 8 + g]);
                mma8(of[dt], a0, a1, a2, a3, b0, b1);
            }
        }
        __syncthreads();
    }

    float inv0 = 1.0f / l0, inv1 = 1.0f / l1;
    int row0 = q0 + wm + g, row1 = row0 + 8;
#pragma unroll
    for (int dt = 0; dt < 16; dt++) {
        int col = hh * D + dt * 8 + 2 * t;
        *(float2*)&Og[(size_t)row0 * (H * D) + col] =
            make_float2(of[dt][0] * inv0, of[dt][1] * inv0);
        *(float2*)&Og[(size_t)row1 * (H * D) + col] =
            make_float2(of[dt][2] * inv1, of[dt][3] * inv1);
    }
}

// ---------------- launch -----------------------------------------------------
extern "C" void kernel_launch(void* const* d_in, const int* in_sizes, int n_in,
                              void* d_out, int out_size) {
    const float* x         = (const float*)d_in[0];
    const int*   ei        = (const int*)d_in[1];
    const float* pos       = (const float*)d_in[3];
    const float* node_in_w = (const float*)d_in[4];
    const float* node_in_b = (const float*)d_in[5];
    const float* z_in      = (const float*)d_in[8];
    const float* z_out     = (const float*)d_in[9];
    const float* sp_mu     = (const float*)d_in[10];
    const float* sp_sigma  = (const float*)d_in[11];
    const float* sp_w      = (const float*)d_in[12];
    const float* sp_b      = (const float*)d_in[13];
    const float* Wq        = (const float*)d_in[14];
    const float* bq        = (const float*)d_in[15];
    const float* Wk        = (const float*)d_in[16];
    const float* bk        = (const float*)d_in[17];
    const float* Wv        = (const float*)d_in[18];
    const float* bv        = (const float*)d_in[19];
    const float* Wo        = (const float*)d_in[20];
    const float* bo        = (const float*)d_in[21];
    const float* ln1_g     = (const float*)d_in[22];
    const float* ln1_b     = (const float*)d_in[23];
    const float* ln2_g     = (const float*)d_in[24];
    const float* ln2_b     = (const float*)d_in[25];
    const float* ff1_w     = (const float*)d_in[26];
    const float* ff1_b     = (const float*)d_in[27];
    const float* ff2_w     = (const float*)d_in[28];
    const float* ff2_b     = (const float*)d_in[29];
    const float* out_w     = (const float*)d_in[30];
    const float* out_b     = (const float*)d_in[31];
    float* out = (float*)d_out;

    float *p_h, *p_xn, *p_bias, *p_q, *p_k, *p_v, *p_ao, *p_ff;
    cudaGetSymbolAddress((void**)&p_h, g_h);
    cudaGetSymbolAddress((void**)&p_xn, g_xn);
    cudaGetSymbolAddress((void**)&p_bias, g_spbias);
    cudaGetSymbolAddress((void**)&p_q, g_q);
    cudaGetSymbolAddress((void**)&p_k, g_k);
    cudaGetSymbolAddress((void**)&p_v, g_v);
    cudaGetSymbolAddress((void**)&p_ao, g_ao);
    cudaGetSymbolAddress((void**)&p_ff, g_ff);

    cudaFuncSetAttribute(k_attn, cudaFuncAttributeMaxDynamicSharedMemorySize,
                         ATTN_SMEM);

    k_zero_deg<<<(N + 255) / 256, 256>>>();
    k_deg<<<(E + 255) / 256, 256>>>(ei);
    k_tab<<<TABN / 256, 256>>>(sp_mu, sp_sigma, sp_w, sp_b);
    k_spbias<<<dim3(N / 256, N), 256>>>(pos);
    k_embed<<<N, D>>>(x, node_in_w, node_in_b, z_in, z_out);

    for (int l = 0; l < NL; l++) {
        k_ln<<<N, 128>>>(p_h, ln1_g + l * D, ln1_b + l * D, p_xn);
        k_gemm_t<<<dim3(D / 64, N / 64, H), 256>>>(
            p_xn, Wq + (size_t)l * H * D * D, bq + (size_t)l * H * D, nullptr,
            p_q, D, D, (long)D * D, (long)D, (long)N * D, 0, 1);
        k_gemm_t<<<dim3(D / 64, N / 64, H), 256>>>(
            p_xn, Wk + (size_t)l * H * D * D, bk + (size_t)l * H * D, nullptr,
            p_k, D, D, (long)D * D, (long)D, (long)N * D, 0, 1);
        k_gemm_t<<<dim3(D / 64, N / 64, H), 256>>>(
            p_xn, Wv + (size_t)l * H * D * D, bv + (size_t)l * H * D, nullptr,
            p_v, D, D, (long)D * D, (long)D, (long)N * D, 0, 1);

        k_attn<<<dim3(N / 128, H), 256, ATTN_SMEM>>>(p_q, p_k, p_v, p_bias,
                                                     p_ao);

        k_gemm_t<<<dim3(D / 64, N / 64, 1), 256>>>(
            p_ao, Wo + (size_t)l * H * D * D, bo + (size_t)l * D, p_h,
            p_h, H * D, D, 0, 0, 0, 0, 0);

        k_ln<<<N, 128>>>(p_h, ln2_g + l * D, ln2_b + l * D, p_xn);
        k_gemm_t<<<dim3(FFD / 64, N / 64, 1), 256>>>(
            p_xn, ff1_w + (size_t)l * D * FFD, ff1_b + (size_t)l * FFD,
            nullptr, p_ff, D, FFD, 0, 0, 0, 1, 0);
        k_gemm_t<<<dim3(D / 64, N / 64, 1), 256>>>(
            p_ff, ff2_w + (size_t)l * FFD * D, ff2_b + (size_t)l * D, p_h,
            p_h, FFD, D, 0, 0, 0, 0, 0);
    }

    k_gemm_t<<<dim3(OUTD / 64, N / 64, 1), 256>>>(
        p_h, out_w, out_b, nullptr, out, D, OUTD, 0, 0, 0, 0, 0);
}

// round 9
// speedup vs baseline: 3.0816x; 1.0695x over previous
#include <cuda_runtime.h>
#include <math.h>
#include <stdint.h>

namespace cfg {
constexpr int N    = 2048;
constexpr int D    = 128;
constexpr int H    = 8;
constexpr int FFD  = 512;
constexpr int NL   = 3;
constexpr int E    = 65536;
constexpr int HS   = 8;
constexpr int OUTD = 64;
}
using namespace cfg;

// ---------------- scratch ---------------------------------------------------
__device__ float g_h[N * D];
__device__ float g_xn[N * D];
__device__ float g_spbias[(size_t)N * N];
__device__ float g_q[H * N * D];
__device__ float g_k[H * N * D];
__device__ float g_v[H * N * D];
__device__ float g_ao[N * H * D];
__device__ float g_ff[N * FFD];
__device__ int   g_indeg[N];
__device__ int   g_outdeg[N];

constexpr int TABN = 16384;
constexpr float DMAX = 16.0f;
__device__ float g_tab[TABN];

// ---------------- helpers ----------------------------------------------------
__device__ __forceinline__ unsigned f2tf(float v) {
    unsigned r;
    asm("cvt.rna.tf32.f32 %0, %1;" : "=r"(r) : "f"(v));
    return r;
}

__device__ __forceinline__ float4 tf4(float4 v) {
    v.x = __uint_as_float(f2tf(v.x));
    v.y = __uint_as_float(f2tf(v.y));
    v.z = __uint_as_float(f2tf(v.z));
    v.w = __uint_as_float(f2tf(v.w));
    return v;
}

__device__ __forceinline__ void mma8(float* d, unsigned a0, unsigned a1,
                                     unsigned a2, unsigned a3,
                                     unsigned b0, unsigned b1) {
    asm volatile(
        "mma.sync.aligned.m16n8k8.row.col.f32.tf32.tf32.f32 "
        "{%0,%1,%2,%3}, {%4,%5,%6,%7}, {%8,%9}, {%0,%1,%2,%3};"
        : "+f"(d[0]), "+f"(d[1]), "+f"(d[2]), "+f"(d[3])
        : "r"(a0), "r"(a1), "r"(a2), "r"(a3), "r"(b0), "r"(b1));
}

// ---------------- degrees ----------------------------------------------------
__global__ void k_zero_deg() {
    int i = blockIdx.x * blockDim.x + threadIdx.x;
    if (i < N) { g_indeg[i] = 0; g_outdeg[i] = 0; }
}

__global__ void k_deg(const int* __restrict__ ei) {
    int e = blockIdx.x * blockDim.x + threadIdx.x;
    if (e < E) {
        atomicAdd(&g_outdeg[ei[e]], 1);
        atomicAdd(&g_indeg[ei[E + e]], 1);
    }
}

// ---------------- node embedding ---------------------------------------------
__global__ void k_embed(const float* __restrict__ x,
                        const float* __restrict__ W,
                        const float* __restrict__ b,
                        const float* __restrict__ z_in,
                        const float* __restrict__ z_out) {
    int n = blockIdx.x;
    int d = threadIdx.x;
    __shared__ float xs[16];
    if (d < 16) xs[d] = x[n * 16 + d];
    __syncthreads();
    float acc = b[d];
#pragma unroll
    for (int k = 0; k < 16; k++) acc = fmaf(xs[k], W[k * D + d], acc);
    int id = min(g_indeg[n], 63);
    int od = min(g_outdeg[n], 63);
    acc += z_in[id * D + d] + z_out[od * D + d];
    g_h[n * D + d] = acc;
}

// ---------------- spatial bias -----------------------------------------------
__global__ void k_tab(const float* __restrict__ mu,
                      const float* __restrict__ sig,
                      const float* __restrict__ w,
                      const float* __restrict__ b0) {
    int i = blockIdx.x * blockDim.x + threadIdx.x;
    float d = (float)i * (DMAX / (float)(TABN - 1));
    float acc = b0[0];
#pragma unroll
    for (int k = 0; k < HS; k++) {
        float t = (d - mu[k]) / sig[k];
        acc = fmaf(w[k], expf(-0.5f * t * t), acc);
    }
    g_tab[i] = acc;
}

__global__ void k_spbias(const float* __restrict__ pos) {
    int j = blockIdx.x * blockDim.x + threadIdx.x;
    int i = blockIdx.y;
    float dx = pos[i * 3]     - pos[j * 3];
    float dy = pos[i * 3 + 1] - pos[j * 3 + 1];
    float dz = pos[i * 3 + 2] - pos[j * 3 + 2];
    float dist = sqrtf(dx * dx + dy * dy + dz * dz + 1e-12f);
    float xx = fminf(dist, DMAX) * ((float)(TABN - 1) / DMAX);
    int i0 = min((int)xx, TABN - 2);
    float fr = xx - (float)i0;
    float t0 = g_tab[i0], t1 = g_tab[i0 + 1];
    g_spbias[(size_t)i * N + j] = t0 + fr * (t1 - t0);
}

// ---------------- layernorm --------------------------------------------------
__global__ void k_ln(const float* __restrict__ in,
                     const float* __restrict__ g,
                     const float* __restrict__ b,
                     float* __restrict__ out) {
    int n = blockIdx.x, d = threadIdx.x;
    float v = in[n * D + d];
    float s = v;
#pragma unroll
    for (int o = 16; o; o >>= 1) s += __shfl_xor_sync(0xffffffffu, s, o);
    __shared__ float r1[4], r2[4];
    int w = d >> 5;
    if ((d & 31) == 0) r1[w] = s;
    __syncthreads();
    float mean = (r1[0] + r1[1] + r1[2] + r1[3]) * (1.0f / D);
    float t = v - mean;
    float s2 = t * t;
#pragma unroll
    for (int o = 16; o; o >>= 1) s2 += __shfl_xor_sync(0xffffffffu, s2, o);
    if ((d & 31) == 0) r2[w] = s2;
    __syncthreads();
    float var = (r2[0] + r2[1] + r2[2] + r2[3]) * (1.0f / D);
    out[n * D + d] = t * rsqrtf(var + 1e-5f) * g[d] + b[d];
}

// ---------------- tf32 GEMM, BK=32, register-prefetched ----------------------
// C = act(A[M,Kd] @ B[Kd,Nc] + bias) (+ res). BM=BN=64, BK=32. Kd % 32 == 0.
// sA stride 36 (a-frag g*36+kc+t bank-clean), sB stride 72.
constexpr int AS_G = 36;
constexpr int BS_G = 72;

__global__ __launch_bounds__(256) void k_gemm_t(
    const float* __restrict__ A, const float* __restrict__ Bm,
    const float* __restrict__ bias, const float* __restrict__ res,
    float* __restrict__ C, int Kd, int Nc,
    long sB, long sBias, long sC, int gelu, int cvt) {
    int zb = blockIdx.z;
    Bm += (size_t)zb * sB;
    bias += (size_t)zb * sBias;
    C += (size_t)zb * sC;

    __shared__ float sA[64 * AS_G];     // 64 rows x 32 k
    __shared__ float sBt[32 * BS_G];    // 32 k x 64 cols

    const int tid = threadIdx.x;
    const int wid = tid >> 5;
    const int lane = tid & 31;
    const int g = lane >> 2, t = lane & 3;
    const int wr = wid & 3, wc = wid >> 2;
    const int m0 = wr * 16, n0 = wc * 32;
    const int row0 = blockIdx.y * 64, col0 = blockIdx.x * 64;

    float acc[4][4] = {};

    // load mapping: A row = tid>>2, cols (tid&3)*8 .. +7 (two float4)
    //               B row = tid>>3, cols (tid&7)*8 .. +7
    const int arw = tid >> 2, acl = (tid & 3) * 8;
    const int brw = tid >> 3, bcl = (tid & 7) * 8;

    const float* aptr = &A[(size_t)(row0 + arw) * Kd + acl];
    const float* bptr = &Bm[(size_t)brw * Nc + col0 + bcl];

    float4 pa0 = tf4(*(const float4*)(aptr));
    float4 pa1 = tf4(*(const float4*)(aptr + 4));
    float4 pb0 = tf4(*(const float4*)(bptr));
    float4 pb1 = tf4(*(const float4*)(bptr + 4));

    for (int k0 = 0; k0 < Kd; k0 += 32) {
        *(float4*)&sA[arw * AS_G + acl]      = pa0;
        *(float4*)&sA[arw * AS_G + acl + 4]  = pa1;
        *(float4*)&sBt[brw * BS_G + bcl]     = pb0;
        *(float4*)&sBt[brw * BS_G + bcl + 4] = pb1;
        __syncthreads();

        if (k0 + 32 < Kd) {
            const float* an = aptr + k0 + 32;
            const float* bn = &Bm[(size_t)(k0 + 32 + brw) * Nc + col0 + bcl];
            pa0 = tf4(*(const float4*)(an));
            pa1 = tf4(*(const float4*)(an + 4));
            pb0 = tf4(*(const float4*)(bn));
            pb1 = tf4(*(const float4*)(bn + 4));
        }

#pragma unroll
        for (int kc = 0; kc < 32; kc += 8) {
            unsigned a0 = __float_as_uint(sA[(m0 + g) * AS_G + kc + t]);
            unsigned a1 = __float_as_uint(sA[(m0 + g + 8) * AS_G + kc + t]);
            unsigned a2 = __float_as_uint(sA[(m0 + g) * AS_G + kc + t + 4]);
            unsigned a3 = __float_as_uint(sA[(m0 + g + 8) * AS_G + kc + t + 4]);
            const float* b0p = &sBt[(kc + t) * BS_G + n0];
            const float* b1p = &sBt[(kc + t + 4) * BS_G + n0];
#pragma unroll
            for (int nt = 0; nt < 4; nt++) {
                unsigned b0 = __float_as_uint(b0p[nt * 8 + g]);
                unsigned b1 = __float_as_uint(b1p[nt * 8 + g]);
                mma8(acc[nt], a0, a1, a2, a3, b0, b1);
            }
        }
        __syncthreads();
    }

#pragma unroll
    for (int nt = 0; nt < 4; nt++) {
#pragma unroll
        for (int half = 0; half < 2; half++) {
            int r = row0 + m0 + g + half * 8;
            int c = col0 + n0 + nt * 8 + 2 * t;
            float v0 = acc[nt][half * 2 + 0] + bias[c];
            float v1 = acc[nt][half * 2 + 1] + bias[c + 1];
            if (gelu) {
                v0 = 0.5f * v0 * (1.0f + erff(v0 * 0.70710678118654752f));
                v1 = 0.5f * v1 * (1.0f + erff(v1 * 0.70710678118654752f));
            }
            if (res) {
                v0 += res[(size_t)r * Nc + c];
                v1 += res[(size_t)r * Nc + c + 1];
            }
            if (cvt) {
                v0 = __uint_as_float(f2tf(v0));
                v1 = __uint_as_float(f2tf(v1));
            }
            *(float2*)&C[(size_t)r * Nc + c] = make_float2(v0, v1);
        }
    }
}

// ---------------- tf32 flash attention, register-prefetched K/V --------------
constexpr int QS  = 132;
constexpr int KS  = 132;
constexpr int VS  = 136;
constexpr int PS  = 68;
constexpr int SM_Q  = 0;
constexpr int SM_K  = SM_Q + 128 * QS;
constexpr int SM_V  = SM_K + 64 * KS;
constexpr int SM_P  = SM_V + 64 * VS;
constexpr int ATTN_FLOATS = SM_P + 128 * PS;
constexpr int ATTN_SMEM = ATTN_FLOATS * 4;  // 171008 bytes
constexpr int NT = N / 64;

__global__ __launch_bounds__(256, 1) void k_attn(
    const float* __restrict__ Qg, const float* __restrict__ Kg,
    const float* __restrict__ Vg, const float* __restrict__ Bg,
    float* __restrict__ Og) {
    extern __shared__ float sm[];
    float* sQ = sm + SM_Q;
    float* sK = sm + SM_K;
    float* sV = sm + SM_V;
    float* sP = sm + SM_P;

    const int hh = blockIdx.y;
    const int q0 = blockIdx.x * 128;
    const float* q  = Qg + (size_t)hh * N * D;
    const float* kp = Kg + (size_t)hh * N * D;
    const float* vp = Vg + (size_t)hh * N * D;

    const int tid  = threadIdx.x;
    const int wid  = tid >> 5;
    const int lane = tid & 31;
    const int g    = lane >> 2;
    const int t    = lane & 3;
    const int wm   = wid * 16;

#pragma unroll
    for (int i = 0; i < 16; i++) {
        int idx = tid + 256 * i;
        int r = idx >> 5, c = (idx & 31) * 4;
        *(float4*)&sQ[r * QS + c] = *(const float4*)&q[(size_t)(q0 + r) * D + c];
    }

    const int pr = tid >> 5;
    const int pc = (tid & 31) * 4;
    float4 kr[8], vr[8];
#pragma unroll
    for (int i = 0; i < 8; i++) {
        int r = pr + 8 * i;
        kr[i] = *(const float4*)&kp[(size_t)r * D + pc];
        vr[i] = *(const float4*)&vp[(size_t)r * D + pc];
    }

    float of[16][4];
#pragma unroll
    for (int dt = 0; dt < 16; dt++)
#pragma unroll
        for (int j = 0; j < 4; j++) of[dt][j] = 0.0f;
    float m0 = -1e30f, m1 = -1e30f, l0 = 0.0f, l1 = 0.0f;
    const float scale = 0.08838834764831845f;

    for (int iter = 0; iter < NT; iter++) {
        const int t0 = iter * 64;

#pragma unroll
        for (int i = 0; i < 8; i++) {
            int r = pr + 8 * i;
            *(float4*)&sK[r * KS + pc] = kr[i];
            *(float4*)&sV[r * VS + pc] = vr[i];
        }
        __syncthreads();

        if (iter + 1 < NT) {
            const float* kn = &kp[(size_t)(t0 + 64) * D];
            const float* vn = &vp[(size_t)(t0 + 64) * D];
#pragma unroll
            for (int i = 0; i < 8; i++) {
                int r = pr + 8 * i;
                kr[i] = *(const float4*)&kn[(size_t)r * D + pc];
                vr[i] = *(const float4*)&vn[(size_t)r * D + pc];
            }
        }

        const float* br0 = &Bg[(size_t)(q0 + wm + g) * N + t0];
        const float* br1 = br0 + 8 * N;
        float2 pb0[8], pb1[8];
#pragma unroll
        for (int nt = 0; nt < 8; nt++) {
            pb0[nt] = *(const float2*)&br0[nt * 8 + 2 * t];
            pb1[nt] = *(const float2*)&br1[nt * 8 + 2 * t];
        }

        float sf[8][4];
#pragma unroll
        for (int nt = 0; nt < 8; nt++)
#pragma unroll
            for (int j = 0; j < 4; j++) sf[nt][j] = 0.0f;

        const float* qb = &sQ[(wm + g) * QS];
#pragma unroll
        for (int k0 = 0; k0 < 128; k0 += 8) {
            unsigned a0 = __float_as_uint(qb[k0 + t]);
            unsigned a1 = __float_as_uint(qb[8 * QS + k0 + t]);
            unsigned a2 = __float_as_uint(qb[k0 + t + 4]);
            unsigned a3 = __float_as_uint(qb[8 * QS + k0 + t + 4]);
#pragma unroll
            for (int nt = 0; nt < 8; nt++) {
                const float* kb = &sK[(nt * 8 + g) * KS + k0];
                unsigned b0 = __float_as_uint(kb[t]);
                unsigned b1 = __float_as_uint(kb[t + 4]);
                mma8(sf[nt], a0, a1, a2, a3, b0, b1);
            }
        }

        float mx0 = -1e30f, mx1 = -1e30f;
#pragma unroll
        for (int nt = 0; nt < 8; nt++) {
            sf[nt][0] = fmaf(sf[nt][0], scale, pb0[nt].x);
            sf[nt][1] = fmaf(sf[nt][1], scale, pb0[nt].y);
            sf[nt][2] = fmaf(sf[nt][2], scale, pb1[nt].x);
            sf[nt][3] = fmaf(sf[nt][3], scale, pb1[nt].y);
            mx0 = fmaxf(mx0, fmaxf(sf[nt][0], sf[nt][1]));
            mx1 = fmaxf(mx1, fmaxf(sf[nt][2], sf[nt][3]));
        }
        mx0 = fmaxf(mx0, __shfl_xor_sync(0xffffffffu, mx0, 1));
        mx0 = fmaxf(mx0, __shfl_xor_sync(0xffffffffu, mx0, 2));
        mx1 = fmaxf(mx1, __shfl_xor_sync(0xffffffffu, mx1, 1));
        mx1 = fmaxf(mx1, __shfl_xor_sync(0xffffffffu, mx1, 2));

        float mn0 = fmaxf(m0, mx0), mn1 = fmaxf(m1, mx1);
        float c0 = __expf(m0 - mn0), c1 = __expf(m1 - mn1);
        m0 = mn0; m1 = mn1;

        float rs0 = 0.0f, rs1 = 0.0f;
        float* pr0 = &sP[(wm + g) * PS];
        float* pr1 = pr0 + 8 * PS;
#pragma unroll
        for (int nt = 0; nt < 8; nt++) {
            float p0 = __uint_as_float(f2tf(__expf(sf[nt][0] - mn0)));
            float p1 = __uint_as_float(f2tf(__expf(sf[nt][1] - mn0)));
            float p2 = __uint_as_float(f2tf(__expf(sf[nt][2] - mn1)));
            float p3 = __uint_as_float(f2tf(__expf(sf[nt][3] - mn1)));
            rs0 += p0 + p1; rs1 += p2 + p3;
            *(float2*)&pr0[nt * 8 + 2 * t] = make_float2(p0, p1);
            *(float2*)&pr1[nt * 8 + 2 * t] = make_float2(p2, p3);
        }
        rs0 += __shfl_xor_sync(0xffffffffu, rs0, 1);
        rs0 += __shfl_xor_sync(0xffffffffu, rs0, 2);
        rs1 += __shfl_xor_sync(0xffffffffu, rs1, 1);
        rs1 += __shfl_xor_sync(0xffffffffu, rs1, 2);
        l0 = l0 * c0 + rs0;
        l1 = l1 * c1 + rs1;
#pragma unroll
        for (int dt = 0; dt < 16; dt++) {
            of[dt][0] *= c0; of[dt][1] *= c0;
            of[dt][2] *= c1; of[dt][3] *= c1;
        }
        __syncwarp();

        const float* pb = &sP[(wm + g) * PS];
#pragma unroll
        for (int j0 = 0; j0 < 64; j0 += 8) {
            unsigned a0 = __float_as_uint(pb[j0 + t]);
            unsigned a1 = __float_as_uint(pb[8 * PS + j0 + t]);
            unsigned a2 = __float_as_uint(pb[j0 + t + 4]);
            unsigned a3 = __float_as_uint(pb[8 * PS + j0 + t + 4]);
            const float* vb  = &sV[(j0 + t) * VS];
            const float* vb4 = &sV[(j0 + t + 4) * VS];
#pragma unroll
            for (int dt = 0; dt < 16; dt++) {
                unsigned b0 = __float_as_uint(vb[dt * 8 + g]);
                unsigned b1 = __float_as_uint(vb4[dt * 8 + g]);
                mma8(of[dt], a0, a1, a2, a3, b0, b1);
            }
        }
        __syncthreads();
    }

    float inv0 = 1.0f / l0, inv1 = 1.0f / l1;
    int row0 = q0 + wm + g, row1 = row0 + 8;
#pragma unroll
    for (int dt = 0; dt < 16; dt++) {
        int col = hh * D + dt * 8 + 2 * t;
        *(float2*)&Og[(size_t)row0 * (H * D) + col] =
            make_float2(of[dt][0] * inv0, of[dt][1] * inv0);
        *(float2*)&Og[(size_t)row1 * (H * D) + col] =
            make_float2(of[dt][2] * inv1, of[dt][3] * inv1);
    }
}

// ---------------- launch -----------------------------------------------------
extern "C" void kernel_launch(void* const* d_in, const int* in_sizes, int n_in,
                              void* d_out, int out_size) {
    const float* x         = (const float*)d_in[0];
    const int*   ei        = (const int*)d_in[1];
    const float* pos       = (const float*)d_in[3];
    const float* node_in_w = (const float*)d_in[4];
    const float* node_in_b = (const float*)d_in[5];
    const float* z_in      = (const float*)d_in[8];
    const float* z_out     = (const float*)d_in[9];
    const float* sp_mu     = (const float*)d_in[10];
    const float* sp_sigma  = (const float*)d_in[11];
    const float* sp_w      = (const float*)d_in[12];
    const float* sp_b      = (const float*)d_in[13];
    const float* Wq        = (const float*)d_in[14];
    const float* bq        = (const float*)d_in[15];
    const float* Wk        = (const float*)d_in[16];
    const float* bk        = (const float*)d_in[17];
    const float* Wv        = (const float*)d_in[18];
    const float* bv        = (const float*)d_in[19];
    const float* Wo        = (const float*)d_in[20];
    const float* bo        = (const float*)d_in[21];
    const float* ln1_g     = (const float*)d_in[22];
    const float* ln1_b     = (const float*)d_in[23];
    const float* ln2_g     = (const float*)d_in[24];
    const float* ln2_b     = (const float*)d_in[25];
    const float* ff1_w     = (const float*)d_in[26];
    const float* ff1_b     = (const float*)d_in[27];
    const float* ff2_w     = (const float*)d_in[28];
    const float* ff2_b     = (const float*)d_in[29];
    const float* out_w     = (const float*)d_in[30];
    const float* out_b     = (const float*)d_in[31];
    float* out = (float*)d_out;

    float *p_h, *p_xn, *p_bias, *p_q, *p_k, *p_v, *p_ao, *p_ff;
    cudaGetSymbolAddress((void**)&p_h, g_h);
    cudaGetSymbolAddress((void**)&p_xn, g_xn);
    cudaGetSymbolAddress((void**)&p_bias, g_spbias);
    cudaGetSymbolAddress((void**)&p_q, g_q);
    cudaGetSymbolAddress((void**)&p_k, g_k);
    cudaGetSymbolAddress((void**)&p_v, g_v);
    cudaGetSymbolAddress((void**)&p_ao, g_ao);
    cudaGetSymbolAddress((void**)&p_ff, g_ff);

    cudaFuncSetAttribute(k_attn, cudaFuncAttributeMaxDynamicSharedMemorySize,
                         ATTN_SMEM);

    k_zero_deg<<<(N + 255) / 256, 256>>>();
    k_deg<<<(E + 255) / 256, 256>>>(ei);
    k_tab<<<TABN / 256, 256>>>(sp_mu, sp_sigma, sp_w, sp_b);
    k_spbias<<<dim3(N / 256, N), 256>>>(pos);
    k_embed<<<N, D>>>(x, node_in_w, node_in_b, z_in, z_out);

    for (int l = 0; l < NL; l++) {
        k_ln<<<N, 128>>>(p_h, ln1_g + l * D, ln1_b + l * D, p_xn);
        k_gemm_t<<<dim3(D / 64, N / 64, H), 256>>>(
            p_xn, Wq + (size_t)l * H * D * D, bq + (size_t)l * H * D, nullptr,
            p_q, D, D, (long)D * D, (long)D, (long)N * D, 0, 1);
        k_gemm_t<<<dim3(D / 64, N / 64, H), 256>>>(
            p_xn, Wk + (size_t)l * H * D * D, bk + (size_t)l * H * D, nullptr,
            p_k, D, D, (long)D * D, (long)D, (long)N * D, 0, 1);
        k_gemm_t<<<dim3(D / 64, N / 64, H), 256>>>(
            p_xn, Wv + (size_t)l * H * D * D, bv + (size_t)l * H * D, nullptr,
            p_v, D, D, (long)D * D, (long)D, (long)N * D, 0, 1);

        k_attn<<<dim3(N / 128, H), 256, ATTN_SMEM>>>(p_q, p_k, p_v, p_bias,
                                                     p_ao);

        k_gemm_t<<<dim3(D / 64, N / 64, 1), 256>>>(
            p_ao, Wo + (size_t)l * H * D * D, bo + (size_t)l * D, p_h,
            p_h, H * D, D, 0, 0, 0, 0, 0);

        k_ln<<<N, 128>>>(p_h, ln2_g + l * D, ln2_b + l * D, p_xn);
        k_gemm_t<<<dim3(FFD / 64, N / 64, 1), 256>>>(
            p_xn, ff1_w + (size_t)l * D * FFD, ff1_b + (size_t)l * FFD,
            nullptr, p_ff, D, FFD, 0, 0, 0, 1, 0);
        k_gemm_t<<<dim3(D / 64, N / 64, 1), 256>>>(
            p_ff, ff2_w + (size_t)l * FFD * D, ff2_b + (size_t)l * D, p_h,
            p_h, FFD, D, 0, 0, 0, 0, 0);
    }

    k_gemm_t<<<dim3(OUTD / 64, N / 64, 1), 256>>>(
        p_h, out_w, out_b, nullptr, out, D, OUTD, 0, 0, 0, 0, 0);
}

// round 10
// speedup vs baseline: 3.1357x; 1.0176x over previous
#include <cuda_runtime.h>
#include <math.h>
#include <stdint.h>

namespace cfg {
constexpr int N    = 2048;
constexpr int D    = 128;
constexpr int H    = 8;
constexpr int FFD  = 512;
constexpr int NL   = 3;
constexpr int E    = 65536;
constexpr int HS   = 8;
constexpr int OUTD = 64;
}
using namespace cfg;

// ---------------- scratch ---------------------------------------------------
__device__ float g_h[N * D];
__device__ float g_xn[N * D];
__device__ float g_spbias[(size_t)N * N];
__device__ float g_q[H * N * D];
__device__ float g_k[H * N * D];
__device__ float g_v[H * N * D];
__device__ float g_ao[N * H * D];
__device__ float g_ff[N * FFD];
__device__ int   g_indeg[N];
__device__ int   g_outdeg[N];

constexpr int TABN = 16384;
constexpr float DMAX = 16.0f;
__device__ float g_tab[TABN];

// ---------------- helpers ----------------------------------------------------
__device__ __forceinline__ unsigned f2tf(float v) {
    unsigned r;
    asm("cvt.rna.tf32.f32 %0, %1;" : "=r"(r) : "f"(v));
    return r;
}

__device__ __forceinline__ float4 tf4(float4 v) {
    v.x = __uint_as_float(f2tf(v.x));
    v.y = __uint_as_float(f2tf(v.y));
    v.z = __uint_as_float(f2tf(v.z));
    v.w = __uint_as_float(f2tf(v.w));
    return v;
}

__device__ __forceinline__ void mma8(float* d, unsigned a0, unsigned a1,
                                     unsigned a2, unsigned a3,
                                     unsigned b0, unsigned b1) {
    asm volatile(
        "mma.sync.aligned.m16n8k8.row.col.f32.tf32.tf32.f32 "
        "{%0,%1,%2,%3}, {%4,%5,%6,%7}, {%8,%9}, {%0,%1,%2,%3};"
        : "+f"(d[0]), "+f"(d[1]), "+f"(d[2]), "+f"(d[3])
        : "r"(a0), "r"(a1), "r"(a2), "r"(a3), "r"(b0), "r"(b1));
}

// ---------------- degrees ----------------------------------------------------
__global__ void k_zero_deg() {
    int i = blockIdx.x * blockDim.x + threadIdx.x;
    if (i < N) { g_indeg[i] = 0; g_outdeg[i] = 0; }
}

__global__ void k_deg(const int* __restrict__ ei) {
    int e = blockIdx.x * blockDim.x + threadIdx.x;
    if (e < E) {
        atomicAdd(&g_outdeg[ei[e]], 1);
        atomicAdd(&g_indeg[ei[E + e]], 1);
    }
}

// ---------------- node embedding ---------------------------------------------
__global__ void k_embed(const float* __restrict__ x,
                        const float* __restrict__ W,
                        const float* __restrict__ b,
                        const float* __restrict__ z_in,
                        const float* __restrict__ z_out) {
    int n = blockIdx.x;
    int d = threadIdx.x;
    __shared__ float xs[16];
    if (d < 16) xs[d] = x[n * 16 + d];
    __syncthreads();
    float acc = b[d];
#pragma unroll
    for (int k = 0; k < 16; k++) acc = fmaf(xs[k], W[k * D + d], acc);
    int id = min(g_indeg[n], 63);
    int od = min(g_outdeg[n], 63);
    acc += z_in[id * D + d] + z_out[od * D + d];
    g_h[n * D + d] = acc;
}

// ---------------- spatial bias -----------------------------------------------
__global__ void k_tab(const float* __restrict__ mu,
                      const float* __restrict__ sig,
                      const float* __restrict__ w,
                      const float* __restrict__ b0) {
    int i = blockIdx.x * blockDim.x + threadIdx.x;
    float d = (float)i * (DMAX / (float)(TABN - 1));
    float acc = b0[0];
#pragma unroll
    for (int k = 0; k < HS; k++) {
        float t = (d - mu[k]) / sig[k];
        acc = fmaf(w[k], expf(-0.5f * t * t), acc);
    }
    g_tab[i] = acc;
}

__global__ void k_spbias(const float* __restrict__ pos) {
    int j = blockIdx.x * blockDim.x + threadIdx.x;
    int i = blockIdx.y;
    float dx = pos[i * 3]     - pos[j * 3];
    float dy = pos[i * 3 + 1] - pos[j * 3 + 1];
    float dz = pos[i * 3 + 2] - pos[j * 3 + 2];
    float dist = sqrtf(dx * dx + dy * dy + dz * dz + 1e-12f);
    float xx = fminf(dist, DMAX) * ((float)(TABN - 1) / DMAX);
    int i0 = min((int)xx, TABN - 2);
    float fr = xx - (float)i0;
    float t0 = g_tab[i0], t1 = g_tab[i0 + 1];
    g_spbias[(size_t)i * N + j] = t0 + fr * (t1 - t0);
}

// ---------------- layernorm --------------------------------------------------
__global__ void k_ln(const float* __restrict__ in,
                     const float* __restrict__ g,
                     const float* __restrict__ b,
                     float* __restrict__ out) {
    int n = blockIdx.x, d = threadIdx.x;
    float v = in[n * D + d];
    float s = v;
#pragma unroll
    for (int o = 16; o; o >>= 1) s += __shfl_xor_sync(0xffffffffu, s, o);
    __shared__ float r1[4], r2[4];
    int w = d >> 5;
    if ((d & 31) == 0) r1[w] = s;
    __syncthreads();
    float mean = (r1[0] + r1[1] + r1[2] + r1[3]) * (1.0f / D);
    float t = v - mean;
    float s2 = t * t;
#pragma unroll
    for (int o = 16; o; o >>= 1) s2 += __shfl_xor_sync(0xffffffffu, s2, o);
    if ((d & 31) == 0) r2[w] = s2;
    __syncthreads();
    float var = (r2[0] + r2[1] + r2[2] + r2[3]) * (1.0f / D);
    out[n * D + d] = t * rsqrtf(var + 1e-5f) * g[d] + b[d];
}

// ---------------- tf32 GEMM BM=64, BK=32, register-prefetched ----------------
constexpr int AS_G = 36;
constexpr int BS_G = 72;

__global__ __launch_bounds__(256) void k_gemm_t(
    const float* __restrict__ A, const float* __restrict__ Bm,
    const float* __restrict__ bias, const float* __restrict__ res,
    float* __restrict__ C, int Kd, int Nc,
    long sB, long sBias, long sC, int gelu, int cvt) {
    int zb = blockIdx.z;
    Bm += (size_t)zb * sB;
    bias += (size_t)zb * sBias;
    C += (size_t)zb * sC;

    __shared__ float sA[64 * AS_G];
    __shared__ float sBt[32 * BS_G];

    const int tid = threadIdx.x;
    const int wid = tid >> 5;
    const int lane = tid & 31;
    const int g = lane >> 2, t = lane & 3;
    const int wr = wid & 3, wc = wid >> 2;
    const int m0 = wr * 16, n0 = wc * 32;
    const int row0 = blockIdx.y * 64, col0 = blockIdx.x * 64;

    float acc[4][4] = {};

    const int arw = tid >> 2, acl = (tid & 3) * 8;
    const int brw = tid >> 3, bcl = (tid & 7) * 8;

    const float* aptr = &A[(size_t)(row0 + arw) * Kd + acl];
    const float* bptr = &Bm[(size_t)brw * Nc + col0 + bcl];

    float4 pa0 = tf4(*(const float4*)(aptr));
    float4 pa1 = tf4(*(const float4*)(aptr + 4));
    float4 pb0 = tf4(*(const float4*)(bptr));
    float4 pb1 = tf4(*(const float4*)(bptr + 4));

    for (int k0 = 0; k0 < Kd; k0 += 32) {
        *(float4*)&sA[arw * AS_G + acl]      = pa0;
        *(float4*)&sA[arw * AS_G + acl + 4]  = pa1;
        *(float4*)&sBt[brw * BS_G + bcl]     = pb0;
        *(float4*)&sBt[brw * BS_G + bcl + 4] = pb1;
        __syncthreads();

        if (k0 + 32 < Kd) {
            const float* an = aptr + k0 + 32;
            const float* bn = &Bm[(size_t)(k0 + 32 + brw) * Nc + col0 + bcl];
            pa0 = tf4(*(const float4*)(an));
            pa1 = tf4(*(const float4*)(an + 4));
            pb0 = tf4(*(const float4*)(bn));
            pb1 = tf4(*(const float4*)(bn + 4));
        }

#pragma unroll
        for (int kc = 0; kc < 32; kc += 8) {
            unsigned a0 = __float_as_uint(sA[(m0 + g) * AS_G + kc + t]);
            unsigned a1 = __float_as_uint(sA[(m0 + g + 8) * AS_G + kc + t]);
            unsigned a2 = __float_as_uint(sA[(m0 + g) * AS_G + kc + t + 4]);
            unsigned a3 = __float_as_uint(sA[(m0 + g + 8) * AS_G + kc + t + 4]);
            const float* b0p = &sBt[(kc + t) * BS_G + n0];
            const float* b1p = &sBt[(kc + t + 4) * BS_G + n0];
#pragma unroll
            for (int nt = 0; nt < 4; nt++) {
                unsigned b0 = __float_as_uint(b0p[nt * 8 + g]);
                unsigned b1 = __float_as_uint(b1p[nt * 8 + g]);
                mma8(acc[nt], a0, a1, a2, a3, b0, b1);
            }
        }
        __syncthreads();
    }

#pragma unroll
    for (int nt = 0; nt < 4; nt++) {
#pragma unroll
        for (int half = 0; half < 2; half++) {
            int r = row0 + m0 + g + half * 8;
            int c = col0 + n0 + nt * 8 + 2 * t;
            float v0 = acc[nt][half * 2 + 0] + bias[c];
            float v1 = acc[nt][half * 2 + 1] + bias[c + 1];
            if (gelu) {
                v0 = 0.5f * v0 * (1.0f + erff(v0 * 0.70710678118654752f));
                v1 = 0.5f * v1 * (1.0f + erff(v1 * 0.70710678118654752f));
            }
            if (res) {
                v0 += res[(size_t)r * Nc + c];
                v1 += res[(size_t)r * Nc + c + 1];
            }
            if (cvt) {
                v0 = __uint_as_float(f2tf(v0));
                v1 = __uint_as_float(f2tf(v1));
            }
            *(float2*)&C[(size_t)r * Nc + c] = make_float2(v0, v1);
        }
    }
}

// ---------------- fused QKV projection (grid.z = 3*H) ------------------------
__global__ __launch_bounds__(256) void k_gemm_qkv(
    const float* __restrict__ A,
    const float* __restrict__ Wq, const float* __restrict__ Wk,
    const float* __restrict__ Wv,
    const float* __restrict__ bq, const float* __restrict__ bk,
    const float* __restrict__ bv,
    float* __restrict__ Cq, float* __restrict__ Ck, float* __restrict__ Cv) {
    const int zb = blockIdx.z;
    const int which = zb >> 3;        // 0=q 1=k 2=v
    const int h = zb & 7;
    const float* Bm   = (which == 0 ? Wq : which == 1 ? Wk : Wv) +
                        (size_t)h * D * D;
    const float* bias = (which == 0 ? bq : which == 1 ? bk : bv) +
                        (size_t)h * D;
    float* C          = (which == 0 ? Cq : which == 1 ? Ck : Cv) +
                        (size_t)h * N * D;
    const int Kd = D, Nc = D;

    __shared__ float sA[64 * AS_G];
    __shared__ float sBt[32 * BS_G];

    const int tid = threadIdx.x;
    const int wid = tid >> 5;
    const int lane = tid & 31;
    const int g = lane >> 2, t = lane & 3;
    const int wr = wid & 3, wc = wid >> 2;
    const int m0 = wr * 16, n0 = wc * 32;
    const int row0 = blockIdx.y * 64, col0 = blockIdx.x * 64;

    float acc[4][4] = {};

    const int arw = tid >> 2, acl = (tid & 3) * 8;
    const int brw = tid >> 3, bcl = (tid & 7) * 8;

    const float* aptr = &A[(size_t)(row0 + arw) * Kd + acl];
    const float* bptr = &Bm[(size_t)brw * Nc + col0 + bcl];

    float4 pa0 = tf4(*(const float4*)(aptr));
    float4 pa1 = tf4(*(const float4*)(aptr + 4));
    float4 pb0 = tf4(*(const float4*)(bptr));
    float4 pb1 = tf4(*(const float4*)(bptr + 4));

    for (int k0 = 0; k0 < Kd; k0 += 32) {
        *(float4*)&sA[arw * AS_G + acl]      = pa0;
        *(float4*)&sA[arw * AS_G + acl + 4]  = pa1;
        *(float4*)&sBt[brw * BS_G + bcl]     = pb0;
        *(float4*)&sBt[brw * BS_G + bcl + 4] = pb1;
        __syncthreads();

        if (k0 + 32 < Kd) {
            const float* an = aptr + k0 + 32;
            const float* bn = &Bm[(size_t)(k0 + 32 + brw) * Nc + col0 + bcl];
            pa0 = tf4(*(const float4*)(an));
            pa1 = tf4(*(const float4*)(an + 4));
            pb0 = tf4(*(const float4*)(bn));
            pb1 = tf4(*(const float4*)(bn + 4));
        }

#pragma unroll
        for (int kc = 0; kc < 32; kc += 8) {
            unsigned a0 = __float_as_uint(sA[(m0 + g) * AS_G + kc + t]);
            unsigned a1 = __float_as_uint(sA[(m0 + g + 8) * AS_G + kc + t]);
            unsigned a2 = __float_as_uint(sA[(m0 + g) * AS_G + kc + t + 4]);
            unsigned a3 = __float_as_uint(sA[(m0 + g + 8) * AS_G + kc + t + 4]);
            const float* b0p = &sBt[(kc + t) * BS_G + n0];
            const float* b1p = &sBt[(kc + t + 4) * BS_G + n0];
#pragma unroll
            for (int nt = 0; nt < 4; nt++) {
                unsigned b0 = __float_as_uint(b0p[nt * 8 + g]);
                unsigned b1 = __float_as_uint(b1p[nt * 8 + g]);
                mma8(acc[nt], a0, a1, a2, a3, b0, b1);
            }
        }
        __syncthreads();
    }

#pragma unroll
    for (int nt = 0; nt < 4; nt++) {
#pragma unroll
        for (int half = 0; half < 2; half++) {
            int r = row0 + m0 + g + half * 8;
            int c = col0 + n0 + nt * 8 + 2 * t;
            float v0 = acc[nt][half * 2 + 0] + bias[c];
            float v1 = acc[nt][half * 2 + 1] + bias[c + 1];
            v0 = __uint_as_float(f2tf(v0));
            v1 = __uint_as_float(f2tf(v1));
            *(float2*)&C[(size_t)r * Nc + c] = make_float2(v0, v1);
        }
    }
}

// ---------------- tf32 GEMM BM=32 (for small-N GEMMs), 128 threads -----------
__global__ __launch_bounds__(128) void k_gemm_s(
    const float* __restrict__ A, const float* __restrict__ Bm,
    const float* __restrict__ bias, const float* __restrict__ res,
    float* __restrict__ C, int Kd, int Nc, int gelu) {
    __shared__ float sA[32 * AS_G];
    __shared__ float sBt[32 * BS_G];

    const int tid = threadIdx.x;
    const int wid = tid >> 5;
    const int lane = tid & 31;
    const int g = lane >> 2, t = lane & 3;
    const int wr = wid & 1, wc = wid >> 1;
    const int m0 = wr * 16, n0 = wc * 32;
    const int row0 = blockIdx.y * 32, col0 = blockIdx.x * 64;

    float acc[4][4] = {};

    const int arw = tid >> 2, acl = (tid & 3) * 8;    // A: 32 rows x 32 k
    const int brw = tid >> 2, bcl = (tid & 3) * 16;   // B: 32 k x 64 cols

    const float* aptr = &A[(size_t)(row0 + arw) * Kd + acl];
    const float* bptr = &Bm[(size_t)brw * Nc + col0 + bcl];

    float4 pa0 = tf4(*(const float4*)(aptr));
    float4 pa1 = tf4(*(const float4*)(aptr + 4));
    float4 pb0 = tf4(*(const float4*)(bptr));
    float4 pb1 = tf4(*(const float4*)(bptr + 4));
    float4 pb2 = tf4(*(const float4*)(bptr + 8));
    float4 pb3 = tf4(*(const float4*)(bptr + 12));

    for (int k0 = 0; k0 < Kd; k0 += 32) {
        *(float4*)&sA[arw * AS_G + acl]       = pa0;
        *(float4*)&sA[arw * AS_G + acl + 4]   = pa1;
        *(float4*)&sBt[brw * BS_G + bcl]      = pb0;
        *(float4*)&sBt[brw * BS_G + bcl + 4]  = pb1;
        *(float4*)&sBt[brw * BS_G + bcl + 8]  = pb2;
        *(float4*)&sBt[brw * BS_G + bcl + 12] = pb3;
        __syncthreads();

        if (k0 + 32 < Kd) {
            const float* an = aptr + k0 + 32;
            const float* bn = &Bm[(size_t)(k0 + 32 + brw) * Nc + col0 + bcl];
            pa0 = tf4(*(const float4*)(an));
            pa1 = tf4(*(const float4*)(an + 4));
            pb0 = tf4(*(const float4*)(bn));
            pb1 = tf4(*(const float4*)(bn + 4));
            pb2 = tf4(*(const float4*)(bn + 8));
            pb3 = tf4(*(const float4*)(bn + 12));
        }

#pragma unroll
        for (int kc = 0; kc < 32; kc += 8) {
            unsigned a0 = __float_as_uint(sA[(m0 + g) * AS_G + kc + t]);
            unsigned a1 = __float_as_uint(sA[(m0 + g + 8) * AS_G + kc + t]);
            unsigned a2 = __float_as_uint(sA[(m0 + g) * AS_G + kc + t + 4]);
            unsigned a3 = __float_as_uint(sA[(m0 + g + 8) * AS_G + kc + t + 4]);
            const float* b0p = &sBt[(kc + t) * BS_G + n0];
            const float* b1p = &sBt[(kc + t + 4) * BS_G + n0];
#pragma unroll
            for (int nt = 0; nt < 4; nt++) {
                unsigned b0 = __float_as_uint(b0p[nt * 8 + g]);
                unsigned b1 = __float_as_uint(b1p[nt * 8 + g]);
                mma8(acc[nt], a0, a1, a2, a3, b0, b1);
            }
        }
        __syncthreads();
    }

#pragma unroll
    for (int nt = 0; nt < 4; nt++) {
#pragma unroll
        for (int half = 0; half < 2; half++) {
            int r = row0 + m0 + g + half * 8;
            int c = col0 + n0 + nt * 8 + 2 * t;
            float v0 = acc[nt][half * 2 + 0] + bias[c];
            float v1 = acc[nt][half * 2 + 1] + bias[c + 1];
            if (gelu) {
                v0 = 0.5f * v0 * (1.0f + erff(v0 * 0.70710678118654752f));
                v1 = 0.5f * v1 * (1.0f + erff(v1 * 0.70710678118654752f));
            }
            if (res) {
                v0 += res[(size_t)r * Nc + c];
                v1 += res[(size_t)r * Nc + c + 1];
            }
            *(float2*)&C[(size_t)r * Nc + c] = make_float2(v0, v1);
        }
    }
}

// ---------------- tf32 flash attention, register-prefetched K/V --------------
constexpr int QS  = 132;
constexpr int KS  = 132;
constexpr int VS  = 136;
constexpr int PS  = 68;
constexpr int SM_Q  = 0;
constexpr int SM_K  = SM_Q + 128 * QS;
constexpr int SM_V  = SM_K + 64 * KS;
constexpr int SM_P  = SM_V + 64 * VS;
constexpr int ATTN_FLOATS = SM_P + 128 * PS;
constexpr int ATTN_SMEM = ATTN_FLOATS * 4;  // 171008 bytes
constexpr int NT = N / 64;

__global__ __launch_bounds__(256, 1) void k_attn(
    const float* __restrict__ Qg, const float* __restrict__ Kg,
    const float* __restrict__ Vg, const float* __restrict__ Bg,
    float* __restrict__ Og) {
    extern __shared__ float sm[];
    float* sQ = sm + SM_Q;
    float* sK = sm + SM_K;
    float* sV = sm + SM_V;
    float* sP = sm + SM_P;

    const int hh = blockIdx.y;
    const int q0 = blockIdx.x * 128;
    const float* q  = Qg + (size_t)hh * N * D;
    const float* kp = Kg + (size_t)hh * N * D;
    const float* vp = Vg + (size_t)hh * N * D;

    const int tid  = threadIdx.x;
    const int wid  = tid >> 5;
    const int lane = tid & 31;
    const int g    = lane >> 2;
    const int t    = lane & 3;
    const int wm   = wid * 16;

#pragma unroll
    for (int i = 0; i < 16; i++) {
        int idx = tid + 256 * i;
        int r = idx >> 5, c = (idx & 31) * 4;
        *(float4*)&sQ[r * QS + c] = *(const float4*)&q[(size_t)(q0 + r) * D + c];
    }

    const int pr = tid >> 5;
    const int pc = (tid & 31) * 4;
    float4 kr[8], vr[8];
#pragma unroll
    for (int i = 0; i < 8; i++) {
        int r = pr + 8 * i;
        kr[i] = *(const float4*)&kp[(size_t)r * D + pc];
        vr[i] = *(const float4*)&vp[(size_t)r * D + pc];
    }

    float of[16][4];
#pragma unroll
    for (int dt = 0; dt < 16; dt++)
#pragma unroll
        for (int j = 0; j < 4; j++) of[dt][j] = 0.0f;
    float m0 = -1e30f, m1 = -1e30f, l0 = 0.0f, l1 = 0.0f;
    const float scale = 0.08838834764831845f;

    for (int iter = 0; iter < NT; iter++) {
        const int t0 = iter * 64;

#pragma unroll
        for (int i = 0; i < 8; i++) {
            int r = pr + 8 * i;
            *(float4*)&sK[r * KS + pc] = kr[i];
            *(float4*)&sV[r * VS + pc] = vr[i];
        }
        __syncthreads();

        if (iter + 1 < NT) {
            const float* kn = &kp[(size_t)(t0 + 64) * D];
            const float* vn = &vp[(size_t)(t0 + 64) * D];
#pragma unroll
            for (int i = 0; i < 8; i++) {
                int r = pr + 8 * i;
                kr[i] = *(const float4*)&kn[(size_t)r * D + pc];
                vr[i] = *(const float4*)&vn[(size_t)r * D + pc];
            }
        }

        const float* br0 = &Bg[(size_t)(q0 + wm + g) * N + t0];
        const float* br1 = br0 + 8 * N;
        float2 pb0[8], pb1[8];
#pragma unroll
        for (int nt = 0; nt < 8; nt++) {
            pb0[nt] = *(const float2*)&br0[nt * 8 + 2 * t];
            pb1[nt] = *(const float2*)&br1[nt * 8 + 2 * t];
        }

        float sf[8][4];
#pragma unroll
        for (int nt = 0; nt < 8; nt++)
#pragma unroll
            for (int j = 0; j < 4; j++) sf[nt][j] = 0.0f;

        const float* qb = &sQ[(wm + g) * QS];
#pragma unroll
        for (int k0 = 0; k0 < 128; k0 += 8) {
            unsigned a0 = __float_as_uint(qb[k0 + t]);
            unsigned a1 = __float_as_uint(qb[8 * QS + k0 + t]);
            unsigned a2 = __float_as_uint(qb[k0 + t + 4]);
            unsigned a3 = __float_as_uint(qb[8 * QS + k0 + t + 4]);
#pragma unroll
            for (int nt = 0; nt < 8; nt++) {
                const float* kb = &sK[(nt * 8 + g) * KS + k0];
                unsigned b0 = __float_as_uint(kb[t]);
                unsigned b1 = __float_as_uint(kb[t + 4]);
                mma8(sf[nt], a0, a1, a2, a3, b0, b1);
            }
        }

        float mx0 = -1e30f, mx1 = -1e30f;
#pragma unroll
        for (int nt = 0; nt < 8; nt++) {
            sf[nt][0] = fmaf(sf[nt][0], scale, pb0[nt].x);
            sf[nt][1] = fmaf(sf[nt][1], scale, pb0[nt].y);
            sf[nt][2] = fmaf(sf[nt][2], scale, pb1[nt].x);
            sf[nt][3] = fmaf(sf[nt][3], scale, pb1[nt].y);
            mx0 = fmaxf(mx0, fmaxf(sf[nt][0], sf[nt][1]));
            mx1 = fmaxf(mx1, fmaxf(sf[nt][2], sf[nt][3]));
        }
        mx0 = fmaxf(mx0, __shfl_xor_sync(0xffffffffu, mx0, 1));
        mx0 = fmaxf(mx0, __shfl_xor_sync(0xffffffffu, mx0, 2));
        mx1 = fmaxf(mx1, __shfl_xor_sync(0xffffffffu, mx1, 1));
        mx1 = fmaxf(mx1, __shfl_xor_sync(0xffffffffu, mx1, 2));

        float mn0 = fmaxf(m0, mx0), mn1 = fmaxf(m1, mx1);
        float c0 = __expf(m0 - mn0), c1 = __expf(m1 - mn1);
        m0 = mn0; m1 = mn1;

        float rs0 = 0.0f, rs1 = 0.0f;
        float* pr0 = &sP[(wm + g) * PS];
        float* pr1 = pr0 + 8 * PS;
#pragma unroll
        for (int nt = 0; nt < 8; nt++) {
            float p0 = __uint_as_float(f2tf(__expf(sf[nt][0] - mn0)));
            float p1 = __uint_as_float(f2tf(__expf(sf[nt][1] - mn0)));
            float p2 = __uint_as_float(f2tf(__expf(sf[nt][2] - mn1)));
            float p3 = __uint_as_float(f2tf(__expf(sf[nt][3] - mn1)));
            rs0 += p0 + p1; rs1 += p2 + p3;
            *(float2*)&pr0[nt * 8 + 2 * t] = make_float2(p0, p1);
            *(float2*)&pr1[nt * 8 + 2 * t] = make_float2(p2, p3);
        }
        rs0 += __shfl_xor_sync(0xffffffffu, rs0, 1);
        rs0 += __shfl_xor_sync(0xffffffffu, rs0, 2);
        rs1 += __shfl_xor_sync(0xffffffffu, rs1, 1);
        rs1 += __shfl_xor_sync(0xffffffffu, rs1, 2);
        l0 = l0 * c0 + rs0;
        l1 = l1 * c1 + rs1;
#pragma unroll
        for (int dt = 0; dt < 16; dt++) {
            of[dt][0] *= c0; of[dt][1] *= c0;
            of[dt][2] *= c1; of[dt][3] *= c1;
        }
        __syncwarp();

        const float* pb = &sP[(wm + g) * PS];
#pragma unroll
        for (int j0 = 0; j0 < 64; j0 += 8) {
            unsigned a0 = __float_as_uint(pb[j0 + t]);
            unsigned a1 = __float_as_uint(pb[8 * PS + j0 + t]);
            unsigned a2 = __float_as_uint(pb[j0 + t + 4]);
            unsigned a3 = __float_as_uint(pb[8 * PS + j0 + t + 4]);
            const float* vb  = &sV[(j0 + t) * VS];
            const float* vb4 = &sV[(j0 + t + 4) * VS];
#pragma unroll
            for (int dt = 0; dt < 16; dt++) {
                unsigned b0 = __float_as_uint(vb[dt * 8 + g]);
                unsigned b1 = __float_as_uint(vb4[dt * 8 + g]);
                mma8(of[dt], a0, a1, a2, a3, b0, b1);
            }
        }
        __syncthreads();
    }

    float inv0 = 1.0f / l0, inv1 = 1.0f / l1;
    int row0 = q0 + wm + g, row1 = row0 + 8;
#pragma unroll
    for (int dt = 0; dt < 16; dt++) {
        int col = hh * D + dt * 8 + 2 * t;
        *(float2*)&Og[(size_t)row0 * (H * D) + col] =
            make_float2(of[dt][0] * inv0, of[dt][1] * inv0);
        *(float2*)&Og[(size_t)row1 * (H * D) + col] =
            make_float2(of[dt][2] * inv1, of[dt][3] * inv1);
    }
}

// ---------------- launch -----------------------------------------------------
extern "C" void kernel_launch(void* const* d_in, const int* in_sizes, int n_in,
                              void* d_out, int out_size) {
    const float* x         = (const float*)d_in[0];
    const int*   ei        = (const int*)d_in[1];
    const float* pos       = (const float*)d_in[3];
    const float* node_in_w = (const float*)d_in[4];
    const float* node_in_b = (const float*)d_in[5];
    const float* z_in      = (const float*)d_in[8];
    const float* z_out     = (const float*)d_in[9];
    const float* sp_mu     = (const float*)d_in[10];
    const float* sp_sigma  = (const float*)d_in[11];
    const float* sp_w      = (const float*)d_in[12];
    const float* sp_b      = (const float*)d_in[13];
    const float* Wq        = (const float*)d_in[14];
    const float* bq        = (const float*)d_in[15];
    const float* Wk        = (const float*)d_in[16];
    const float* bk        = (const float*)d_in[17];
    const float* Wv        = (const float*)d_in[18];
    const float* bv        = (const float*)d_in[19];
    const float* Wo        = (const float*)d_in[20];
    const float* bo        = (const float*)d_in[21];
    const float* ln1_g     = (const float*)d_in[22];
    const float* ln1_b     = (const float*)d_in[23];
    const float* ln2_g     = (const float*)d_in[24];
    const float* ln2_b     = (const float*)d_in[25];
    const float* ff1_w     = (const float*)d_in[26];
    const float* ff1_b     = (const float*)d_in[27];
    const float* ff2_w     = (const float*)d_in[28];
    const float* ff2_b     = (const float*)d_in[29];
    const float* out_w     = (const float*)d_in[30];
    const float* out_b     = (const float*)d_in[31];
    float* out = (float*)d_out;

    float *p_h, *p_xn, *p_bias, *p_q, *p_k, *p_v, *p_ao, *p_ff;
    cudaGetSymbolAddress((void**)&p_h, g_h);
    cudaGetSymbolAddress((void**)&p_xn, g_xn);
    cudaGetSymbolAddress((void**)&p_bias, g_spbias);
    cudaGetSymbolAddress((void**)&p_q, g_q);
    cudaGetSymbolAddress((void**)&p_k, g_k);
    cudaGetSymbolAddress((void**)&p_v, g_v);
    cudaGetSymbolAddress((void**)&p_ao, g_ao);
    cudaGetSymbolAddress((void**)&p_ff, g_ff);

    cudaFuncSetAttribute(k_attn, cudaFuncAttributeMaxDynamicSharedMemorySize,
                         ATTN_SMEM);

    k_zero_deg<<<(N + 255) / 256, 256>>>();
    k_deg<<<(E + 255) / 256, 256>>>(ei);
    k_tab<<<TABN / 256, 256>>>(sp_mu, sp_sigma, sp_w, sp_b);
    k_spbias<<<dim3(N / 256, N), 256>>>(pos);
    k_embed<<<N, D>>>(x, node_in_w, node_in_b, z_in, z_out);

    for (int l = 0; l < NL; l++) {
        k_ln<<<N, 128>>>(p_h, ln1_g + l * D, ln1_b + l * D, p_xn);
        k_gemm_qkv<<<dim3(D / 64, N / 64, 3 * H), 256>>>(
            p_xn,
            Wq + (size_t)l * H * D * D, Wk + (size_t)l * H * D * D,
            Wv + (size_t)l * H * D * D,
            bq + (size_t)l * H * D, bk + (size_t)l * H * D,
            bv + (size_t)l * H * D,
            p_q, p_k, p_v);

        k_attn<<<dim3(N / 128, H), 256, ATTN_SMEM>>>(p_q, p_k, p_v, p_bias,
                                                     p_ao);

        k_gemm_s<<<dim3(D / 64, N / 32), 128>>>(
            p_ao, Wo + (size_t)l * H * D * D, bo + (size_t)l * D, p_h,
            p_h, H * D, D, 0);

        k_ln<<<N, 128>>>(p_h, ln2_g + l * D, ln2_b + l * D, p_xn);
        k_gemm_t<<<dim3(FFD / 64, N / 64, 1), 256>>>(
            p_xn, ff1_w + (size_t)l * D * FFD, ff1_b + (size_t)l * FFD,
            nullptr, p_ff, D, FFD, 0, 0, 0, 1, 0);
        k_gemm_s<<<dim3(D / 64, N / 32), 128>>>(
            p_ff, ff2_w + (size_t)l * FFD * D, ff2_b + (size_t)l * D, p_h,
            p_h, FFD, D, 0);
    }

    k_gemm_s<<<dim3(OUTD / 64, N / 32), 128>>>(
        p_h, out_w, out_b, nullptr, out, D, OUTD, 0);
}

// round 12
// speedup vs baseline: 3.2152x; 1.0253x over previous
#include <cuda_runtime.h>
#include <math.h>
#include <stdint.h>

namespace cfg {
constexpr int N    = 2048;
constexpr int D    = 128;
constexpr int H    = 8;
constexpr int FFD  = 512;
constexpr int NL   = 3;
constexpr int E    = 65536;
constexpr int HS   = 8;
constexpr int OUTD = 64;
}
using namespace cfg;

// ---------------- scratch ---------------------------------------------------
__device__ float g_h[N * D];
__device__ float g_xn[N * D];
__device__ float g_spbias[(size_t)N * N];
__device__ float g_q[H * N * D];
__device__ float g_k[H * N * D];
__device__ float g_v[H * N * D];
__device__ float g_ao[N * H * D];
__device__ float g_ff[N * FFD];
__device__ int   g_indeg[N];
__device__ int   g_outdeg[N];

constexpr int TABN = 16384;
constexpr float DMAX = 16.0f;
__device__ float g_tab[TABN];

// ---------------- helpers ----------------------------------------------------
__device__ __forceinline__ unsigned f2tf(float v) {
    unsigned r;
    asm("cvt.rna.tf32.f32 %0, %1;" : "=r"(r) : "f"(v));
    return r;
}

__device__ __forceinline__ float4 tf4(float4 v) {
    v.x = __uint_as_float(f2tf(v.x));
    v.y = __uint_as_float(f2tf(v.y));
    v.z = __uint_as_float(f2tf(v.z));
    v.w = __uint_as_float(f2tf(v.w));
    return v;
}

__device__ __forceinline__ void mma8(float* d, unsigned a0, unsigned a1,
                                     unsigned a2, unsigned a3,
                                     unsigned b0, unsigned b1) {
    asm volatile(
        "mma.sync.aligned.m16n8k8.row.col.f32.tf32.tf32.f32 "
        "{%0,%1,%2,%3}, {%4,%5,%6,%7}, {%8,%9}, {%0,%1,%2,%3};"
        : "+f"(d[0]), "+f"(d[1]), "+f"(d[2]), "+f"(d[3])
        : "r"(a0), "r"(a1), "r"(a2), "r"(a3), "r"(b0), "r"(b1));
}

// ---------------- degrees ----------------------------------------------------
__global__ void k_zero_deg() {
    int i = blockIdx.x * blockDim.x + threadIdx.x;
    if (i < N) { g_indeg[i] = 0; g_outdeg[i] = 0; }
}

__global__ void k_deg(const int* __restrict__ ei) {
    int e = blockIdx.x * blockDim.x + threadIdx.x;
    if (e < E) {
        atomicAdd(&g_outdeg[ei[e]], 1);
        atomicAdd(&g_indeg[ei[E + e]], 1);
    }
}

// ---------------- node embedding ---------------------------------------------
__global__ void k_embed(const float* __restrict__ x,
                        const float* __restrict__ W,
                        const float* __restrict__ b,
                        const float* __restrict__ z_in,
                        const float* __restrict__ z_out) {
    int n = blockIdx.x;
    int d = threadIdx.x;
    __shared__ float xs[16];
    if (d < 16) xs[d] = x[n * 16 + d];
    __syncthreads();
    float acc = b[d];
#pragma unroll
    for (int k = 0; k < 16; k++) acc = fmaf(xs[k], W[k * D + d], acc);
    int id = min(g_indeg[n], 63);
    int od = min(g_outdeg[n], 63);
    acc += z_in[id * D + d] + z_out[od * D + d];
    g_h[n * D + d] = acc;
}

// ---------------- spatial bias -----------------------------------------------
__global__ void k_tab(const float* __restrict__ mu,
                      const float* __restrict__ sig,
                      const float* __restrict__ w,
                      const float* __restrict__ b0) {
    int i = blockIdx.x * blockDim.x + threadIdx.x;
    float d = (float)i * (DMAX / (float)(TABN - 1));
    float acc = b0[0];
#pragma unroll
    for (int k = 0; k < HS; k++) {
        float t = (d - mu[k]) / sig[k];
        acc = fmaf(w[k], expf(-0.5f * t * t), acc);
    }
    g_tab[i] = acc;
}

__global__ void k_spbias(const float* __restrict__ pos) {
    int j = blockIdx.x * blockDim.x + threadIdx.x;
    int i = blockIdx.y;
    float dx = pos[i * 3]     - pos[j * 3];
    float dy = pos[i * 3 + 1] - pos[j * 3 + 1];
    float dz = pos[i * 3 + 2] - pos[j * 3 + 2];
    float dist = sqrtf(dx * dx + dy * dy + dz * dz + 1e-12f);
    float xx = fminf(dist, DMAX) * ((float)(TABN - 1) / DMAX);
    int i0 = min((int)xx, TABN - 2);
    float fr = xx - (float)i0;
    float t0 = g_tab[i0], t1 = g_tab[i0 + 1];
    g_spbias[(size_t)i * N + j] = t0 + fr * (t1 - t0);
}

// ---------------- layernorm --------------------------------------------------
__global__ void k_ln(const float* __restrict__ in,
                     const float* __restrict__ g,
                     const float* __restrict__ b,
                     float* __restrict__ out) {
    int n = blockIdx.x, d = threadIdx.x;
    float v = in[n * D + d];
    float s = v;
#pragma unroll
    for (int o = 16; o; o >>= 1) s += __shfl_xor_sync(0xffffffffu, s, o);
    __shared__ float r1[4], r2[4];
    int w = d >> 5;
    if ((d & 31) == 0) r1[w] = s;
    __syncthreads();
    float mean = (r1[0] + r1[1] + r1[2] + r1[3]) * (1.0f / D);
    float t = v - mean;
    float s2 = t * t;
#pragma unroll
    for (int o = 16; o; o >>= 1) s2 += __shfl_xor_sync(0xffffffffu, s2, o);
    if ((d & 31) == 0) r2[w] = s2;
    __syncthreads();
    float var = (r2[0] + r2[1] + r2[2] + r2[3]) * (1.0f / D);
    out[n * D + d] = t * rsqrtf(var + 1e-5f) * g[d] + b[d];
}

// ---------------- tf32 GEMM BM=64, BK=32, register-prefetched ----------------
constexpr int AS_G = 36;
constexpr int BS_G = 72;

__global__ __launch_bounds__(256) void k_gemm_t(
    const float* __restrict__ A, const float* __restrict__ Bm,
    const float* __restrict__ bias, const float* __restrict__ res,
    float* __restrict__ C, int Kd, int Nc,
    long sB, long sBias, long sC, int gelu, int cvt) {
    int zb = blockIdx.z;
    Bm += (size_t)zb * sB;
    bias += (size_t)zb * sBias;
    C += (size_t)zb * sC;

    __shared__ float sA[64 * AS_G];
    __shared__ float sBt[32 * BS_G];

    const int tid = threadIdx.x;
    const int wid = tid >> 5;
    const int lane = tid & 31;
    const int g = lane >> 2, t = lane & 3;
    const int wr = wid & 3, wc = wid >> 2;
    const int m0 = wr * 16, n0 = wc * 32;
    const int row0 = blockIdx.y * 64, col0 = blockIdx.x * 64;

    float acc[4][4] = {};

    const int arw = tid >> 2, acl = (tid & 3) * 8;
    const int brw = tid >> 3, bcl = (tid & 7) * 8;

    const float* aptr = &A[(size_t)(row0 + arw) * Kd + acl];
    const float* bptr = &Bm[(size_t)brw * Nc + col0 + bcl];

    float4 pa0 = tf4(*(const float4*)(aptr));
    float4 pa1 = tf4(*(const float4*)(aptr + 4));
    float4 pb0 = tf4(*(const float4*)(bptr));
    float4 pb1 = tf4(*(const float4*)(bptr + 4));

    for (int k0 = 0; k0 < Kd; k0 += 32) {
        *(float4*)&sA[arw * AS_G + acl]      = pa0;
        *(float4*)&sA[arw * AS_G + acl + 4]  = pa1;
        *(float4*)&sBt[brw * BS_G + bcl]     = pb0;
        *(float4*)&sBt[brw * BS_G + bcl + 4] = pb1;
        __syncthreads();

        if (k0 + 32 < Kd) {
            const float* an = aptr + k0 + 32;
            const float* bn = &Bm[(size_t)(k0 + 32 + brw) * Nc + col0 + bcl];
            pa0 = tf4(*(const float4*)(an));
            pa1 = tf4(*(const float4*)(an + 4));
            pb0 = tf4(*(const float4*)(bn));
            pb1 = tf4(*(const float4*)(bn + 4));
        }

#pragma unroll
        for (int kc = 0; kc < 32; kc += 8) {
            unsigned a0 = __float_as_uint(sA[(m0 + g) * AS_G + kc + t]);
            unsigned a1 = __float_as_uint(sA[(m0 + g + 8) * AS_G + kc + t]);
            unsigned a2 = __float_as_uint(sA[(m0 + g) * AS_G + kc + t + 4]);
            unsigned a3 = __float_as_uint(sA[(m0 + g + 8) * AS_G + kc + t + 4]);
            const float* b0p = &sBt[(kc + t) * BS_G + n0];
            const float* b1p = &sBt[(kc + t + 4) * BS_G + n0];
#pragma unroll
            for (int nt = 0; nt < 4; nt++) {
                unsigned b0 = __float_as_uint(b0p[nt * 8 + g]);
                unsigned b1 = __float_as_uint(b1p[nt * 8 + g]);
                mma8(acc[nt], a0, a1, a2, a3, b0, b1);
            }
        }
        __syncthreads();
    }

#pragma unroll
    for (int nt = 0; nt < 4; nt++) {
#pragma unroll
        for (int half = 0; half < 2; half++) {
            int r = row0 + m0 + g + half * 8;
            int c = col0 + n0 + nt * 8 + 2 * t;
            float v0 = acc[nt][half * 2 + 0] + bias[c];
            float v1 = acc[nt][half * 2 + 1] + bias[c + 1];
            if (gelu) {
                v0 = 0.5f * v0 * (1.0f + erff(v0 * 0.70710678118654752f));
                v1 = 0.5f * v1 * (1.0f + erff(v1 * 0.70710678118654752f));
            }
            if (res) {
                v0 += res[(size_t)r * Nc + c];
                v1 += res[(size_t)r * Nc + c + 1];
            }
            if (cvt) {
                v0 = __uint_as_float(f2tf(v0));
                v1 = __uint_as_float(f2tf(v1));
            }
            *(float2*)&C[(size_t)r * Nc + c] = make_float2(v0, v1);
        }
    }
}

// ---------------- fused QKV, BM=128 x BN=128 x BK=32 -------------------------
constexpr int BS2 = 136;

__global__ __launch_bounds__(256) void k_gemm_qkv2(
    const float* __restrict__ A,
    const float* __restrict__ Wq, const float* __restrict__ Wk,
    const float* __restrict__ Wv,
    const float* __restrict__ bq, const float* __restrict__ bk,
    const float* __restrict__ bv,
    float* __restrict__ Cq, float* __restrict__ Ck, float* __restrict__ Cv) {
    const int zb = blockIdx.z;
    const int which = zb >> 3;
    const int h = zb & 7;
    const float* Bm   = (which == 0 ? Wq : which == 1 ? Wk : Wv) +
                        (size_t)h * D * D;
    const float* bias = (which == 0 ? bq : which == 1 ? bk : bv) +
                        (size_t)h * D;
    float* C          = (which == 0 ? Cq : which == 1 ? Ck : Cv) +
                        (size_t)h * N * D;
    const int Kd = D, Nc = D;

    __shared__ float sA[128 * AS_G];
    __shared__ float sBt[32 * BS2];

    const int tid = threadIdx.x;
    const int wid = tid >> 5;
    const int lane = tid & 31;
    const int g = lane >> 2, t = lane & 3;
    const int wr = wid & 3, wc = wid >> 2;
    const int m0 = wr * 32, n0 = wc * 64;
    const int row0 = blockIdx.y * 128, col0 = blockIdx.x * 128;

    float acc[2][8][4] = {};

    const int arw = tid >> 1, acl = (tid & 1) * 16;
    const int brw = tid >> 3, bc0 = (tid & 7) * 4;

    const float* aptr = &A[(size_t)(row0 + arw) * Kd + acl];

    float4 pa[4], pb[4];
#pragma unroll
    for (int i = 0; i < 4; i++)
        pa[i] = tf4(*(const float4*)(aptr + 4 * i));
#pragma unroll
    for (int c = 0; c < 4; c++)
        pb[c] = tf4(*(const float4*)&Bm[(size_t)brw * Nc + col0 + bc0 + 32 * c]);

    for (int k0 = 0; k0 < Kd; k0 += 32) {
#pragma unroll
        for (int i = 0; i < 4; i++)
            *(float4*)&sA[arw * AS_G + acl + 4 * i] = pa[i];
#pragma unroll
        for (int c = 0; c < 4; c++)
            *(float4*)&sBt[brw * BS2 + bc0 + 32 * c] = pb[c];
        __syncthreads();

        if (k0 + 32 < Kd) {
            const float* an = aptr + k0 + 32;
#pragma unroll
            for (int i = 0; i < 4; i++)
                pa[i] = tf4(*(const float4*)(an + 4 * i));
#pragma unroll
            for (int c = 0; c < 4; c++)
                pb[c] = tf4(*(const float4*)
                    &Bm[(size_t)(k0 + 32 + brw) * Nc + col0 + bc0 + 32 * c]);
        }

#pragma unroll
        for (int kc = 0; kc < 32; kc += 8) {
            unsigned af[2][4];
#pragma unroll
            for (int mt = 0; mt < 2; mt++) {
                const float* ab = &sA[(m0 + mt * 16 + g) * AS_G + kc];
                af[mt][0] = __float_as_uint(ab[t]);
                af[mt][1] = __float_as_uint(ab[8 * AS_G + t]);
                af[mt][2] = __float_as_uint(ab[t + 4]);
                af[mt][3] = __float_as_uint(ab[8 * AS_G + t + 4]);
            }
            const float* b0p = &sBt[(kc + t) * BS2 + n0];
            const float* b1p = &sBt[(kc + t + 4) * BS2 + n0];
#pragma unroll
            for (int nt = 0; nt < 8; nt++) {
                unsigned b0 = __float_as_uint(b0p[nt * 8 + g]);
                unsigned b1 = __float_as_uint(b1p[nt * 8 + g]);
                mma8(acc[0][nt], af[0][0], af[0][1], af[0][2], af[0][3], b0, b1);
                mma8(acc[1][nt], af[1][0], af[1][1], af[1][2], af[1][3], b0, b1);
            }
        }
        __syncthreads();
    }

#pragma unroll
    for (int mt = 0; mt < 2; mt++)
#pragma unroll
        for (int nt = 0; nt < 8; nt++)
#pragma unroll
            for (int half = 0; half < 2; half++) {
                int r = row0 + m0 + mt * 16 + g + half * 8;
                int c = col0 + n0 + nt * 8 + 2 * t;
                float v0 = acc[mt][nt][half * 2 + 0] + bias[c];
                float v1 = acc[mt][nt][half * 2 + 1] + bias[c + 1];
                v0 = __uint_as_float(f2tf(v0));
                v1 = __uint_as_float(f2tf(v1));
                *(float2*)&C[(size_t)r * Nc + c] = make_float2(v0, v1);
            }
}

// ---------------- tf32 GEMM BM=32 (small-N GEMMs), 128 threads ---------------
__global__ __launch_bounds__(128) void k_gemm_s(
    const float* __restrict__ A, const float* __restrict__ Bm,
    const float* __restrict__ bias, const float* __restrict__ res,
    float* __restrict__ C, int Kd, int Nc, int gelu) {
    __shared__ float sA[32 * AS_G];
    __shared__ float sBt[32 * BS_G];

    const int tid = threadIdx.x;
    const int wid = tid >> 5;
    const int lane = tid & 31;
    const int g = lane >> 2, t = lane & 3;
    const int wr = wid & 1, wc = wid >> 1;
    const int m0 = wr * 16, n0 = wc * 32;
    const int row0 = blockIdx.y * 32, col0 = blockIdx.x * 64;

    float acc[4][4] = {};

    const int arw = tid >> 2, acl = (tid & 3) * 8;
    const int brw = tid >> 2, bcl = (tid & 3) * 16;

    const float* aptr = &A[(size_t)(row0 + arw) * Kd + acl];
    const float* bptr = &Bm[(size_t)brw * Nc + col0 + bcl];

    float4 pa0 = tf4(*(const float4*)(aptr));
    float4 pa1 = tf4(*(const float4*)(aptr + 4));
    float4 pb0 = tf4(*(const float4*)(bptr));
    float4 pb1 = tf4(*(const float4*)(bptr + 4));
    float4 pb2 = tf4(*(const float4*)(bptr + 8));
    float4 pb3 = tf4(*(const float4*)(bptr + 12));

    for (int k0 = 0; k0 < Kd; k0 += 32) {
        *(float4*)&sA[arw * AS_G + acl]       = pa0;
        *(float4*)&sA[arw * AS_G + acl + 4]   = pa1;
        *(float4*)&sBt[brw * BS_G + bcl]      = pb0;
        *(float4*)&sBt[brw * BS_G + bcl + 4]  = pb1;
        *(float4*)&sBt[brw * BS_G + bcl + 8]  = pb2;
        *(float4*)&sBt[brw * BS_G + bcl + 12] = pb3;
        __syncthreads();

        if (k0 + 32 < Kd) {
            const float* an = aptr + k0 + 32;
            const float* bn = &Bm[(size_t)(k0 + 32 + brw) * Nc + col0 + bcl];
            pa0 = tf4(*(const float4*)(an));
            pa1 = tf4(*(const float4*)(an + 4));
            pb0 = tf4(*(const float4*)(bn));
            pb1 = tf4(*(const float4*)(bn + 4));
            pb2 = tf4(*(const float4*)(bn + 8));
            pb3 = tf4(*(const float4*)(bn + 12));
        }

#pragma unroll
        for (int kc = 0; kc < 32; kc += 8) {
            unsigned a0 = __float_as_uint(sA[(m0 + g) * AS_G + kc + t]);
            unsigned a1 = __float_as_uint(sA[(m0 + g + 8) * AS_G + kc + t]);
            unsigned a2 = __float_as_uint(sA[(m0 + g) * AS_G + kc + t + 4]);
            unsigned a3 = __float_as_uint(sA[(m0 + g + 8) * AS_G + kc + t + 4]);
            const float* b0p = &sBt[(kc + t) * BS_G + n0];
            const float* b1p = &sBt[(kc + t + 4) * BS_G + n0];
#pragma unroll
            for (int nt = 0; nt < 4; nt++) {
                unsigned b0 = __float_as_uint(b0p[nt * 8 + g]);
                unsigned b1 = __float_as_uint(b1p[nt * 8 + g]);
                mma8(acc[nt], a0, a1, a2, a3, b0, b1);
            }
        }
        __syncthreads();
    }

#pragma unroll
    for (int nt = 0; nt < 4; nt++) {
#pragma unroll
        for (int half = 0; half < 2; half++) {
            int r = row0 + m0 + g + half * 8;
            int c = col0 + n0 + nt * 8 + 2 * t;
            float v0 = acc[nt][half * 2 + 0] + bias[c];
            float v1 = acc[nt][half * 2 + 1] + bias[c + 1];
            if (gelu) {
                v0 = 0.5f * v0 * (1.0f + erff(v0 * 0.70710678118654752f));
                v1 = 0.5f * v1 * (1.0f + erff(v1 * 0.70710678118654752f));
            }
            if (res) {
                v0 += res[(size_t)r * Nc + c];
                v1 += res[(size_t)r * Nc + c + 1];
            }
            *(float2*)&C[(size_t)r * Nc + c] = make_float2(v0, v1);
        }
    }
}

// ---------------- tf32 flash attention, register-prefetched K/V --------------
constexpr int QS  = 132;
constexpr int KS  = 132;
constexpr int VS  = 136;
constexpr int PS  = 68;
constexpr int SM_Q  = 0;
constexpr int SM_K  = SM_Q + 128 * QS;
constexpr int SM_V  = SM_K + 64 * KS;
constexpr int SM_P  = SM_V + 64 * VS;
constexpr int ATTN_FLOATS = SM_P + 128 * PS;
constexpr int ATTN_SMEM = ATTN_FLOATS * 4;  // 171008 bytes
constexpr int NT = N / 64;

__global__ __launch_bounds__(256, 1) void k_attn(
    const float* __restrict__ Qg, const float* __restrict__ Kg,
    const float* __restrict__ Vg, const float* __restrict__ Bg,
    float* __restrict__ Og) {
    extern __shared__ float sm[];
    float* sQ = sm + SM_Q;
    float* sK = sm + SM_K;
    float* sV = sm + SM_V;
    float* sP = sm + SM_P;

    const int hh = blockIdx.y;
    const int q0 = blockIdx.x * 128;
    const float* q  = Qg + (size_t)hh * N * D;
    const float* kp = Kg + (size_t)hh * N * D;
    const float* vp = Vg + (size_t)hh * N * D;

    const int tid  = threadIdx.x;
    const int wid  = tid >> 5;
    const int lane = tid & 31;
    const int g    = lane >> 2;
    const int t    = lane & 3;
    const int wm   = wid * 16;

#pragma unroll
    for (int i = 0; i < 16; i++) {
        int idx = tid + 256 * i;
        int r = idx >> 5, c = (idx & 31) * 4;
        *(float4*)&sQ[r * QS + c] = *(const float4*)&q[(size_t)(q0 + r) * D + c];
    }

    const int pr = tid >> 5;
    const int pc = (tid & 31) * 4;
    float4 kr[8], vr[8];
#pragma unroll
    for (int i = 0; i < 8; i++) {
        int r = pr + 8 * i;
        kr[i] = *(const float4*)&kp[(size_t)r * D + pc];
        vr[i] = *(const float4*)&vp[(size_t)r * D + pc];
    }

    float of[16][4];
#pragma unroll
    for (int dt = 0; dt < 16; dt++)
#pragma unroll
        for (int j = 0; j < 4; j++) of[dt][j] = 0.0f;
    float m0 = -1e30f, m1 = -1e30f, l0 = 0.0f, l1 = 0.0f;
    const float scale = 0.08838834764831845f;

    for (int iter = 0; iter < NT; iter++) {
        const int t0 = iter * 64;

#pragma unroll
        for (int i = 0; i < 8; i++) {
            int r = pr + 8 * i;
            *(float4*)&sK[r * KS + pc] = kr[i];
            *(float4*)&sV[r * VS + pc] = vr[i];
        }
        __syncthreads();

        if (iter + 1 < NT) {
            const float* kn = &kp[(size_t)(t0 + 64) * D];
            const float* vn = &vp[(size_t)(t0 + 64) * D];
#pragma unroll
            for (int i = 0; i < 8; i++) {
                int r = pr + 8 * i;
                kr[i] = *(const float4*)&kn[(size_t)r * D + pc];
                vr[i] = *(const float4*)&vn[(size_t)r * D + pc];
            }
        }

        const float* br0 = &Bg[(size_t)(q0 + wm + g) * N + t0];
        const float* br1 = br0 + 8 * N;
        float2 pb0[8], pb1[8];
#pragma unroll
        for (int nt = 0; nt < 8; nt++) {
            pb0[nt] = *(const float2*)&br0[nt * 8 + 2 * t];
            pb1[nt] = *(const float2*)&br1[nt * 8 + 2 * t];
        }

        float sf[8][4];
#pragma unroll
        for (int nt = 0; nt < 8; nt++)
#pragma unroll
            for (int j = 0; j < 4; j++) sf[nt][j] = 0.0f;

        const float* qb = &sQ[(wm + g) * QS];
#pragma unroll
        for (int k0 = 0; k0 < 128; k0 += 8) {
            unsigned a0 = __float_as_uint(qb[k0 + t]);
            unsigned a1 = __float_as_uint(qb[8 * QS + k0 + t]);
            unsigned a2 = __float_as_uint(qb[k0 + t + 4]);
            unsigned a3 = __float_as_uint(qb[8 * QS + k0 + t + 4]);
#pragma unroll
            for (int nt = 0; nt < 8; nt++) {
                const float* kb = &sK[(nt * 8 + g) * KS + k0];
                unsigned b0 = __float_as_uint(kb[t]);
                unsigned b1 = __float_as_uint(kb[t + 4]);
                mma8(sf[nt], a0, a1, a2, a3, b0, b1);
            }
        }

        float mx0 = -1e30f, mx1 = -1e30f;
#pragma unroll
        for (int nt = 0; nt < 8; nt++) {
            sf[nt][0] = fmaf(sf[nt][0], scale, pb0[nt].x);
            sf[nt][1] = fmaf(sf[nt][1], scale, pb0[nt].y);
            sf[nt][2] = fmaf(sf[nt][2], scale, pb1[nt].x);
            sf[nt][3] = fmaf(sf[nt][3], scale, pb1[nt].y);
            mx0 = fmaxf(mx0, fmaxf(sf[nt][0], sf[nt][1]));
            mx1 = fmaxf(mx1, fmaxf(sf[nt][2], sf[nt][3]));
        }
        mx0 = fmaxf(mx0, __shfl_xor_sync(0xffffffffu, mx0, 1));
        mx0 = fmaxf(mx0, __shfl_xor_sync(0xffffffffu, mx0, 2));
        mx1 = fmaxf(mx1, __shfl_xor_sync(0xffffffffu, mx1, 1));
        mx1 = fmaxf(mx1, __shfl_xor_sync(0xffffffffu, mx1, 2));

        float mn0 = fmaxf(m0, mx0), mn1 = fmaxf(m1, mx1);
        float c0 = __expf(m0 - mn0), c1 = __expf(m1 - mn1);
        m0 = mn0; m1 = mn1;

        float rs0 = 0.0f, rs1 = 0.0f;
        float* pr0 = &sP[(wm + g) * PS];
        float* pr1 = pr0 + 8 * PS;
#pragma unroll
        for (int nt = 0; nt < 8; nt++) {
            float p0 = __uint_as_float(f2tf(__expf(sf[nt][0] - mn0)));
            float p1 = __uint_as_float(f2tf(__expf(sf[nt][1] - mn0)));
            float p2 = __uint_as_float(f2tf(__expf(sf[nt][2] - mn1)));
            float p3 = __uint_as_float(f2tf(__expf(sf[nt][3] - mn1)));
            rs0 += p0 + p1; rs1 += p2 + p3;
            *(float2*)&pr0[nt * 8 + 2 * t] = make_float2(p0, p1);
            *(float2*)&pr1[nt * 8 + 2 * t] = make_float2(p2, p3);
        }
        rs0 += __shfl_xor_sync(0xffffffffu, rs0, 1);
        rs0 += __shfl_xor_sync(0xffffffffu, rs0, 2);
        rs1 += __shfl_xor_sync(0xffffffffu, rs1, 1);
        rs1 += __shfl_xor_sync(0xffffffffu, rs1, 2);
        l0 = l0 * c0 + rs0;
        l1 = l1 * c1 + rs1;
#pragma unroll
        for (int dt = 0; dt < 16; dt++) {
            of[dt][0] *= c0; of[dt][1] *= c0;
            of[dt][2] *= c1; of[dt][3] *= c1;
        }
        __syncwarp();

        const float* pb = &sP[(wm + g) * PS];
#pragma unroll
        for (int j0 = 0; j0 < 64; j0 += 8) {
            unsigned a0 = __float_as_uint(pb[j0 + t]);
            unsigned a1 = __float_as_uint(pb[8 * PS + j0 + t]);
            unsigned a2 = __float_as_uint(pb[j0 + t + 4]);
            unsigned a3 = __float_as_uint(pb[8 * PS + j0 + t + 4]);
            const float* vb  = &sV[(j0 + t) * VS];
            const float* vb4 = &sV[(j0 + t + 4) * VS];
#pragma unroll
            for (int dt = 0; dt < 16; dt++) {
                unsigned b0 = __float_as_uint(vb[dt * 8 + g]);
                unsigned b1 = __float_as_uint(vb4[dt * 8 + g]);
                mma8(of[dt], a0, a1, a2, a3, b0, b1);
            }
        }
        __syncthreads();
    }

    float inv0 = 1.0f / l0, inv1 = 1.0f / l1;
    int row0 = q0 + wm + g, row1 = row0 + 8;
#pragma unroll
    for (int dt = 0; dt < 16; dt++) {
        int col = hh * D + dt * 8 + 2 * t;
        *(float2*)&Og[(size_t)row0 * (H * D) + col] =
            make_float2(of[dt][0] * inv0, of[dt][1] * inv0);
        *(float2*)&Og[(size_t)row1 * (H * D) + col] =
            make_float2(of[dt][2] * inv1, of[dt][3] * inv1);
    }
}

// ---------------- launch -----------------------------------------------------
extern "C" void kernel_launch(void* const* d_in, const int* in_sizes, int n_in,
                              void* d_out, int out_size) {
    const float* x         = (const float*)d_in[0];
    const int*   ei        = (const int*)d_in[1];
    const float* pos       = (const float*)d_in[3];
    const float* node_in_w = (const float*)d_in[4];
    const float* node_in_b = (const float*)d_in[5];
    const float* z_in      = (const float*)d_in[8];
    const float* z_out     = (const float*)d_in[9];
    const float* sp_mu     = (const float*)d_in[10];
    const float* sp_sigma  = (const float*)d_in[11];
    const float* sp_w      = (const float*)d_in[12];
    const float* sp_b      = (const float*)d_in[13];
    const float* Wq        = (const float*)d_in[14];
    const float* bq        = (const float*)d_in[15];
    const float* Wk        = (const float*)d_in[16];
    const float* bk        = (const float*)d_in[17];
    const float* Wv        = (const float*)d_in[18];
    const float* bv        = (const float*)d_in[19];
    const float* Wo        = (const float*)d_in[20];
    const float* bo        = (const float*)d_in[21];
    const float* ln1_g     = (const float*)d_in[22];
    const float* ln1_b     = (const float*)d_in[23];
    const float* ln2_g     = (const float*)d_in[24];
    const float* ln2_b     = (const float*)d_in[25];
    const float* ff1_w     = (const float*)d_in[26];
    const float* ff1_b     = (const float*)d_in[27];
    const float* ff2_w     = (const float*)d_in[28];
    const float* ff2_b     = (const float*)d_in[29];
    const float* out_w     = (const float*)d_in[30];
    const float* out_b     = (const float*)d_in[31];
    float* out = (float*)d_out;

    float *p_h, *p_xn, *p_bias, *p_q, *p_k, *p_v, *p_ao, *p_ff;
    cudaGetSymbolAddress((void**)&p_h, g_h);
    cudaGetSymbolAddress((void**)&p_xn, g_xn);
    cudaGetSymbolAddress((void**)&p_bias, g_spbias);
    cudaGetSymbolAddress((void**)&p_q, g_q);
    cudaGetSymbolAddress((void**)&p_k, g_k);
    cudaGetSymbolAddress((void**)&p_v, g_v);
    cudaGetSymbolAddress((void**)&p_ao, g_ao);
    cudaGetSymbolAddress((void**)&p_ff, g_ff);

    cudaFuncSetAttribute(k_attn, cudaFuncAttributeMaxDynamicSharedMemorySize,
                         ATTN_SMEM);

    k_zero_deg<<<(N + 255) / 256, 256>>>();
    k_deg<<<(E + 255) / 256, 256>>>(ei);
    k_tab<<<TABN / 256, 256>>>(sp_mu, sp_sigma, sp_w, sp_b);
    k_spbias<<<dim3(N / 256, N), 256>>>(pos);
    k_embed<<<N, D>>>(x, node_in_w, node_in_b, z_in, z_out);

    for (int l = 0; l < NL; l++) {
        k_ln<<<N, 128>>>(p_h, ln1_g + l * D, ln1_b + l * D, p_xn);
        k_gemm_qkv2<<<dim3(1, N / 128, 3 * H), 256>>>(
            p_xn,
            Wq + (size_t)l * H * D * D, Wk + (size_t)l * H * D * D,
            Wv + (size_t)l * H * D * D,
            bq + (size_t)l * H * D, bk + (size_t)l * H * D,
            bv + (size_t)l * H * D,
            p_q, p_k, p_v);

        k_attn<<<dim3(N / 128, H), 256, ATTN_SMEM>>>(p_q, p_k, p_v, p_bias,
                                                     p_ao);

        k_gemm_s<<<dim3(D / 64, N / 32), 128>>>(
            p_ao, Wo + (size_t)l * H * D * D, bo + (size_t)l * D, p_h,
            p_h, H * D, D, 0);

        k_ln<<<N, 128>>>(p_h, ln2_g + l * D, ln2_b + l * D, p_xn);
        k_gemm_t<<<dim3(FFD / 64, N / 64, 1), 256>>>(
            p_xn, ff1_w + (size_t)l * D * FFD, ff1_b + (size_t)l * FFD,
            nullptr, p_ff, D, FFD, 0, 0, 0, 1, 0);
        k_gemm_s<<<dim3(D / 64, N / 32), 128>>>(
            p_ff, ff2_w + (size_t)l * FFD * D, ff2_b + (size_t)l * D, p_h,
            p_h, FFD, D, 0);
    }

    k_gemm_s<<<dim3(OUTD / 64, N / 32), 128>>>(
        p_h, out_w, out_b, nullptr, out, D, OUTD, 0);
}